// round 9
// baseline (speedup 1.0000x reference)
#include <cuda_runtime.h>
#include <cuda_bf16.h>
#include <math.h>

#define NN 50000
#define EE 800000
#define HID 128
#define FFH 512

// ---------------- scratch (device globals: allocation-free) ----------------
__device__ __nv_bfloat16 g_xbf[(size_t)NN * HID];
__device__ __nv_bfloat16 g_wcat[384 * 128];
__device__ __nv_bfloat16 g_wo[128 * 128];
__device__ __nv_bfloat16 g_w1[512 * 128];
__device__ __nv_bfloat16 g_w2[128 * 512];
__device__ float g_bcat[384], g_bo[128], g_b1[512], g_b2[128];
__device__ __nv_bfloat16 g_qkv[(size_t)NN * 384];
__device__ int g_src[EE], g_dst[EE], g_esrc[EE];
__device__ int g_rowptr[NN + 1], g_fill[NN];
__device__ int g_bsum[64];
__device__ int g_arrive;   // static-init 0; reset to 0 by last block every call
__device__ __nv_bfloat16 g_aggbf[(size_t)NN * HID];
__device__ float g_h[(size_t)NN * HID];
__device__ __nv_bfloat16 g_hbf[(size_t)NN * HID];
__device__ __nv_bfloat16 g_ff1bf[(size_t)NN * FFH];

// ---------------- prep kernels ----------------
__global__ void zero_fill() {
    int i = blockIdx.x * blockDim.x + threadIdx.x;
    if (i < NN) g_fill[i] = 0;
}

__global__ void prep_edges(const void* __restrict__ ei) {
    int i = blockIdx.x * blockDim.x + threadIdx.x;
    if (i >= EE) return;
    // dtype sniff per-thread (L1-broadcast): int64 view of int32 data combines
    // two random node ids -> ~1e14, outside [0, NN). Deterministic.
    const long long* p64 = (const long long*)ei;
    int is64 = 1;
#pragma unroll
    for (int j = 0; j < 4; j++) {
        long long v = p64[j];
        if (v < 0 || v >= NN) is64 = 0;
    }
    long long s, d;
    if (is64) {
        s = p64[i];
        d = p64[(size_t)EE + i];
    } else {
        const int* p = (const int*)ei;
        s = p[i];
        d = p[(size_t)EE + i];
    }
    if (s < 0) s = 0; if (s >= NN) s = NN - 1;
    if (d < 0) d = 0; if (d >= NN) d = NN - 1;
    g_src[i] = (int)s;
    g_dst[i] = (int)d;
    atomicAdd(&g_fill[(int)d], 1);   // fused histogram
}

// fused block-scan + (last block) top-scan via arrival counter
__global__ void scan_bt() {
    __shared__ int sh[1024];
    __shared__ int s_old;
    int b = blockIdx.x, t = threadIdx.x;
    int i = b * 1024 + t;
    int d = (i < NN) ? g_fill[i] : 0;
    sh[t] = d;
    __syncthreads();
#pragma unroll
    for (int off = 1; off < 1024; off <<= 1) {
        int v = (t >= off) ? sh[t - off] : 0;
        __syncthreads();
        sh[t] += v;
        __syncthreads();
    }
    if (i < NN) g_rowptr[i] = sh[t] - d;  // exclusive, block-local
    if (t == 1023) {
        g_bsum[b] = sh[1023];
        __threadfence();
    }
    __syncthreads();
    if (t == 0) s_old = atomicAdd(&g_arrive, 1);
    __syncthreads();
    if (s_old == gridDim.x - 1) {
        int nb = gridDim.x;
        if (t < nb) sh[t] = *(volatile int*)&g_bsum[t];
        __syncthreads();
        if (t == 0) {
            int run = 0;
            for (int j = 0; j < nb; j++) { int v = sh[j]; sh[j] = run; run += v; }
            g_rowptr[NN] = run;
            g_arrive = 0;   // deterministic reset for next call
        }
        __syncthreads();
        if (t < nb) g_bsum[t] = sh[t];
    }
}

__global__ void scan_fix() {
    int b = blockIdx.x;
    int i = b * 1024 + threadIdx.x;
    if (i < NN) {
        int r = g_rowptr[i] + g_bsum[b];
        g_rowptr[i] = r;
        g_fill[i] = r;
    }
}

__global__ void scatter_kernel() {
    int i = blockIdx.x * blockDim.x + threadIdx.x;
    if (i < EE) {
        int d = g_dst[i];
        int p = atomicAdd(&g_fill[d], 1);
        g_esrc[p] = g_src[i];
    }
}

// fused: x -> bf16 conversion + weight conversion + bias staging
__global__ void prep_wx(const float* __restrict__ x,
                        const float* __restrict__ Wq, const float* __restrict__ bq,
                        const float* __restrict__ Wk, const float* __restrict__ bk,
                        const float* __restrict__ Wv, const float* __restrict__ bv,
                        const float* __restrict__ Wo, const float* __restrict__ bo,
                        const float* __restrict__ W1, const float* __restrict__ b1,
                        const float* __restrict__ W2, const float* __restrict__ b2) {
    int i = blockIdx.x * blockDim.x + threadIdx.x;
    if (i < NN * HID) g_xbf[i] = __float2bfloat16(x[i]);
    if (i < 128 * 128) {
        g_wcat[i]         = __float2bfloat16(Wq[i]);
        g_wcat[16384 + i] = __float2bfloat16(Wk[i]);
        g_wcat[32768 + i] = __float2bfloat16(Wv[i]);
        g_wo[i]           = __float2bfloat16(Wo[i]);
    }
    if (i < 512 * 128) {
        g_w1[i] = __float2bfloat16(W1[i]);
        g_w2[i] = __float2bfloat16(W2[i]);
    }
    if (i < 128) {
        g_bcat[i] = bq[i];
        g_bcat[128 + i] = bk[i];
        g_bcat[256 + i] = bv[i];
        g_bo[i] = bo[i];
        g_b2[i] = b2[i];
    }
    if (i < 512) g_b1[i] = b1[i];
}

// ---------------- bf16 tensor-core GEMM helpers ----------------
__device__ __forceinline__ void mma16816(float c[4], unsigned a0, unsigned a1, unsigned a2,
                                         unsigned a3, unsigned b0, unsigned b1) {
    asm volatile(
        "mma.sync.aligned.m16n8k16.row.col.f32.bf16.bf16.f32 "
        "{%0,%1,%2,%3}, {%4,%5,%6,%7}, {%8,%9}, {%0,%1,%2,%3};\n"
        : "+f"(c[0]), "+f"(c[1]), "+f"(c[2]), "+f"(c[3])
        : "r"(a0), "r"(a1), "r"(a2), "r"(a3), "r"(b0), "r"(b1));
}

__device__ __forceinline__ void ldx4(unsigned& r0, unsigned& r1, unsigned& r2, unsigned& r3,
                                     unsigned addr) {
    asm volatile("ldmatrix.sync.aligned.m8n8.x4.shared.b16 {%0,%1,%2,%3}, [%4];"
                 : "=r"(r0), "=r"(r1), "=r"(r2), "=r"(r3)
                 : "r"(addr));
}

__device__ __forceinline__ void cp16(unsigned saddr, const void* gaddr, int szbytes) {
    asm volatile("cp.async.cg.shared.global [%0], [%1], 16, %2;"
                 :: "r"(saddr), "l"(gaddr), "r"(szbytes));
}

__device__ __forceinline__ float warp_sum(float s) {
#pragma unroll
    for (int o = 16; o > 0; o >>= 1) s += __shfl_xor_sync(0xffffffffu, s, o);
    return s;
}

__device__ __forceinline__ float gelu_f(float v) {
    return 0.5f * v * (1.0f + erff(v * 0.70710678118654752f));
}

// ============ wide GEMM (K=128): A resident in smem, loop over N blocks ============
// used for QKV (NB=3) and FF1+gelu (NB=4)
#define WASU 68
#define WA_U (128 * WASU)
#define WIDE_SMEM (3 * WA_U * 4)   // A + 2 B buffers = 104448 B

__global__ __launch_bounds__(256) void gemm_wide(int sel, int M) {
    const __nv_bfloat16 *A, *W;
    const float* bias;
    __nv_bfloat16* C;
    int NB, N;
    bool gelu;
    if (sel == 0) { A = g_xbf; W = g_wcat; bias = g_bcat; C = g_qkv;   NB = 3; N = 384; gelu = false; }
    else          { A = g_hbf; W = g_w1;   bias = g_b1;   C = g_ff1bf; NB = 4; N = 512; gelu = true;  }

    extern __shared__ unsigned sh[];
    unsigned sbase = (unsigned)__cvta_generic_to_shared(sh);

    int t = threadIdx.x;
    int warp = t >> 5, lane = t & 31;
    int wm = warp >> 2, wn = warp & 3;
    int bm = blockIdx.x * 128;
    int r = lane >> 2, cp = lane & 3;

    int q = lane >> 3, lr = lane & 7;
    int rb = lr + (q & 1) * 8;
    int cb4 = (q >> 1) * 4;

    unsigned aAddr[2];
#pragma unroll
    for (int mi2 = 0; mi2 < 2; mi2++)
        aAddr[mi2] = sbase + 4u * ((wm * 64 + mi2 * 32 + rb) * WASU + cb4);
    unsigned bAddrBuf[2][2];
#pragma unroll
    for (int buf = 0; buf < 2; buf++)
#pragma unroll
        for (int n2 = 0; n2 < 2; n2++)
            bAddrBuf[buf][n2] = sbase + 4u * ((1 + buf) * WA_U + (wn * 32 + n2 * 16 + rb) * WASU + cb4);

    // fill A (whole 128x128 bf16) -- 8 uint4 per thread
#pragma unroll
    for (int j = 0; j < 8; j++) {
        int flat = j * 256 + t;
        int row = flat >> 4, c4 = flat & 15;
        int gr = bm + row;
        const void* gp = A + (size_t)gr * 128 + c4 * 8;
        unsigned sp = sbase + 4u * (row * WASU + c4 * 4);
        cp16(sp, gp, (gr < M) ? 16 : 0);
    }
    // fill B block 0 into buf 0 (same group as A)
    {
        const __nv_bfloat16* Wb = W;
#pragma unroll
        for (int j = 0; j < 8; j++) {
            int flat = j * 256 + t;
            int row = flat >> 4, c4 = flat & 15;
            const void* gp = Wb + (size_t)row * 128 + c4 * 8;
            unsigned sp = sbase + 4u * (WA_U + row * WASU + c4 * 4);
            cp16(sp, gp, 16);
        }
    }
    asm volatile("cp.async.commit_group;");
    // fill B block 1 into buf 1
    if (NB > 1) {
        const __nv_bfloat16* Wb = W + (size_t)128 * 128;
#pragma unroll
        for (int j = 0; j < 8; j++) {
            int flat = j * 256 + t;
            int row = flat >> 4, c4 = flat & 15;
            const void* gp = Wb + (size_t)row * 128 + c4 * 8;
            unsigned sp = sbase + 4u * (2 * WA_U + row * WASU + c4 * 4);
            cp16(sp, gp, 16);
        }
    }
    asm volatile("cp.async.commit_group;");

    for (int bn = 0; bn < NB; bn++) {
        asm volatile("cp.async.wait_group 1;");
        __syncthreads();

        float c[4][4][4];
#pragma unroll
        for (int a = 0; a < 4; a++)
#pragma unroll
            for (int b = 0; b < 4; b++)
#pragma unroll
                for (int d = 0; d < 4; d++) c[a][b][d] = 0.f;

        int buf = bn & 1;
#pragma unroll
        for (int ks = 0; ks < 8; ks++) {
            unsigned bfr[4][2];
#pragma unroll
            for (int n2 = 0; n2 < 2; n2++) {
                unsigned r0, r1, r2, r3;
                ldx4(r0, r1, r2, r3, bAddrBuf[buf][n2] + ks * 32);
                bfr[2 * n2][0] = r0; bfr[2 * n2 + 1][0] = r1;
                bfr[2 * n2][1] = r2; bfr[2 * n2 + 1][1] = r3;
            }
#pragma unroll
            for (int mi = 0; mi < 4; mi++) {
                unsigned a0, a1, a2, a3;
                ldx4(a0, a1, a2, a3, aAddr[mi >> 1] + (mi & 1) * (16u * WASU * 4) + ks * 32);
#pragma unroll
                for (int ni = 0; ni < 4; ni++)
                    mma16816(c[mi][ni], a0, a1, a2, a3, bfr[ni][0], bfr[ni][1]);
            }
        }
        __syncthreads();   // done reading buf before refill
        if (bn + 2 < NB) {
            const __nv_bfloat16* Wb = W + (size_t)(bn + 2) * 128 * 128;
#pragma unroll
            for (int j = 0; j < 8; j++) {
                int flat = j * 256 + t;
                int row = flat >> 4, c4 = flat & 15;
                const void* gp = Wb + (size_t)row * 128 + c4 * 8;
                unsigned sp = sbase + 4u * ((1 + buf) * WA_U + row * WASU + c4 * 4);
                cp16(sp, gp, 16);
            }
        }
        asm volatile("cp.async.commit_group;");

        // epilogue for this bn
#pragma unroll
        for (int mi = 0; mi < 4; mi++) {
            int grow0 = bm + wm * 64 + mi * 16 + r;
            int grow1 = grow0 + 8;
#pragma unroll
            for (int ni = 0; ni < 4; ni++) {
                int col = bn * 128 + wn * 32 + ni * 8 + cp * 2;
                float bb0 = bias[col], bb1 = bias[col + 1];
                float v0 = c[mi][ni][0] + bb0, v1 = c[mi][ni][1] + bb1;
                float v2 = c[mi][ni][2] + bb0, v3 = c[mi][ni][3] + bb1;
                if (gelu) { v0 = gelu_f(v0); v1 = gelu_f(v1); v2 = gelu_f(v2); v3 = gelu_f(v3); }
                if (grow0 < M) {
                    __nv_bfloat162 h;
                    h.x = __float2bfloat16(v0); h.y = __float2bfloat16(v1);
                    *reinterpret_cast<__nv_bfloat162*>(&C[(size_t)grow0 * N + col]) = h;
                }
                if (grow1 < M) {
                    __nv_bfloat162 h;
                    h.x = __float2bfloat16(v2); h.y = __float2bfloat16(v3);
                    *reinterpret_cast<__nv_bfloat162*>(&C[(size_t)grow1 * N + col]) = h;
                }
            }
        }
    }
}

// ============ pipelined GEMM (Wo + LN1, FF2 + LN2) ============
#define SSTG 36
#define STAGE_U (128 * SSTG)
#define GEMM_SMEM (4 * STAGE_U * 4)  // 73728 B

// mode 3 only now: +bias +resid -> LayerNorm
__global__ __launch_bounds__(256) void gemm_kernel(int sel, int M, int N, int K,
                                                   const float* __restrict__ resid_in,
                                                   const float* __restrict__ gam,
                                                   const float* __restrict__ bet,
                                                   float* __restrict__ outp) {
    const __nv_bfloat16 *A, *W;
    const float* bias;
    if (sel == 1) { A = g_aggbf; W = g_wo; bias = g_bo; }
    else          { A = g_ff1bf; W = g_w2; bias = g_b2; }
    const float* resid = (sel == 1) ? resid_in : g_h;
    float* O32 = (sel == 1) ? g_h : outp;
    __nv_bfloat16* O16 = (sel == 1) ? g_hbf : nullptr;

    extern __shared__ unsigned sh[];

    int t = threadIdx.x;
    int warp = t >> 5, lane = t & 31;
    int wm = warp >> 2, wn = warp & 3;
    int bm = blockIdx.x * 128, bn = blockIdx.y * 128;
    int r = lane >> 2, cp = lane & 3;

    float c[4][4][4];
#pragma unroll
    for (int a = 0; a < 4; a++)
#pragma unroll
        for (int b = 0; b < 4; b++)
#pragma unroll
            for (int d = 0; d < 4; d++) c[a][b][d] = 0.f;

    unsigned sbase = (unsigned)__cvta_generic_to_shared(sh);

    int q = lane >> 3, lr = lane & 7;
    int rb = lr + (q & 1) * 8;
    int cb4 = (q >> 1) * 4;
    unsigned aAddr[2];
#pragma unroll
    for (int mi2 = 0; mi2 < 2; mi2++)
        aAddr[mi2] = sbase + 4u * ((wm * 64 + mi2 * 32 + rb) * SSTG + cb4);
    unsigned bAddr[2];
#pragma unroll
    for (int n2 = 0; n2 < 2; n2++)
        bAddr[n2] = sbase + 4u * (2 * STAGE_U + (wn * 32 + n2 * 16 + rb) * SSTG + cb4);

    const int S = K >> 6;

    auto fill = [&](int s) {
        int b = s & 1;
        int kc = s << 6;
#pragma unroll
        for (int j = 0; j < 4; j++) {
            int flat = j * 256 + t;
            int row = flat >> 3, c16 = flat & 7;
            int gr = bm + row;
            const void* gp = A + (size_t)gr * K + kc + c16 * 8;
            unsigned sp = sbase + 4u * (b * STAGE_U + row * SSTG + c16 * 4);
            cp16(sp, gp, (gr < M) ? 16 : 0);
        }
#pragma unroll
        for (int j = 0; j < 4; j++) {
            int flat = j * 256 + t;
            int row = flat >> 3, c16 = flat & 7;
            const void* gp = W + (size_t)(bn + row) * K + kc + c16 * 8;
            unsigned sp = sbase + 4u * (2 * STAGE_U + b * STAGE_U + row * SSTG + c16 * 4);
            cp16(sp, gp, 16);
        }
        asm volatile("cp.async.commit_group;");
    };

    fill(0);
    for (int s = 0; s < S; s++) {
        if (s + 1 < S) {
            fill(s + 1);
            asm volatile("cp.async.wait_group 1;");
        } else {
            asm volatile("cp.async.wait_group 0;");
        }
        __syncthreads();
        unsigned boff = (unsigned)((s & 1) * STAGE_U * 4);
#pragma unroll
        for (int ks = 0; ks < 4; ks++) {
            unsigned bfr[4][2];
#pragma unroll
            for (int n2 = 0; n2 < 2; n2++) {
                unsigned r0, r1, r2, r3;
                ldx4(r0, r1, r2, r3, bAddr[n2] + boff + ks * 32);
                bfr[2 * n2][0] = r0; bfr[2 * n2 + 1][0] = r1;
                bfr[2 * n2][1] = r2; bfr[2 * n2 + 1][1] = r3;
            }
#pragma unroll
            for (int mi = 0; mi < 4; mi++) {
                unsigned a0, a1, a2, a3;
                ldx4(a0, a1, a2, a3, aAddr[mi >> 1] + boff + (mi & 1) * (16u * SSTG * 4) + ks * 32);
#pragma unroll
                for (int ni = 0; ni < 4; ni++)
                    mma16816(c[mi][ni], a0, a1, a2, a3, bfr[ni][0], bfr[ni][1]);
            }
        }
        __syncthreads();
    }

    // fused residual + LayerNorm epilogue (N == 128)
    float* Cs = (float*)sh;  // [128][132]
#pragma unroll
    for (int mi = 0; mi < 4; mi++) {
        int rl0 = wm * 64 + mi * 16 + r;
#pragma unroll
        for (int ni = 0; ni < 4; ni++) {
            int col = wn * 32 + ni * 8 + cp * 2;
            Cs[rl0 * 132 + col]       = c[mi][ni][0];
            Cs[rl0 * 132 + col + 1]   = c[mi][ni][1];
            Cs[(rl0 + 8) * 132 + col]     = c[mi][ni][2];
            Cs[(rl0 + 8) * 132 + col + 1] = c[mi][ni][3];
        }
    }
    __syncthreads();
    int cbx = lane * 4;
    float b0 = bias[cbx], b1 = bias[cbx + 1], b2v = bias[cbx + 2], b3 = bias[cbx + 3];
    float gg0 = gam[cbx], gg1 = gam[cbx + 1], gg2 = gam[cbx + 2], gg3 = gam[cbx + 3];
    float bb0 = bet[cbx], bb1 = bet[cbx + 1], bb2 = bet[cbx + 2], bb3 = bet[cbx + 3];
#pragma unroll
    for (int i = 0; i < 16; i++) {
        int rl = warp * 16 + i;
        int grow = bm + rl;
        if (grow >= M) break;
        const float* rr = resid + (size_t)grow * 128 + cbx;
        float t0 = Cs[rl * 132 + cbx]     + b0 + rr[0];
        float t1 = Cs[rl * 132 + cbx + 1] + b1 + rr[1];
        float t2 = Cs[rl * 132 + cbx + 2] + b2v + rr[2];
        float t3 = Cs[rl * 132 + cbx + 3] + b3 + rr[3];
        float mu = warp_sum(t0 + t1 + t2 + t3) * (1.f / 128.f);
        float d0 = t0 - mu, d1 = t1 - mu, d2 = t2 - mu, d3 = t3 - mu;
        float var = warp_sum(d0 * d0 + d1 * d1 + d2 * d2 + d3 * d3) * (1.f / 128.f);
        float rs = rsqrtf(var + 1e-5f);
        float o0 = d0 * rs * gg0 + bb0;
        float o1 = d1 * rs * gg1 + bb1;
        float o2 = d2 * rs * gg2 + bb2;
        float o3 = d3 * rs * gg3 + bb3;
        *reinterpret_cast<float4*>(O32 + (size_t)grow * 128 + cbx) =
            make_float4(o0, o1, o2, o3);
        if (O16) {
            __nv_bfloat162 p0, p1;
            p0.x = __float2bfloat16(o0); p0.y = __float2bfloat16(o1);
            p1.x = __float2bfloat16(o2); p1.y = __float2bfloat16(o3);
            uint2 u;
            u.x = *reinterpret_cast<unsigned*>(&p0);
            u.y = *reinterpret_cast<unsigned*>(&p1);
            *reinterpret_cast<uint2*>(O16 + (size_t)grow * 128 + cbx) = u;
        }
    }
}

// ---------------- attention: lane = (edge-group, head); 4 edges in flight ----------------
__device__ __forceinline__ void ld16bf(float* f, const __nv_bfloat16* p) {
    uint4 u0 = *reinterpret_cast<const uint4*>(p);
    uint4 u1 = *reinterpret_cast<const uint4*>(p + 8);
    const unsigned* w = &u0.x;
#pragma unroll
    for (int j = 0; j < 4; j++) {
        float2 f2 = __bfloat1622float2(*reinterpret_cast<const __nv_bfloat162*>(&w[j]));
        f[2 * j] = f2.x; f[2 * j + 1] = f2.y;
    }
    const unsigned* w1 = &u1.x;
#pragma unroll
    for (int j = 0; j < 4; j++) {
        float2 f2 = __bfloat1622float2(*reinterpret_cast<const __nv_bfloat162*>(&w1[j]));
        f[8 + 2 * j] = f2.x; f[8 + 2 * j + 1] = f2.y;
    }
}

__global__ __launch_bounds__(256) void attn_kernel() {
    int w = (blockIdx.x * blockDim.x + threadIdx.x) >> 5;  // node
    if (w >= NN) return;
    int lane = threadIdx.x & 31;
    int g = lane >> 3;   // edge-group 0..3
    int h = lane & 7;    // head 0..7

    float qv[16];
    ld16bf(qv, g_qkv + (size_t)w * 384 + h * 16);

    int s = g_rowptr[w], e = g_rowptr[w + 1];
    int iters = (e - s + 3) >> 2;

    float denom = 0.f;
    float acc[16];
#pragma unroll
    for (int i = 0; i < 16; i++) acc[i] = 0.f;

    for (int it = 0; it < iters; it++) {
        int p = s + it * 4 + g;
        bool valid = p < e;
        int src = valid ? g_esrc[p] : 0;
        const __nv_bfloat16* base = g_qkv + (size_t)src * 384 + h * 16;
        float kv[16], vv[16];
        ld16bf(kv, base + 128);
        ld16bf(vv, base + 256);
        float d = 0.f;
#pragma unroll
        for (int i = 0; i < 16; i++) d += qv[i] * kv[i];
        float ea = valid ? __expf(d * 0.25f) : 0.f;
        denom += ea;
#pragma unroll
        for (int i = 0; i < 16; i++) acc[i] += ea * vv[i];
    }

    denom += __shfl_xor_sync(0xffffffffu, denom, 8);
    denom += __shfl_xor_sync(0xffffffffu, denom, 16);
#pragma unroll
    for (int i = 0; i < 16; i++) {
        acc[i] += __shfl_xor_sync(0xffffffffu, acc[i], 8);
        acc[i] += __shfl_xor_sync(0xffffffffu, acc[i], 16);
    }
    float inv = 1.f / (denom + 1e-16f);
    if (g == 0) {
        unsigned pk[8];
#pragma unroll
        for (int j = 0; j < 8; j++) {
            __nv_bfloat162 b;
            b.x = __float2bfloat16(acc[2 * j] * inv);
            b.y = __float2bfloat16(acc[2 * j + 1] * inv);
            pk[j] = *reinterpret_cast<unsigned*>(&b);
        }
        __nv_bfloat16* out = g_aggbf + (size_t)w * 128 + h * 16;
        *reinterpret_cast<uint4*>(out)     = make_uint4(pk[0], pk[1], pk[2], pk[3]);
        *reinterpret_cast<uint4*>(out + 8) = make_uint4(pk[4], pk[5], pk[6], pk[7]);
    }
}

// ---------------- launch ----------------
extern "C" void kernel_launch(void* const* d_in, const int* in_sizes, int n_in,
                              void* d_out, int out_size) {
    const float* x = (const float*)d_in[0];
    const void* ei = d_in[1];
    const float* Wq = (const float*)d_in[2];
    const float* bq = (const float*)d_in[3];
    const float* Wk = (const float*)d_in[4];
    const float* bk = (const float*)d_in[5];
    const float* Wv = (const float*)d_in[6];
    const float* bv = (const float*)d_in[7];
    const float* Wo = (const float*)d_in[8];
    const float* bo = (const float*)d_in[9];
    const float* W1 = (const float*)d_in[10];
    const float* b1 = (const float*)d_in[11];
    const float* W2 = (const float*)d_in[12];
    const float* b2 = (const float*)d_in[13];
    const float* g1 = (const float*)d_in[14];
    const float* be1 = (const float*)d_in[15];
    const float* g2 = (const float*)d_in[16];
    const float* be2 = (const float*)d_in[17];
    float* out = (float*)d_out;

    cudaFuncSetAttribute(gemm_kernel, cudaFuncAttributeMaxDynamicSharedMemorySize, GEMM_SMEM);
    cudaFuncSetAttribute(gemm_wide, cudaFuncAttributeMaxDynamicSharedMemorySize, WIDE_SMEM);

    // Lazily-created side stream + fork/join events (created on the first
    // uncaptured correctness call; reused during capture -> parallel branches).
    static cudaStream_t s_side = nullptr;
    static cudaEvent_t ev_fork = nullptr, ev_join = nullptr;
    if (s_side == nullptr) {
        if (cudaStreamCreateWithFlags(&s_side, cudaStreamNonBlocking) != cudaSuccess)
            s_side = nullptr;
        if (s_side) {
            cudaEventCreateWithFlags(&ev_fork, cudaEventDisableTiming);
            cudaEventCreateWithFlags(&ev_join, cudaEventDisableTiming);
        }
    }

    const int SCB = (NN + 1023) / 1024;  // 49

    if (s_side) {
        cudaEventRecord(ev_fork, 0);
        cudaStreamWaitEvent(s_side, ev_fork, 0);

        zero_fill<<<SCB, 1024, 0, s_side>>>();
        prep_edges<<<(EE + 255) / 256, 256, 0, s_side>>>(ei);
        scan_bt<<<SCB, 1024, 0, s_side>>>();
        scan_fix<<<SCB, 1024, 0, s_side>>>();
        scatter_kernel<<<(EE + 255) / 256, 256, 0, s_side>>>();
        cudaEventRecord(ev_join, s_side);

        prep_wx<<<(NN * HID + 255) / 256, 256>>>(x, Wq, bq, Wk, bk, Wv, bv, Wo, bo, W1, b1, W2, b2);
        gemm_wide<<<391, 256, WIDE_SMEM>>>(0, NN);   // QKV

        cudaStreamWaitEvent(0, ev_join, 0);
    } else {
        zero_fill<<<SCB, 1024>>>();
        prep_edges<<<(EE + 255) / 256, 256>>>(ei);
        scan_bt<<<SCB, 1024>>>();
        scan_fix<<<SCB, 1024>>>();
        scatter_kernel<<<(EE + 255) / 256, 256>>>();
        prep_wx<<<(NN * HID + 255) / 256, 256>>>(x, Wq, bq, Wk, bk, Wv, bv, Wo, bo, W1, b1, W2, b2);
        gemm_wide<<<391, 256, WIDE_SMEM>>>(0, NN);
    }

    attn_kernel<<<(NN * 32 + 255) / 256, 256>>>();                                    // agg
    gemm_kernel<<<dim3(391, 1), 256, GEMM_SMEM>>>(1, NN, 128, 128, x, g1, be1, nullptr); // Wo + LN1
    gemm_wide<<<391, 256, WIDE_SMEM>>>(2, NN);                                        // FF1 + gelu
    gemm_kernel<<<dim3(391, 1), 256, GEMM_SMEM>>>(3, NN, 128, 512, nullptr, g2, be2, out); // FF2 + LN2
}

// round 10
// speedup vs baseline: 1.0424x; 1.0424x over previous
#include <cuda_runtime.h>
#include <cuda_bf16.h>
#include <math.h>

#define NN 50000
#define EE 800000
#define HID 128
#define FFH 512

// ---------------- scratch (device globals: allocation-free) ----------------
__device__ __nv_bfloat16 g_xbf[(size_t)NN * HID];
__device__ __nv_bfloat16 g_wcat[384 * 128];
__device__ __nv_bfloat16 g_wo[128 * 128];
__device__ __nv_bfloat16 g_w1[512 * 128];
__device__ __nv_bfloat16 g_w2[128 * 512];
__device__ float g_bcat[384], g_bo[128], g_b1[512], g_b2[128];
__device__ __nv_bfloat16 g_qkv[(size_t)NN * 384];
__device__ int g_src[EE], g_dst[EE], g_esrc[EE];
__device__ int g_rowptr[NN + 1], g_fill[NN];
__device__ int g_bsum[64];
__device__ int g_arrive;   // static-init 0; reset to 0 by last block every call
__device__ __nv_bfloat16 g_aggbf[(size_t)NN * HID];
__device__ float g_h[(size_t)NN * HID];
__device__ __nv_bfloat16 g_hbf[(size_t)NN * HID];
__device__ __nv_bfloat16 g_ff1bf[(size_t)NN * FFH];

// ---------------- prep kernels ----------------
__global__ void zero_fill() {
    int i = blockIdx.x * blockDim.x + threadIdx.x;
    if (i < NN) g_fill[i] = 0;
}

__global__ void prep_edges(const void* __restrict__ ei) {
    int i = blockIdx.x * blockDim.x + threadIdx.x;
    if (i >= EE) return;
    // dtype sniff per-thread (L1-broadcast): int64 view of int32 data combines
    // two random node ids -> ~1e14, outside [0, NN). Deterministic.
    const long long* p64 = (const long long*)ei;
    int is64 = 1;
#pragma unroll
    for (int j = 0; j < 4; j++) {
        long long v = p64[j];
        if (v < 0 || v >= NN) is64 = 0;
    }
    long long s, d;
    if (is64) {
        s = p64[i];
        d = p64[(size_t)EE + i];
    } else {
        const int* p = (const int*)ei;
        s = p[i];
        d = p[(size_t)EE + i];
    }
    if (s < 0) s = 0; if (s >= NN) s = NN - 1;
    if (d < 0) d = 0; if (d >= NN) d = NN - 1;
    g_src[i] = (int)s;
    g_dst[i] = (int)d;
    atomicAdd(&g_fill[(int)d], 1);   // fused histogram
}

// fused block-scan + (last block) top-scan via arrival counter
__global__ void scan_bt() {
    __shared__ int sh[1024];
    __shared__ int s_old;
    int b = blockIdx.x, t = threadIdx.x;
    int i = b * 1024 + t;
    int d = (i < NN) ? g_fill[i] : 0;
    sh[t] = d;
    __syncthreads();
#pragma unroll
    for (int off = 1; off < 1024; off <<= 1) {
        int v = (t >= off) ? sh[t - off] : 0;
        __syncthreads();
        sh[t] += v;
        __syncthreads();
    }
    if (i < NN) g_rowptr[i] = sh[t] - d;  // exclusive, block-local
    if (t == 1023) {
        g_bsum[b] = sh[1023];
        __threadfence();
    }
    __syncthreads();
    if (t == 0) s_old = atomicAdd(&g_arrive, 1);
    __syncthreads();
    if (s_old == gridDim.x - 1) {
        int nb = gridDim.x;
        if (t < nb) sh[t] = *(volatile int*)&g_bsum[t];
        __syncthreads();
        if (t == 0) {
            int run = 0;
            for (int j = 0; j < nb; j++) { int v = sh[j]; sh[j] = run; run += v; }
            g_rowptr[NN] = run;
            g_arrive = 0;   // deterministic reset for next call
        }
        __syncthreads();
        if (t < nb) g_bsum[t] = sh[t];
    }
}

__global__ void scan_fix() {
    int b = blockIdx.x;
    int i = b * 1024 + threadIdx.x;
    if (i < NN) {
        int r = g_rowptr[i] + g_bsum[b];
        g_rowptr[i] = r;
        g_fill[i] = r;
    }
}

__global__ void scatter_kernel() {
    int i = blockIdx.x * blockDim.x + threadIdx.x;
    if (i < EE) {
        int d = g_dst[i];
        int p = atomicAdd(&g_fill[d], 1);
        g_esrc[p] = g_src[i];
    }
}

// fused: x -> bf16 conversion + weight conversion + bias staging
__global__ void prep_wx(const float* __restrict__ x,
                        const float* __restrict__ Wq, const float* __restrict__ bq,
                        const float* __restrict__ Wk, const float* __restrict__ bk,
                        const float* __restrict__ Wv, const float* __restrict__ bv,
                        const float* __restrict__ Wo, const float* __restrict__ bo,
                        const float* __restrict__ W1, const float* __restrict__ b1,
                        const float* __restrict__ W2, const float* __restrict__ b2) {
    int i = blockIdx.x * blockDim.x + threadIdx.x;
    if (i < NN * HID) g_xbf[i] = __float2bfloat16(x[i]);
    if (i < 128 * 128) {
        g_wcat[i]         = __float2bfloat16(Wq[i]);
        g_wcat[16384 + i] = __float2bfloat16(Wk[i]);
        g_wcat[32768 + i] = __float2bfloat16(Wv[i]);
        g_wo[i]           = __float2bfloat16(Wo[i]);
    }
    if (i < 512 * 128) {
        g_w1[i] = __float2bfloat16(W1[i]);
        g_w2[i] = __float2bfloat16(W2[i]);
    }
    if (i < 128) {
        g_bcat[i] = bq[i];
        g_bcat[128 + i] = bk[i];
        g_bcat[256 + i] = bv[i];
        g_bo[i] = bo[i];
        g_b2[i] = b2[i];
    }
    if (i < 512) g_b1[i] = b1[i];
}

// ---------------- bf16 tensor-core GEMM ----------------
__device__ __forceinline__ void mma16816(float c[4], unsigned a0, unsigned a1, unsigned a2,
                                         unsigned a3, unsigned b0, unsigned b1) {
    asm volatile(
        "mma.sync.aligned.m16n8k16.row.col.f32.bf16.bf16.f32 "
        "{%0,%1,%2,%3}, {%4,%5,%6,%7}, {%8,%9}, {%0,%1,%2,%3};\n"
        : "+f"(c[0]), "+f"(c[1]), "+f"(c[2]), "+f"(c[3])
        : "r"(a0), "r"(a1), "r"(a2), "r"(a3), "r"(b0), "r"(b1));
}

__device__ __forceinline__ void ldx4(unsigned& r0, unsigned& r1, unsigned& r2, unsigned& r3,
                                     unsigned addr) {
    asm volatile("ldmatrix.sync.aligned.m8n8.x4.shared.b16 {%0,%1,%2,%3}, [%4];"
                 : "=r"(r0), "=r"(r1), "=r"(r2), "=r"(r3)
                 : "r"(addr));
}

__device__ __forceinline__ void cp16(unsigned saddr, const void* gaddr, int szbytes) {
    asm volatile("cp.async.cg.shared.global [%0], [%1], 16, %2;"
                 :: "r"(saddr), "l"(gaddr), "r"(szbytes));
}

__device__ __forceinline__ float warp_sum(float s) {
#pragma unroll
    for (int o = 16; o > 0; o >>= 1) s += __shfl_xor_sync(0xffffffffu, s, o);
    return s;
}

__device__ __forceinline__ float gelu_f(float v) {
    return 0.5f * v * (1.0f + erff(v * 0.70710678118654752f));
}

// 64-deep K stages, TRIPLE buffered (3 stages in flight for K=512).
#define SSTG 36
#define STAGE_U (128 * SSTG)
#define NSTAGE 3
#define GEMM_SMEM (2 * NSTAGE * STAGE_U * 4)  // 110592 B; 2 CTAs/SM

// block tile 128(M) x 128(N), 8 warps as 2(m) x 4(n), warp tile 64x32
// modes: 1 = bf16 store, 2 = gelu+bf16 store, 3 = +bias +resid -> LayerNorm
__global__ __launch_bounds__(256) void gemm_kernel(int sel, int M, int N, int K,
                                                   const float* __restrict__ resid_in,
                                                   const float* __restrict__ gam,
                                                   const float* __restrict__ bet,
                                                   float* __restrict__ outp) {
    const __nv_bfloat16 *A, *W;
    const float* bias;
    __nv_bfloat16* C16 = nullptr;
    int mode;
    if (sel == 0)      { A = g_xbf;   W = g_wcat; bias = g_bcat; mode = 1; C16 = g_qkv; }
    else if (sel == 1) { A = g_aggbf; W = g_wo;   bias = g_bo;   mode = 3; }
    else if (sel == 2) { A = g_hbf;   W = g_w1;   bias = g_b1;   mode = 2; C16 = g_ff1bf; }
    else               { A = g_ff1bf; W = g_w2;   bias = g_b2;   mode = 3; }
    const float* resid = (sel == 1) ? resid_in : g_h;
    float* O32 = (sel == 1) ? g_h : outp;
    __nv_bfloat16* O16 = (sel == 1) ? g_hbf : nullptr;

    extern __shared__ unsigned sh[];
    // layout: A stages [0..2]*STAGE_U, B stages [3..5]*STAGE_U

    int t = threadIdx.x;
    int warp = t >> 5, lane = t & 31;
    int wm = warp >> 2, wn = warp & 3;
    int bm = blockIdx.x * 128, bn = blockIdx.y * 128;
    int r = lane >> 2, cp = lane & 3;

    float c[4][4][4];
#pragma unroll
    for (int a = 0; a < 4; a++)
#pragma unroll
        for (int b = 0; b < 4; b++)
#pragma unroll
            for (int d = 0; d < 4; d++) c[a][b][d] = 0.f;

    unsigned sbase = (unsigned)__cvta_generic_to_shared(sh);

    int q = lane >> 3, lr = lane & 7;
    int rb = lr + (q & 1) * 8;
    int cb4 = (q >> 1) * 4;
    unsigned aAddr[2];
#pragma unroll
    for (int mi2 = 0; mi2 < 2; mi2++)
        aAddr[mi2] = sbase + 4u * ((wm * 64 + mi2 * 32 + rb) * SSTG + cb4);
    unsigned bAddr[2];
#pragma unroll
    for (int n2 = 0; n2 < 2; n2++)
        bAddr[n2] = sbase + 4u * (NSTAGE * STAGE_U + (wn * 32 + n2 * 16 + rb) * SSTG + cb4);

    const int S = K >> 6;

    auto fill = [&](int s) {
        int b = s % NSTAGE;
        int kc = s << 6;
#pragma unroll
        for (int j = 0; j < 4; j++) {
            int flat = j * 256 + t;
            int row = flat >> 3, c16 = flat & 7;
            int gr = bm + row;
            const void* gp = A + (size_t)gr * K + kc + c16 * 8;
            unsigned sp = sbase + 4u * (b * STAGE_U + row * SSTG + c16 * 4);
            cp16(sp, gp, (gr < M) ? 16 : 0);
        }
#pragma unroll
        for (int j = 0; j < 4; j++) {
            int flat = j * 256 + t;
            int row = flat >> 3, c16 = flat & 7;
            const void* gp = W + (size_t)(bn + row) * K + kc + c16 * 8;
            unsigned sp = sbase + 4u * ((NSTAGE + b) * STAGE_U + row * SSTG + c16 * 4);
            cp16(sp, gp, 16);
        }
        asm volatile("cp.async.commit_group;");
    };

    fill(0);
    if (S > 1) fill(1);
    for (int s = 0; s < S; s++) {
        if (s + 1 < S) {
            asm volatile("cp.async.wait_group 1;");
        } else {
            asm volatile("cp.async.wait_group 0;");
        }
        __syncthreads();
        unsigned boff = (unsigned)((s % NSTAGE) * STAGE_U * 4);
#pragma unroll
        for (int ks = 0; ks < 4; ks++) {
            unsigned bfr[4][2];
#pragma unroll
            for (int n2 = 0; n2 < 2; n2++) {
                unsigned r0, r1, r2, r3;
                ldx4(r0, r1, r2, r3, bAddr[n2] + boff + ks * 32);
                bfr[2 * n2][0] = r0; bfr[2 * n2 + 1][0] = r1;
                bfr[2 * n2][1] = r2; bfr[2 * n2 + 1][1] = r3;
            }
#pragma unroll
            for (int mi = 0; mi < 4; mi++) {
                unsigned a0, a1, a2, a3;
                ldx4(a0, a1, a2, a3, aAddr[mi >> 1] + boff + (mi & 1) * (16u * SSTG * 4) + ks * 32);
#pragma unroll
                for (int ni = 0; ni < 4; ni++)
                    mma16816(c[mi][ni], a0, a1, a2, a3, bfr[ni][0], bfr[ni][1]);
            }
        }
        __syncthreads();
        if (s + 2 < S) fill(s + 2);   // buffer (s+2)%3 == (s-1)%3, freed after compute(s-1)
    }

    if (mode != 3) {
#pragma unroll
        for (int mi = 0; mi < 4; mi++) {
            int grow0 = bm + wm * 64 + mi * 16 + r;
            int grow1 = grow0 + 8;
#pragma unroll
            for (int ni = 0; ni < 4; ni++) {
                int col = bn + wn * 32 + ni * 8 + cp * 2;
                float bb0 = bias[col], bb1 = bias[col + 1];
                float v0 = c[mi][ni][0] + bb0, v1 = c[mi][ni][1] + bb1;
                float v2 = c[mi][ni][2] + bb0, v3 = c[mi][ni][3] + bb1;
                if (mode == 2) { v0 = gelu_f(v0); v1 = gelu_f(v1); v2 = gelu_f(v2); v3 = gelu_f(v3); }
                if (grow0 < M) {
                    __nv_bfloat162 h;
                    h.x = __float2bfloat16(v0); h.y = __float2bfloat16(v1);
                    *reinterpret_cast<__nv_bfloat162*>(&C16[(size_t)grow0 * N + col]) = h;
                }
                if (grow1 < M) {
                    __nv_bfloat162 h;
                    h.x = __float2bfloat16(v2); h.y = __float2bfloat16(v3);
                    *reinterpret_cast<__nv_bfloat162*>(&C16[(size_t)grow1 * N + col]) = h;
                }
            }
        }
    } else {
        // fused residual + LayerNorm epilogue (N == 128, single bn block)
        float* Cs = (float*)sh;  // [128][132] = 67584 B <= GEMM_SMEM
#pragma unroll
        for (int mi = 0; mi < 4; mi++) {
            int rl0 = wm * 64 + mi * 16 + r;
#pragma unroll
            for (int ni = 0; ni < 4; ni++) {
                int col = wn * 32 + ni * 8 + cp * 2;
                Cs[rl0 * 132 + col]       = c[mi][ni][0];
                Cs[rl0 * 132 + col + 1]   = c[mi][ni][1];
                Cs[(rl0 + 8) * 132 + col]     = c[mi][ni][2];
                Cs[(rl0 + 8) * 132 + col + 1] = c[mi][ni][3];
            }
        }
        __syncthreads();
        int cbx = lane * 4;
        float b0 = bias[cbx], b1 = bias[cbx + 1], b2v = bias[cbx + 2], b3 = bias[cbx + 3];
        float gg0 = gam[cbx], gg1 = gam[cbx + 1], gg2 = gam[cbx + 2], gg3 = gam[cbx + 3];
        float bb0 = bet[cbx], bb1 = bet[cbx + 1], bb2 = bet[cbx + 2], bb3 = bet[cbx + 3];
#pragma unroll
        for (int i = 0; i < 16; i++) {
            int rl = warp * 16 + i;
            int grow = bm + rl;
            if (grow >= M) break;
            const float* rr = resid + (size_t)grow * 128 + cbx;
            float t0 = Cs[rl * 132 + cbx]     + b0 + rr[0];
            float t1 = Cs[rl * 132 + cbx + 1] + b1 + rr[1];
            float t2 = Cs[rl * 132 + cbx + 2] + b2v + rr[2];
            float t3 = Cs[rl * 132 + cbx + 3] + b3 + rr[3];
            float mu = warp_sum(t0 + t1 + t2 + t3) * (1.f / 128.f);
            float d0 = t0 - mu, d1 = t1 - mu, d2 = t2 - mu, d3 = t3 - mu;
            float var = warp_sum(d0 * d0 + d1 * d1 + d2 * d2 + d3 * d3) * (1.f / 128.f);
            float rs = rsqrtf(var + 1e-5f);
            float o0 = d0 * rs * gg0 + bb0;
            float o1 = d1 * rs * gg1 + bb1;
            float o2 = d2 * rs * gg2 + bb2;
            float o3 = d3 * rs * gg3 + bb3;
            *reinterpret_cast<float4*>(O32 + (size_t)grow * 128 + cbx) =
                make_float4(o0, o1, o2, o3);
            if (O16) {
                __nv_bfloat162 p0, p1;
                p0.x = __float2bfloat16(o0); p0.y = __float2bfloat16(o1);
                p1.x = __float2bfloat16(o2); p1.y = __float2bfloat16(o3);
                uint2 u;
                u.x = *reinterpret_cast<unsigned*>(&p0);
                u.y = *reinterpret_cast<unsigned*>(&p1);
                *reinterpret_cast<uint2*>(O16 + (size_t)grow * 128 + cbx) = u;
            }
        }
    }
}

// ---------------- attention: lane = (edge-group, head); 4 edges in flight ----------------
__device__ __forceinline__ void ld16bf(float* f, const __nv_bfloat16* p) {
    uint4 u0 = *reinterpret_cast<const uint4*>(p);
    uint4 u1 = *reinterpret_cast<const uint4*>(p + 8);
    const unsigned* w = &u0.x;
#pragma unroll
    for (int j = 0; j < 4; j++) {
        float2 f2 = __bfloat1622float2(*reinterpret_cast<const __nv_bfloat162*>(&w[j]));
        f[2 * j] = f2.x; f[2 * j + 1] = f2.y;
    }
    const unsigned* w1 = &u1.x;
#pragma unroll
    for (int j = 0; j < 4; j++) {
        float2 f2 = __bfloat1622float2(*reinterpret_cast<const __nv_bfloat162*>(&w1[j]));
        f[8 + 2 * j] = f2.x; f[8 + 2 * j + 1] = f2.y;
    }
}

__global__ __launch_bounds__(256) void attn_kernel() {
    int w = (blockIdx.x * blockDim.x + threadIdx.x) >> 5;  // node
    if (w >= NN) return;
    int lane = threadIdx.x & 31;
    int g = lane >> 3;   // edge-group 0..3
    int h = lane & 7;    // head 0..7

    float qv[16];
    ld16bf(qv, g_qkv + (size_t)w * 384 + h * 16);

    int s = g_rowptr[w], e = g_rowptr[w + 1];
    int iters = (e - s + 3) >> 2;

    float denom = 0.f;
    float acc[16];
#pragma unroll
    for (int i = 0; i < 16; i++) acc[i] = 0.f;

    for (int it = 0; it < iters; it++) {
        int p = s + it * 4 + g;
        bool valid = p < e;
        int src = valid ? g_esrc[p] : 0;
        const __nv_bfloat16* base = g_qkv + (size_t)src * 384 + h * 16;
        float kv[16], vv[16];
        ld16bf(kv, base + 128);
        ld16bf(vv, base + 256);
        float d = 0.f;
#pragma unroll
        for (int i = 0; i < 16; i++) d += qv[i] * kv[i];
        float ea = valid ? __expf(d * 0.25f) : 0.f;
        denom += ea;
#pragma unroll
        for (int i = 0; i < 16; i++) acc[i] += ea * vv[i];
    }

    denom += __shfl_xor_sync(0xffffffffu, denom, 8);
    denom += __shfl_xor_sync(0xffffffffu, denom, 16);
#pragma unroll
    for (int i = 0; i < 16; i++) {
        acc[i] += __shfl_xor_sync(0xffffffffu, acc[i], 8);
        acc[i] += __shfl_xor_sync(0xffffffffu, acc[i], 16);
    }
    float inv = 1.f / (denom + 1e-16f);
    if (g == 0) {
        unsigned pk[8];
#pragma unroll
        for (int j = 0; j < 8; j++) {
            __nv_bfloat162 b;
            b.x = __float2bfloat16(acc[2 * j] * inv);
            b.y = __float2bfloat16(acc[2 * j + 1] * inv);
            pk[j] = *reinterpret_cast<unsigned*>(&b);
        }
        __nv_bfloat16* out = g_aggbf + (size_t)w * 128 + h * 16;
        *reinterpret_cast<uint4*>(out)     = make_uint4(pk[0], pk[1], pk[2], pk[3]);
        *reinterpret_cast<uint4*>(out + 8) = make_uint4(pk[4], pk[5], pk[6], pk[7]);
    }
}

// ---------------- launch ----------------
extern "C" void kernel_launch(void* const* d_in, const int* in_sizes, int n_in,
                              void* d_out, int out_size) {
    const float* x = (const float*)d_in[0];
    const void* ei = d_in[1];
    const float* Wq = (const float*)d_in[2];
    const float* bq = (const float*)d_in[3];
    const float* Wk = (const float*)d_in[4];
    const float* bk = (const float*)d_in[5];
    const float* Wv = (const float*)d_in[6];
    const float* bv = (const float*)d_in[7];
    const float* Wo = (const float*)d_in[8];
    const float* bo = (const float*)d_in[9];
    const float* W1 = (const float*)d_in[10];
    const float* b1 = (const float*)d_in[11];
    const float* W2 = (const float*)d_in[12];
    const float* b2 = (const float*)d_in[13];
    const float* g1 = (const float*)d_in[14];
    const float* be1 = (const float*)d_in[15];
    const float* g2 = (const float*)d_in[16];
    const float* be2 = (const float*)d_in[17];
    float* out = (float*)d_out;

    cudaFuncSetAttribute(gemm_kernel, cudaFuncAttributeMaxDynamicSharedMemorySize, GEMM_SMEM);

    // Lazily-created side stream + fork/join events (created on the first
    // uncaptured correctness call; reused during capture -> parallel branches).
    static cudaStream_t s_side = nullptr;
    static cudaEvent_t ev_fork = nullptr, ev_join = nullptr;
    if (s_side == nullptr) {
        if (cudaStreamCreateWithFlags(&s_side, cudaStreamNonBlocking) != cudaSuccess)
            s_side = nullptr;
        if (s_side) {
            cudaEventCreateWithFlags(&ev_fork, cudaEventDisableTiming);
            cudaEventCreateWithFlags(&ev_join, cudaEventDisableTiming);
        }
    }

    const int SCB = (NN + 1023) / 1024;  // 49

    if (s_side) {
        cudaEventRecord(ev_fork, 0);
        cudaStreamWaitEvent(s_side, ev_fork, 0);

        zero_fill<<<SCB, 1024, 0, s_side>>>();
        prep_edges<<<(EE + 255) / 256, 256, 0, s_side>>>(ei);
        scan_bt<<<SCB, 1024, 0, s_side>>>();
        scan_fix<<<SCB, 1024, 0, s_side>>>();
        scatter_kernel<<<(EE + 255) / 256, 256, 0, s_side>>>();
        cudaEventRecord(ev_join, s_side);

        prep_wx<<<(NN * HID + 255) / 256, 256>>>(x, Wq, bq, Wk, bk, Wv, bv, Wo, bo, W1, b1, W2, b2);
        gemm_kernel<<<dim3(391, 3), 256, GEMM_SMEM>>>(0, NN, 384, 128, nullptr, nullptr, nullptr, nullptr); // QKV

        cudaStreamWaitEvent(0, ev_join, 0);
    } else {
        zero_fill<<<SCB, 1024>>>();
        prep_edges<<<(EE + 255) / 256, 256>>>(ei);
        scan_bt<<<SCB, 1024>>>();
        scan_fix<<<SCB, 1024>>>();
        scatter_kernel<<<(EE + 255) / 256, 256>>>();
        prep_wx<<<(NN * HID + 255) / 256, 256>>>(x, Wq, bq, Wk, bk, Wv, bv, Wo, bo, W1, b1, W2, b2);
        gemm_kernel<<<dim3(391, 3), 256, GEMM_SMEM>>>(0, NN, 384, 128, nullptr, nullptr, nullptr, nullptr);
    }

    attn_kernel<<<(NN * 32 + 255) / 256, 256>>>();                                                       // agg
    gemm_kernel<<<dim3(391, 1), 256, GEMM_SMEM>>>(1, NN, 128, 128, x, g1, be1, nullptr);                 // Wo + LN1
    gemm_kernel<<<dim3(391, 4), 256, GEMM_SMEM>>>(2, NN, 512, 128, nullptr, nullptr, nullptr, nullptr);  // W1 + gelu
    gemm_kernel<<<dim3(391, 1), 256, GEMM_SMEM>>>(3, NN, 128, 512, nullptr, g2, be2, out);               // W2 + LN2
}

// round 11
// speedup vs baseline: 1.4965x; 1.4357x over previous
#include <cuda_runtime.h>
#include <cuda_bf16.h>
#include <math.h>

#define NN 50000
#define EE 800000
#define HID 128
#define FFH 512

// ---------------- scratch (device globals: allocation-free) ----------------
__device__ __nv_bfloat16 g_xbf[(size_t)NN * HID];
__device__ __nv_bfloat16 g_wcat[384 * 128];
__device__ __nv_bfloat16 g_wo[128 * 128];
__device__ __nv_bfloat16 g_w1[512 * 128];
__device__ __nv_bfloat16 g_w2[128 * 512];
__device__ float g_bcat[384], g_bo[128], g_b1[512], g_b2[128];
__device__ __nv_bfloat16 g_qkv[(size_t)NN * 384];
__device__ int g_src[EE], g_dst[EE], g_esrc[EE];
__device__ int g_rowptr[NN + 1], g_fill[NN];
__device__ int g_bsum[64];
__device__ int g_arrive;   // static-init 0; reset to 0 by last block every call
__device__ __nv_bfloat16 g_aggbf[(size_t)NN * HID];
__device__ float g_h[(size_t)NN * HID];
__device__ __nv_bfloat16 g_hbf[(size_t)NN * HID];
__device__ __nv_bfloat16 g_ff1bf[(size_t)NN * FFH];

// ---------------- prep kernels ----------------
__global__ void zero_fill() {
    int i = blockIdx.x * blockDim.x + threadIdx.x;
    if (i < NN) g_fill[i] = 0;
}

__global__ void prep_edges(const void* __restrict__ ei) {
    int i = blockIdx.x * blockDim.x + threadIdx.x;
    if (i >= EE) return;
    // dtype sniff per-thread (L1-broadcast): int64 view of int32 data combines
    // two random node ids -> ~1e14, outside [0, NN). Deterministic.
    const long long* p64 = (const long long*)ei;
    int is64 = 1;
#pragma unroll
    for (int j = 0; j < 4; j++) {
        long long v = p64[j];
        if (v < 0 || v >= NN) is64 = 0;
    }
    long long s, d;
    if (is64) {
        s = p64[i];
        d = p64[(size_t)EE + i];
    } else {
        const int* p = (const int*)ei;
        s = p[i];
        d = p[(size_t)EE + i];
    }
    if (s < 0) s = 0; if (s >= NN) s = NN - 1;
    if (d < 0) d = 0; if (d >= NN) d = NN - 1;
    g_src[i] = (int)s;
    g_dst[i] = (int)d;
    atomicAdd(&g_fill[(int)d], 1);   // fused histogram
}

// fused block-scan + (last block) top-scan via arrival counter
__global__ void scan_bt() {
    __shared__ int sh[1024];
    __shared__ int s_old;
    int b = blockIdx.x, t = threadIdx.x;
    int i = b * 1024 + t;
    int d = (i < NN) ? g_fill[i] : 0;
    sh[t] = d;
    __syncthreads();
#pragma unroll
    for (int off = 1; off < 1024; off <<= 1) {
        int v = (t >= off) ? sh[t - off] : 0;
        __syncthreads();
        sh[t] += v;
        __syncthreads();
    }
    if (i < NN) g_rowptr[i] = sh[t] - d;  // exclusive, block-local
    if (t == 1023) {
        g_bsum[b] = sh[1023];
        __threadfence();
    }
    __syncthreads();
    if (t == 0) s_old = atomicAdd(&g_arrive, 1);
    __syncthreads();
    if (s_old == gridDim.x - 1) {
        int nb = gridDim.x;
        if (t < nb) sh[t] = *(volatile int*)&g_bsum[t];
        __syncthreads();
        if (t == 0) {
            int run = 0;
            for (int j = 0; j < nb; j++) { int v = sh[j]; sh[j] = run; run += v; }
            g_rowptr[NN] = run;
            g_arrive = 0;   // deterministic reset for next call
        }
        __syncthreads();
        if (t < nb) g_bsum[t] = sh[t];
    }
}

__global__ void scan_fix() {
    int b = blockIdx.x;
    int i = b * 1024 + threadIdx.x;
    if (i < NN) {
        int r = g_rowptr[i] + g_bsum[b];
        g_rowptr[i] = r;
        g_fill[i] = r;
    }
}

__global__ void scatter_kernel() {
    int i = blockIdx.x * blockDim.x + threadIdx.x;
    if (i < EE) {
        int d = g_dst[i];
        int p = atomicAdd(&g_fill[d], 1);
        g_esrc[p] = g_src[i];
    }
}

// critical path prep: x -> bf16, Wq/Wk/Wv -> g_wcat, all biases
__global__ void prep_qkv(const float* __restrict__ x,
                         const float* __restrict__ Wq, const float* __restrict__ bq,
                         const float* __restrict__ Wk, const float* __restrict__ bk,
                         const float* __restrict__ Wv, const float* __restrict__ bv,
                         const float* __restrict__ bo, const float* __restrict__ b1,
                         const float* __restrict__ b2) {
    int i = blockIdx.x * blockDim.x + threadIdx.x;
    if (i < NN * HID) g_xbf[i] = __float2bfloat16(x[i]);
    if (i < 128 * 128) {
        g_wcat[i]         = __float2bfloat16(Wq[i]);
        g_wcat[16384 + i] = __float2bfloat16(Wk[i]);
        g_wcat[32768 + i] = __float2bfloat16(Wv[i]);
    }
    if (i < 128) {
        g_bcat[i] = bq[i];
        g_bcat[128 + i] = bk[i];
        g_bcat[256 + i] = bv[i];
        g_bo[i] = bo[i];
        g_b2[i] = b2[i];
    }
    if (i < 512) g_b1[i] = b1[i];
}

// off-critical-path prep (hidden on side stream): Wo/W1/W2 -> bf16
__global__ void prep_w(const float* __restrict__ Wo, const float* __restrict__ W1,
                       const float* __restrict__ W2) {
    int i = blockIdx.x * blockDim.x + threadIdx.x;
    if (i < 128 * 128) g_wo[i] = __float2bfloat16(Wo[i]);
    if (i < 512 * 128) {
        g_w1[i] = __float2bfloat16(W1[i]);
        g_w2[i] = __float2bfloat16(W2[i]);
    }
}

// ---------------- bf16 tensor-core GEMM ----------------
__device__ __forceinline__ void mma16816(float c[4], unsigned a0, unsigned a1, unsigned a2,
                                         unsigned a3, unsigned b0, unsigned b1) {
    asm volatile(
        "mma.sync.aligned.m16n8k16.row.col.f32.bf16.bf16.f32 "
        "{%0,%1,%2,%3}, {%4,%5,%6,%7}, {%8,%9}, {%0,%1,%2,%3};\n"
        : "+f"(c[0]), "+f"(c[1]), "+f"(c[2]), "+f"(c[3])
        : "r"(a0), "r"(a1), "r"(a2), "r"(a3), "r"(b0), "r"(b1));
}

__device__ __forceinline__ void ldx4(unsigned& r0, unsigned& r1, unsigned& r2, unsigned& r3,
                                     unsigned addr) {
    asm volatile("ldmatrix.sync.aligned.m8n8.x4.shared.b16 {%0,%1,%2,%3}, [%4];"
                 : "=r"(r0), "=r"(r1), "=r"(r2), "=r"(r3)
                 : "r"(addr));
}

__device__ __forceinline__ void cp16(unsigned saddr, const void* gaddr, int szbytes) {
    asm volatile("cp.async.cg.shared.global [%0], [%1], 16, %2;"
                 :: "r"(saddr), "l"(gaddr), "r"(szbytes));
}

__device__ __forceinline__ float warp_sum(float s) {
#pragma unroll
    for (int o = 16; o > 0; o >>= 1) s += __shfl_xor_sync(0xffffffffu, s, o);
    return s;
}

__device__ __forceinline__ float gelu_f(float v) {
    return 0.5f * v * (1.0f + erff(v * 0.70710678118654752f));
}

// 64-deep K stages, double buffered (R8 configuration: 2 CTAs/SM).
#define SSTG 36
#define STAGE_U (128 * SSTG)
#define GEMM_SMEM (4 * STAGE_U * 4)  // 73728 B

// block tile 128(M) x 128(N), 8 warps as 2(m) x 4(n), warp tile 64x32
// modes: 1 = bf16 store, 2 = gelu+bf16 store, 3 = +bias +resid -> LayerNorm
__global__ __launch_bounds__(256) void gemm_kernel(int sel, int M, int N, int K,
                                                   const float* __restrict__ resid_in,
                                                   const float* __restrict__ gam,
                                                   const float* __restrict__ bet,
                                                   float* __restrict__ outp) {
    const __nv_bfloat16 *A, *W;
    const float* bias;
    __nv_bfloat16* C16 = nullptr;
    int mode;
    if (sel == 0)      { A = g_xbf;   W = g_wcat; bias = g_bcat; mode = 1; C16 = g_qkv; }
    else if (sel == 1) { A = g_aggbf; W = g_wo;   bias = g_bo;   mode = 3; }
    else if (sel == 2) { A = g_hbf;   W = g_w1;   bias = g_b1;   mode = 2; C16 = g_ff1bf; }
    else               { A = g_ff1bf; W = g_w2;   bias = g_b2;   mode = 3; }
    const float* resid = (sel == 1) ? resid_in : g_h;
    float* O32 = (sel == 1) ? g_h : outp;
    __nv_bfloat16* O16 = (sel == 1) ? g_hbf : nullptr;

    extern __shared__ unsigned sh[];

    int t = threadIdx.x;
    int warp = t >> 5, lane = t & 31;
    int wm = warp >> 2, wn = warp & 3;
    int bm = blockIdx.x * 128, bn = blockIdx.y * 128;
    int r = lane >> 2, cp = lane & 3;

    float c[4][4][4];
#pragma unroll
    for (int a = 0; a < 4; a++)
#pragma unroll
        for (int b = 0; b < 4; b++)
#pragma unroll
            for (int d = 0; d < 4; d++) c[a][b][d] = 0.f;

    unsigned sbase = (unsigned)__cvta_generic_to_shared(sh);

    int q = lane >> 3, lr = lane & 7;
    int rb = lr + (q & 1) * 8;
    int cb4 = (q >> 1) * 4;
    unsigned aAddr[2];
#pragma unroll
    for (int mi2 = 0; mi2 < 2; mi2++)
        aAddr[mi2] = sbase + 4u * ((wm * 64 + mi2 * 32 + rb) * SSTG + cb4);
    unsigned bAddr[2];
#pragma unroll
    for (int n2 = 0; n2 < 2; n2++)
        bAddr[n2] = sbase + 4u * (2 * STAGE_U + (wn * 32 + n2 * 16 + rb) * SSTG + cb4);

    const int S = K >> 6;

    auto fill = [&](int s) {
        int b = s & 1;
        int kc = s << 6;
#pragma unroll
        for (int j = 0; j < 4; j++) {
            int flat = j * 256 + t;
            int row = flat >> 3, c16 = flat & 7;
            int gr = bm + row;
            const void* gp = A + (size_t)gr * K + kc + c16 * 8;
            unsigned sp = sbase + 4u * (b * STAGE_U + row * SSTG + c16 * 4);
            cp16(sp, gp, (gr < M) ? 16 : 0);
        }
#pragma unroll
        for (int j = 0; j < 4; j++) {
            int flat = j * 256 + t;
            int row = flat >> 3, c16 = flat & 7;
            const void* gp = W + (size_t)(bn + row) * K + kc + c16 * 8;
            unsigned sp = sbase + 4u * (2 * STAGE_U + b * STAGE_U + row * SSTG + c16 * 4);
            cp16(sp, gp, 16);
        }
        asm volatile("cp.async.commit_group;");
    };

    fill(0);
    for (int s = 0; s < S; s++) {
        if (s + 1 < S) {
            fill(s + 1);
            asm volatile("cp.async.wait_group 1;");
        } else {
            asm volatile("cp.async.wait_group 0;");
        }
        __syncthreads();
        unsigned boff = (unsigned)((s & 1) * STAGE_U * 4);
#pragma unroll
        for (int ks = 0; ks < 4; ks++) {
            unsigned bfr[4][2];
#pragma unroll
            for (int n2 = 0; n2 < 2; n2++) {
                unsigned r0, r1, r2, r3;
                ldx4(r0, r1, r2, r3, bAddr[n2] + boff + ks * 32);
                bfr[2 * n2][0] = r0; bfr[2 * n2 + 1][0] = r1;
                bfr[2 * n2][1] = r2; bfr[2 * n2 + 1][1] = r3;
            }
#pragma unroll
            for (int mi = 0; mi < 4; mi++) {
                unsigned a0, a1, a2, a3;
                ldx4(a0, a1, a2, a3, aAddr[mi >> 1] + boff + (mi & 1) * (16u * SSTG * 4) + ks * 32);
#pragma unroll
                for (int ni = 0; ni < 4; ni++)
                    mma16816(c[mi][ni], a0, a1, a2, a3, bfr[ni][0], bfr[ni][1]);
            }
        }
        __syncthreads();
    }

    if (mode != 3) {
#pragma unroll
        for (int mi = 0; mi < 4; mi++) {
            int grow0 = bm + wm * 64 + mi * 16 + r;
            int grow1 = grow0 + 8;
#pragma unroll
            for (int ni = 0; ni < 4; ni++) {
                int col = bn + wn * 32 + ni * 8 + cp * 2;
                float bb0 = bias[col], bb1 = bias[col + 1];
                float v0 = c[mi][ni][0] + bb0, v1 = c[mi][ni][1] + bb1;
                float v2 = c[mi][ni][2] + bb0, v3 = c[mi][ni][3] + bb1;
                if (mode == 2) { v0 = gelu_f(v0); v1 = gelu_f(v1); v2 = gelu_f(v2); v3 = gelu_f(v3); }
                if (grow0 < M) {
                    __nv_bfloat162 h;
                    h.x = __float2bfloat16(v0); h.y = __float2bfloat16(v1);
                    *reinterpret_cast<__nv_bfloat162*>(&C16[(size_t)grow0 * N + col]) = h;
                }
                if (grow1 < M) {
                    __nv_bfloat162 h;
                    h.x = __float2bfloat16(v2); h.y = __float2bfloat16(v3);
                    *reinterpret_cast<__nv_bfloat162*>(&C16[(size_t)grow1 * N + col]) = h;
                }
            }
        }
    } else {
        // fused residual + LayerNorm epilogue (N == 128, single bn block)
        float* Cs = (float*)sh;  // [128][132] = 67584 B <= GEMM_SMEM
#pragma unroll
        for (int mi = 0; mi < 4; mi++) {
            int rl0 = wm * 64 + mi * 16 + r;
#pragma unroll
            for (int ni = 0; ni < 4; ni++) {
                int col = wn * 32 + ni * 8 + cp * 2;
                Cs[rl0 * 132 + col]       = c[mi][ni][0];
                Cs[rl0 * 132 + col + 1]   = c[mi][ni][1];
                Cs[(rl0 + 8) * 132 + col]     = c[mi][ni][2];
                Cs[(rl0 + 8) * 132 + col + 1] = c[mi][ni][3];
            }
        }
        __syncthreads();
        int cbx = lane * 4;
        float b0 = bias[cbx], b1 = bias[cbx + 1], b2v = bias[cbx + 2], b3 = bias[cbx + 3];
        float gg0 = gam[cbx], gg1 = gam[cbx + 1], gg2 = gam[cbx + 2], gg3 = gam[cbx + 3];
        float bb0 = bet[cbx], bb1 = bet[cbx + 1], bb2 = bet[cbx + 2], bb3 = bet[cbx + 3];
#pragma unroll
        for (int i = 0; i < 16; i++) {
            int rl = warp * 16 + i;
            int grow = bm + rl;
            if (grow >= M) break;
            const float* rr = resid + (size_t)grow * 128 + cbx;
            float t0 = Cs[rl * 132 + cbx]     + b0 + rr[0];
            float t1 = Cs[rl * 132 + cbx + 1] + b1 + rr[1];
            float t2 = Cs[rl * 132 + cbx + 2] + b2v + rr[2];
            float t3 = Cs[rl * 132 + cbx + 3] + b3 + rr[3];
            float mu = warp_sum(t0 + t1 + t2 + t3) * (1.f / 128.f);
            float d0 = t0 - mu, d1 = t1 - mu, d2 = t2 - mu, d3 = t3 - mu;
            float var = warp_sum(d0 * d0 + d1 * d1 + d2 * d2 + d3 * d3) * (1.f / 128.f);
            float rs = rsqrtf(var + 1e-5f);
            float o0 = d0 * rs * gg0 + bb0;
            float o1 = d1 * rs * gg1 + bb1;
            float o2 = d2 * rs * gg2 + bb2;
            float o3 = d3 * rs * gg3 + bb3;
            *reinterpret_cast<float4*>(O32 + (size_t)grow * 128 + cbx) =
                make_float4(o0, o1, o2, o3);
            if (O16) {
                __nv_bfloat162 p0, p1;
                p0.x = __float2bfloat16(o0); p0.y = __float2bfloat16(o1);
                p1.x = __float2bfloat16(o2); p1.y = __float2bfloat16(o3);
                uint2 u;
                u.x = *reinterpret_cast<unsigned*>(&p0);
                u.y = *reinterpret_cast<unsigned*>(&p1);
                *reinterpret_cast<uint2*>(O16 + (size_t)grow * 128 + cbx) = u;
            }
        }
    }
}

// ---------------- attention: lane = (edge-group, head); 4 edges in flight ----------------
__device__ __forceinline__ void ld16bf(float* f, const __nv_bfloat16* p) {
    uint4 u0 = *reinterpret_cast<const uint4*>(p);
    uint4 u1 = *reinterpret_cast<const uint4*>(p + 8);
    const unsigned* w = &u0.x;
#pragma unroll
    for (int j = 0; j < 4; j++) {
        float2 f2 = __bfloat1622float2(*reinterpret_cast<const __nv_bfloat162*>(&w[j]));
        f[2 * j] = f2.x; f[2 * j + 1] = f2.y;
    }
    const unsigned* w1 = &u1.x;
#pragma unroll
    for (int j = 0; j < 4; j++) {
        float2 f2 = __bfloat1622float2(*reinterpret_cast<const __nv_bfloat162*>(&w1[j]));
        f[8 + 2 * j] = f2.x; f[8 + 2 * j + 1] = f2.y;
    }
}

__global__ __launch_bounds__(256) void attn_kernel() {
    int w = (blockIdx.x * blockDim.x + threadIdx.x) >> 5;  // node
    if (w >= NN) return;
    int lane = threadIdx.x & 31;
    int g = lane >> 3;   // edge-group 0..3
    int h = lane & 7;    // head 0..7

    float qv[16];
    ld16bf(qv, g_qkv + (size_t)w * 384 + h * 16);

    int s = g_rowptr[w], e = g_rowptr[w + 1];
    int iters = (e - s + 3) >> 2;

    float denom = 0.f;
    float acc[16];
#pragma unroll
    for (int i = 0; i < 16; i++) acc[i] = 0.f;

    for (int it = 0; it < iters; it++) {
        int p = s + it * 4 + g;
        bool valid = p < e;
        int src = valid ? g_esrc[p] : 0;
        const __nv_bfloat16* base = g_qkv + (size_t)src * 384 + h * 16;
        float kv[16], vv[16];
        ld16bf(kv, base + 128);
        ld16bf(vv, base + 256);
        float d = 0.f;
#pragma unroll
        for (int i = 0; i < 16; i++) d += qv[i] * kv[i];
        float ea = valid ? __expf(d * 0.25f) : 0.f;
        denom += ea;
#pragma unroll
        for (int i = 0; i < 16; i++) acc[i] += ea * vv[i];
    }

    denom += __shfl_xor_sync(0xffffffffu, denom, 8);
    denom += __shfl_xor_sync(0xffffffffu, denom, 16);
#pragma unroll
    for (int i = 0; i < 16; i++) {
        acc[i] += __shfl_xor_sync(0xffffffffu, acc[i], 8);
        acc[i] += __shfl_xor_sync(0xffffffffu, acc[i], 16);
    }
    float inv = 1.f / (denom + 1e-16f);
    if (g == 0) {
        unsigned pk[8];
#pragma unroll
        for (int j = 0; j < 8; j++) {
            __nv_bfloat162 b;
            b.x = __float2bfloat16(acc[2 * j] * inv);
            b.y = __float2bfloat16(acc[2 * j + 1] * inv);
            pk[j] = *reinterpret_cast<unsigned*>(&b);
        }
        __nv_bfloat16* out = g_aggbf + (size_t)w * 128 + h * 16;
        *reinterpret_cast<uint4*>(out)     = make_uint4(pk[0], pk[1], pk[2], pk[3]);
        *reinterpret_cast<uint4*>(out + 8) = make_uint4(pk[4], pk[5], pk[6], pk[7]);
    }
}

// ---------------- launch ----------------
extern "C" void kernel_launch(void* const* d_in, const int* in_sizes, int n_in,
                              void* d_out, int out_size) {
    const float* x = (const float*)d_in[0];
    const void* ei = d_in[1];
    const float* Wq = (const float*)d_in[2];
    const float* bq = (const float*)d_in[3];
    const float* Wk = (const float*)d_in[4];
    const float* bk = (const float*)d_in[5];
    const float* Wv = (const float*)d_in[6];
    const float* bv = (const float*)d_in[7];
    const float* Wo = (const float*)d_in[8];
    const float* bo = (const float*)d_in[9];
    const float* W1 = (const float*)d_in[10];
    const float* b1 = (const float*)d_in[11];
    const float* W2 = (const float*)d_in[12];
    const float* b2 = (const float*)d_in[13];
    const float* g1 = (const float*)d_in[14];
    const float* be1 = (const float*)d_in[15];
    const float* g2 = (const float*)d_in[16];
    const float* be2 = (const float*)d_in[17];
    float* out = (float*)d_out;

    cudaFuncSetAttribute(gemm_kernel, cudaFuncAttributeMaxDynamicSharedMemorySize, GEMM_SMEM);

    // Lazily-created side stream + fork/join events (created on the first
    // uncaptured correctness call; reused during capture -> parallel branches).
    static cudaStream_t s_side = nullptr;
    static cudaEvent_t ev_fork = nullptr, ev_join = nullptr;
    if (s_side == nullptr) {
        if (cudaStreamCreateWithFlags(&s_side, cudaStreamNonBlocking) != cudaSuccess)
            s_side = nullptr;
        if (s_side) {
            cudaEventCreateWithFlags(&ev_fork, cudaEventDisableTiming);
            cudaEventCreateWithFlags(&ev_join, cudaEventDisableTiming);
        }
    }

    const int SCB = (NN + 1023) / 1024;  // 49

    if (s_side) {
        // fork: CSR chain + Wo/W1/W2 conversion on side stream (all hidden
        // under prep_qkv + QKV GEMM); join before attention.
        cudaEventRecord(ev_fork, 0);
        cudaStreamWaitEvent(s_side, ev_fork, 0);

        zero_fill<<<SCB, 1024, 0, s_side>>>();
        prep_edges<<<(EE + 255) / 256, 256, 0, s_side>>>(ei);
        scan_bt<<<SCB, 1024, 0, s_side>>>();
        scan_fix<<<SCB, 1024, 0, s_side>>>();
        scatter_kernel<<<(EE + 255) / 256, 256, 0, s_side>>>();
        prep_w<<<256, 256, 0, s_side>>>(Wo, W1, W2);
        cudaEventRecord(ev_join, s_side);

        prep_qkv<<<(NN * HID + 255) / 256, 256>>>(x, Wq, bq, Wk, bk, Wv, bv, bo, b1, b2);
        gemm_kernel<<<dim3(391, 3), 256, GEMM_SMEM>>>(0, NN, 384, 128, nullptr, nullptr, nullptr, nullptr); // QKV

        cudaStreamWaitEvent(0, ev_join, 0);
    } else {
        zero_fill<<<SCB, 1024>>>();
        prep_edges<<<(EE + 255) / 256, 256>>>(ei);
        scan_bt<<<SCB, 1024>>>();
        scan_fix<<<SCB, 1024>>>();
        scatter_kernel<<<(EE + 255) / 256, 256>>>();
        prep_w<<<256, 256>>>(Wo, W1, W2);
        prep_qkv<<<(NN * HID + 255) / 256, 256>>>(x, Wq, bq, Wk, bk, Wv, bv, bo, b1, b2);
        gemm_kernel<<<dim3(391, 3), 256, GEMM_SMEM>>>(0, NN, 384, 128, nullptr, nullptr, nullptr, nullptr);
    }

    attn_kernel<<<(NN * 32 + 255) / 256, 256>>>();                                                       // agg
    gemm_kernel<<<dim3(391, 1), 256, GEMM_SMEM>>>(1, NN, 128, 128, x, g1, be1, nullptr);                 // Wo + LN1
    gemm_kernel<<<dim3(391, 4), 256, GEMM_SMEM>>>(2, NN, 512, 128, nullptr, nullptr, nullptr, nullptr);  // W1 + gelu
    gemm_kernel<<<dim3(391, 1), 256, GEMM_SMEM>>>(3, NN, 128, 512, nullptr, g2, be2, out);               // W2 + LN2
}

// round 12
// speedup vs baseline: 1.5405x; 1.0294x over previous
#include <cuda_runtime.h>
#include <cuda_bf16.h>
#include <math.h>

#define NN 50000
#define EE 800000
#define HID 128
#define FFH 512

// ---------------- scratch (device globals: allocation-free) ----------------
__device__ __nv_bfloat16 g_xbf[(size_t)NN * HID];
__device__ __nv_bfloat16 g_wcat[384 * 128];
__device__ __nv_bfloat16 g_wo[128 * 128];
__device__ __nv_bfloat16 g_w1[512 * 128];
__device__ __nv_bfloat16 g_w2[128 * 512];
__device__ float g_bcat[384], g_bo[128], g_b1[512], g_b2[128];
__device__ __nv_bfloat16 g_qkv[(size_t)NN * 384];
__device__ int g_src[EE], g_dst[EE], g_esrc[EE];
__device__ int g_rowptr[NN + 1], g_fill[NN];
__device__ int g_bsum[64];
__device__ int g_arrive;   // static-init 0; reset to 0 by last block every call
__device__ __nv_bfloat16 g_aggbf[(size_t)NN * HID];
__device__ float g_h[(size_t)NN * HID];
__device__ __nv_bfloat16 g_hbf[(size_t)NN * HID];
__device__ __nv_bfloat16 g_ff1bf[(size_t)NN * FFH];

// ---------------- prep kernels ----------------
__global__ void zero_fill() {
    int i = blockIdx.x * blockDim.x + threadIdx.x;
    if (i < NN) g_fill[i] = 0;
}

__global__ void prep_edges(const void* __restrict__ ei) {
    int i = blockIdx.x * blockDim.x + threadIdx.x;
    if (i >= EE) return;
    // dtype sniff per-thread (L1-broadcast): int64 view of int32 data combines
    // two random node ids -> ~1e14, outside [0, NN). Deterministic.
    const long long* p64 = (const long long*)ei;
    int is64 = 1;
#pragma unroll
    for (int j = 0; j < 4; j++) {
        long long v = p64[j];
        if (v < 0 || v >= NN) is64 = 0;
    }
    long long s, d;
    if (is64) {
        s = p64[i];
        d = p64[(size_t)EE + i];
    } else {
        const int* p = (const int*)ei;
        s = p[i];
        d = p[(size_t)EE + i];
    }
    if (s < 0) s = 0; if (s >= NN) s = NN - 1;
    if (d < 0) d = 0; if (d >= NN) d = NN - 1;
    g_src[i] = (int)s;
    g_dst[i] = (int)d;
    atomicAdd(&g_fill[(int)d], 1);   // fused histogram
}

// fused block-scan + (last block) top-scan via arrival counter
__global__ void scan_bt() {
    __shared__ int sh[1024];
    __shared__ int s_old;
    int b = blockIdx.x, t = threadIdx.x;
    int i = b * 1024 + t;
    int d = (i < NN) ? g_fill[i] : 0;
    sh[t] = d;
    __syncthreads();
#pragma unroll
    for (int off = 1; off < 1024; off <<= 1) {
        int v = (t >= off) ? sh[t - off] : 0;
        __syncthreads();
        sh[t] += v;
        __syncthreads();
    }
    if (i < NN) g_rowptr[i] = sh[t] - d;  // exclusive, block-local
    if (t == 1023) {
        g_bsum[b] = sh[1023];
        __threadfence();
    }
    __syncthreads();
    if (t == 0) s_old = atomicAdd(&g_arrive, 1);
    __syncthreads();
    if (s_old == gridDim.x - 1) {
        int nb = gridDim.x;
        if (t < nb) sh[t] = *(volatile int*)&g_bsum[t];
        __syncthreads();
        if (t == 0) {
            int run = 0;
            for (int j = 0; j < nb; j++) { int v = sh[j]; sh[j] = run; run += v; }
            g_rowptr[NN] = run;
            g_arrive = 0;   // deterministic reset for next call
        }
        __syncthreads();
        if (t < nb) g_bsum[t] = sh[t];
    }
}

__global__ void scan_fix() {
    int b = blockIdx.x;
    int i = b * 1024 + threadIdx.x;
    if (i < NN) {
        int r = g_rowptr[i] + g_bsum[b];
        g_rowptr[i] = r;
        g_fill[i] = r;
    }
}

__global__ void scatter_kernel() {
    int i = blockIdx.x * blockDim.x + threadIdx.x;
    if (i < EE) {
        int d = g_dst[i];
        int p = atomicAdd(&g_fill[d], 1);
        g_esrc[p] = g_src[i];
    }
}

// fused: x -> bf16 conversion + weight conversion + bias staging (R8 layout)
__global__ void prep_wx(const float* __restrict__ x,
                        const float* __restrict__ Wq, const float* __restrict__ bq,
                        const float* __restrict__ Wk, const float* __restrict__ bk,
                        const float* __restrict__ Wv, const float* __restrict__ bv,
                        const float* __restrict__ Wo, const float* __restrict__ bo,
                        const float* __restrict__ W1, const float* __restrict__ b1,
                        const float* __restrict__ W2, const float* __restrict__ b2) {
    int i = blockIdx.x * blockDim.x + threadIdx.x;
    if (i < NN * HID) g_xbf[i] = __float2bfloat16(x[i]);
    if (i < 128 * 128) {
        g_wcat[i]         = __float2bfloat16(Wq[i]);
        g_wcat[16384 + i] = __float2bfloat16(Wk[i]);
        g_wcat[32768 + i] = __float2bfloat16(Wv[i]);
        g_wo[i]           = __float2bfloat16(Wo[i]);
    }
    if (i < 512 * 128) {
        g_w1[i] = __float2bfloat16(W1[i]);
        g_w2[i] = __float2bfloat16(W2[i]);
    }
    if (i < 128) {
        g_bcat[i] = bq[i];
        g_bcat[128 + i] = bk[i];
        g_bcat[256 + i] = bv[i];
        g_bo[i] = bo[i];
        g_b2[i] = b2[i];
    }
    if (i < 512) g_b1[i] = b1[i];
}

// ---------------- bf16 tensor-core GEMM ----------------
__device__ __forceinline__ void mma16816(float c[4], unsigned a0, unsigned a1, unsigned a2,
                                         unsigned a3, unsigned b0, unsigned b1) {
    asm volatile(
        "mma.sync.aligned.m16n8k16.row.col.f32.bf16.bf16.f32 "
        "{%0,%1,%2,%3}, {%4,%5,%6,%7}, {%8,%9}, {%0,%1,%2,%3};\n"
        : "+f"(c[0]), "+f"(c[1]), "+f"(c[2]), "+f"(c[3])
        : "r"(a0), "r"(a1), "r"(a2), "r"(a3), "r"(b0), "r"(b1));
}

__device__ __forceinline__ void ldx4(unsigned& r0, unsigned& r1, unsigned& r2, unsigned& r3,
                                     unsigned addr) {
    asm volatile("ldmatrix.sync.aligned.m8n8.x4.shared.b16 {%0,%1,%2,%3}, [%4];"
                 : "=r"(r0), "=r"(r1), "=r"(r2), "=r"(r3)
                 : "r"(addr));
}

__device__ __forceinline__ void cp16(unsigned saddr, const void* gaddr, int szbytes) {
    asm volatile("cp.async.cg.shared.global [%0], [%1], 16, %2;"
                 :: "r"(saddr), "l"(gaddr), "r"(szbytes));
}

__device__ __forceinline__ float warp_sum(float s) {
#pragma unroll
    for (int o = 16; o > 0; o >>= 1) s += __shfl_xor_sync(0xffffffffu, s, o);
    return s;
}

__device__ __forceinline__ float gelu_f(float v) {
    return 0.5f * v * (1.0f + erff(v * 0.70710678118654752f));
}

// 64-deep K stages, double buffered (measured champion config: 2 CTAs/SM).
#define SSTG 36
#define STAGE_U (128 * SSTG)
#define GEMM_SMEM (4 * STAGE_U * 4)  // 73728 B

// block tile 128(M) x 128(N), 8 warps as 2(m) x 4(n), warp tile 64x32
// modes: 1 = bf16 store, 2 = gelu+bf16 store, 3 = +bias +resid -> LayerNorm
__global__ __launch_bounds__(256) void gemm_kernel(int sel, int M, int N, int K,
                                                   const float* __restrict__ resid_in,
                                                   const float* __restrict__ gam,
                                                   const float* __restrict__ bet,
                                                   float* __restrict__ outp) {
    const __nv_bfloat16 *A, *W;
    const float* bias;
    __nv_bfloat16* C16 = nullptr;
    int mode;
    if (sel == 0)      { A = g_xbf;   W = g_wcat; bias = g_bcat; mode = 1; C16 = g_qkv; }
    else if (sel == 1) { A = g_aggbf; W = g_wo;   bias = g_bo;   mode = 3; }
    else if (sel == 2) { A = g_hbf;   W = g_w1;   bias = g_b1;   mode = 2; C16 = g_ff1bf; }
    else               { A = g_ff1bf; W = g_w2;   bias = g_b2;   mode = 3; }
    const float* resid = (sel == 1) ? resid_in : g_h;
    float* O32 = (sel == 1) ? g_h : outp;
    __nv_bfloat16* O16 = (sel == 1) ? g_hbf : nullptr;

    extern __shared__ unsigned sh[];

    int t = threadIdx.x;
    int warp = t >> 5, lane = t & 31;
    int wm = warp >> 2, wn = warp & 3;
    int bm = blockIdx.x * 128, bn = blockIdx.y * 128;
    int r = lane >> 2, cp = lane & 3;

    float c[4][4][4];
#pragma unroll
    for (int a = 0; a < 4; a++)
#pragma unroll
        for (int b = 0; b < 4; b++)
#pragma unroll
            for (int d = 0; d < 4; d++) c[a][b][d] = 0.f;

    unsigned sbase = (unsigned)__cvta_generic_to_shared(sh);

    int q = lane >> 3, lr = lane & 7;
    int rb = lr + (q & 1) * 8;
    int cb4 = (q >> 1) * 4;
    unsigned aAddr[2];
#pragma unroll
    for (int mi2 = 0; mi2 < 2; mi2++)
        aAddr[mi2] = sbase + 4u * ((wm * 64 + mi2 * 32 + rb) * SSTG + cb4);
    unsigned bAddr[2];
#pragma unroll
    for (int n2 = 0; n2 < 2; n2++)
        bAddr[n2] = sbase + 4u * (2 * STAGE_U + (wn * 32 + n2 * 16 + rb) * SSTG + cb4);

    const int S = K >> 6;

    auto fill = [&](int s) {
        int b = s & 1;
        int kc = s << 6;
#pragma unroll
        for (int j = 0; j < 4; j++) {
            int flat = j * 256 + t;
            int row = flat >> 3, c16 = flat & 7;
            int gr = bm + row;
            const void* gp = A + (size_t)gr * K + kc + c16 * 8;
            unsigned sp = sbase + 4u * (b * STAGE_U + row * SSTG + c16 * 4);
            cp16(sp, gp, (gr < M) ? 16 : 0);
        }
#pragma unroll
        for (int j = 0; j < 4; j++) {
            int flat = j * 256 + t;
            int row = flat >> 3, c16 = flat & 7;
            const void* gp = W + (size_t)(bn + row) * K + kc + c16 * 8;
            unsigned sp = sbase + 4u * (2 * STAGE_U + b * STAGE_U + row * SSTG + c16 * 4);
            cp16(sp, gp, 16);
        }
        asm volatile("cp.async.commit_group;");
    };

    fill(0);
    for (int s = 0; s < S; s++) {
        if (s + 1 < S) {
            fill(s + 1);
            asm volatile("cp.async.wait_group 1;");
        } else {
            asm volatile("cp.async.wait_group 0;");
        }
        __syncthreads();
        unsigned boff = (unsigned)((s & 1) * STAGE_U * 4);
#pragma unroll
        for (int ks = 0; ks < 4; ks++) {
            unsigned bfr[4][2];
#pragma unroll
            for (int n2 = 0; n2 < 2; n2++) {
                unsigned r0, r1, r2, r3;
                ldx4(r0, r1, r2, r3, bAddr[n2] + boff + ks * 32);
                bfr[2 * n2][0] = r0; bfr[2 * n2 + 1][0] = r1;
                bfr[2 * n2][1] = r2; bfr[2 * n2 + 1][1] = r3;
            }
#pragma unroll
            for (int mi = 0; mi < 4; mi++) {
                unsigned a0, a1, a2, a3;
                ldx4(a0, a1, a2, a3, aAddr[mi >> 1] + boff + (mi & 1) * (16u * SSTG * 4) + ks * 32);
#pragma unroll
                for (int ni = 0; ni < 4; ni++)
                    mma16816(c[mi][ni], a0, a1, a2, a3, bfr[ni][0], bfr[ni][1]);
            }
        }
        __syncthreads();
    }

    if (mode != 3) {
#pragma unroll
        for (int mi = 0; mi < 4; mi++) {
            int grow0 = bm + wm * 64 + mi * 16 + r;
            int grow1 = grow0 + 8;
#pragma unroll
            for (int ni = 0; ni < 4; ni++) {
                int col = bn + wn * 32 + ni * 8 + cp * 2;
                float bb0 = bias[col], bb1 = bias[col + 1];
                float v0 = c[mi][ni][0] + bb0, v1 = c[mi][ni][1] + bb1;
                float v2 = c[mi][ni][2] + bb0, v3 = c[mi][ni][3] + bb1;
                if (mode == 2) { v0 = gelu_f(v0); v1 = gelu_f(v1); v2 = gelu_f(v2); v3 = gelu_f(v3); }
                if (grow0 < M) {
                    __nv_bfloat162 h;
                    h.x = __float2bfloat16(v0); h.y = __float2bfloat16(v1);
                    *reinterpret_cast<__nv_bfloat162*>(&C16[(size_t)grow0 * N + col]) = h;
                }
                if (grow1 < M) {
                    __nv_bfloat162 h;
                    h.x = __float2bfloat16(v2); h.y = __float2bfloat16(v3);
                    *reinterpret_cast<__nv_bfloat162*>(&C16[(size_t)grow1 * N + col]) = h;
                }
            }
        }
    } else {
        // fused residual + LayerNorm epilogue (N == 128, single bn block)
        float* Cs = (float*)sh;  // [128][132] = 67584 B <= GEMM_SMEM
#pragma unroll
        for (int mi = 0; mi < 4; mi++) {
            int rl0 = wm * 64 + mi * 16 + r;
#pragma unroll
            for (int ni = 0; ni < 4; ni++) {
                int col = wn * 32 + ni * 8 + cp * 2;
                Cs[rl0 * 132 + col]       = c[mi][ni][0];
                Cs[rl0 * 132 + col + 1]   = c[mi][ni][1];
                Cs[(rl0 + 8) * 132 + col]     = c[mi][ni][2];
                Cs[(rl0 + 8) * 132 + col + 1] = c[mi][ni][3];
            }
        }
        __syncthreads();
        int cbx = lane * 4;
        float b0 = bias[cbx], b1 = bias[cbx + 1], b2v = bias[cbx + 2], b3 = bias[cbx + 3];
        float gg0 = gam[cbx], gg1 = gam[cbx + 1], gg2 = gam[cbx + 2], gg3 = gam[cbx + 3];
        float bb0 = bet[cbx], bb1 = bet[cbx + 1], bb2 = bet[cbx + 2], bb3 = bet[cbx + 3];
#pragma unroll
        for (int i = 0; i < 16; i++) {
            int rl = warp * 16 + i;
            int grow = bm + rl;
            if (grow >= M) break;
            const float* rr = resid + (size_t)grow * 128 + cbx;
            float t0 = Cs[rl * 132 + cbx]     + b0 + rr[0];
            float t1 = Cs[rl * 132 + cbx + 1] + b1 + rr[1];
            float t2 = Cs[rl * 132 + cbx + 2] + b2v + rr[2];
            float t3 = Cs[rl * 132 + cbx + 3] + b3 + rr[3];
            float mu = warp_sum(t0 + t1 + t2 + t3) * (1.f / 128.f);
            float d0 = t0 - mu, d1 = t1 - mu, d2 = t2 - mu, d3 = t3 - mu;
            float var = warp_sum(d0 * d0 + d1 * d1 + d2 * d2 + d3 * d3) * (1.f / 128.f);
            float rs = rsqrtf(var + 1e-5f);
            float o0 = d0 * rs * gg0 + bb0;
            float o1 = d1 * rs * gg1 + bb1;
            float o2 = d2 * rs * gg2 + bb2;
            float o3 = d3 * rs * gg3 + bb3;
            *reinterpret_cast<float4*>(O32 + (size_t)grow * 128 + cbx) =
                make_float4(o0, o1, o2, o3);
            if (O16) {
                __nv_bfloat162 p0, p1;
                p0.x = __float2bfloat16(o0); p0.y = __float2bfloat16(o1);
                p1.x = __float2bfloat16(o2); p1.y = __float2bfloat16(o3);
                uint2 u;
                u.x = *reinterpret_cast<unsigned*>(&p0);
                u.y = *reinterpret_cast<unsigned*>(&p1);
                *reinterpret_cast<uint2*>(O16 + (size_t)grow * 128 + cbx) = u;
            }
        }
    }
}

// ---------------- attention: lane = (edge-group, head); 4 edges in flight ----------------
__device__ __forceinline__ void ld16bf(float* f, const __nv_bfloat16* p) {
    uint4 u0 = *reinterpret_cast<const uint4*>(p);
    uint4 u1 = *reinterpret_cast<const uint4*>(p + 8);
    const unsigned* w = &u0.x;
#pragma unroll
    for (int j = 0; j < 4; j++) {
        float2 f2 = __bfloat1622float2(*reinterpret_cast<const __nv_bfloat162*>(&w[j]));
        f[2 * j] = f2.x; f[2 * j + 1] = f2.y;
    }
    const unsigned* w1 = &u1.x;
#pragma unroll
    for (int j = 0; j < 4; j++) {
        float2 f2 = __bfloat1622float2(*reinterpret_cast<const __nv_bfloat162*>(&w1[j]));
        f[8 + 2 * j] = f2.x; f[8 + 2 * j + 1] = f2.y;
    }
}

__global__ __launch_bounds__(256) void attn_kernel() {
    int w = (blockIdx.x * blockDim.x + threadIdx.x) >> 5;  // node
    if (w >= NN) return;
    int lane = threadIdx.x & 31;
    int g = lane >> 3;   // edge-group 0..3
    int h = lane & 7;    // head 0..7

    float qv[16];
    ld16bf(qv, g_qkv + (size_t)w * 384 + h * 16);

    int s = g_rowptr[w], e = g_rowptr[w + 1];
    int iters = (e - s + 3) >> 2;

    float denom = 0.f;
    float acc[16];
#pragma unroll
    for (int i = 0; i < 16; i++) acc[i] = 0.f;

    for (int it = 0; it < iters; it++) {
        int p = s + it * 4 + g;
        bool valid = p < e;
        int src = valid ? g_esrc[p] : 0;
        const __nv_bfloat16* base = g_qkv + (size_t)src * 384 + h * 16;
        float kv[16], vv[16];
        ld16bf(kv, base + 128);
        ld16bf(vv, base + 256);
        float d = 0.f;
#pragma unroll
        for (int i = 0; i < 16; i++) d += qv[i] * kv[i];
        float ea = valid ? __expf(d * 0.25f) : 0.f;
        denom += ea;
#pragma unroll
        for (int i = 0; i < 16; i++) acc[i] += ea * vv[i];
    }

    denom += __shfl_xor_sync(0xffffffffu, denom, 8);
    denom += __shfl_xor_sync(0xffffffffu, denom, 16);
#pragma unroll
    for (int i = 0; i < 16; i++) {
        acc[i] += __shfl_xor_sync(0xffffffffu, acc[i], 8);
        acc[i] += __shfl_xor_sync(0xffffffffu, acc[i], 16);
    }
    float inv = 1.f / (denom + 1e-16f);
    if (g == 0) {
        unsigned pk[8];
#pragma unroll
        for (int j = 0; j < 8; j++) {
            __nv_bfloat162 b;
            b.x = __float2bfloat16(acc[2 * j] * inv);
            b.y = __float2bfloat16(acc[2 * j + 1] * inv);
            pk[j] = *reinterpret_cast<unsigned*>(&b);
        }
        __nv_bfloat16* out = g_aggbf + (size_t)w * 128 + h * 16;
        *reinterpret_cast<uint4*>(out)     = make_uint4(pk[0], pk[1], pk[2], pk[3]);
        *reinterpret_cast<uint4*>(out + 8) = make_uint4(pk[4], pk[5], pk[6], pk[7]);
    }
}

// ---------------- launch ----------------
extern "C" void kernel_launch(void* const* d_in, const int* in_sizes, int n_in,
                              void* d_out, int out_size) {
    const float* x = (const float*)d_in[0];
    const void* ei = d_in[1];
    const float* Wq = (const float*)d_in[2];
    const float* bq = (const float*)d_in[3];
    const float* Wk = (const float*)d_in[4];
    const float* bk = (const float*)d_in[5];
    const float* Wv = (const float*)d_in[6];
    const float* bv = (const float*)d_in[7];
    const float* Wo = (const float*)d_in[8];
    const float* bo = (const float*)d_in[9];
    const float* W1 = (const float*)d_in[10];
    const float* b1 = (const float*)d_in[11];
    const float* W2 = (const float*)d_in[12];
    const float* b2 = (const float*)d_in[13];
    const float* g1 = (const float*)d_in[14];
    const float* be1 = (const float*)d_in[15];
    const float* g2 = (const float*)d_in[16];
    const float* be2 = (const float*)d_in[17];
    float* out = (float*)d_out;

    cudaFuncSetAttribute(gemm_kernel, cudaFuncAttributeMaxDynamicSharedMemorySize, GEMM_SMEM);

    // Lazily-created side stream + fork/join events (created on the first
    // uncaptured correctness call; reused during capture -> parallel branches).
    static cudaStream_t s_side = nullptr;
    static cudaEvent_t ev_fork = nullptr, ev_join = nullptr;
    if (s_side == nullptr) {
        if (cudaStreamCreateWithFlags(&s_side, cudaStreamNonBlocking) != cudaSuccess)
            s_side = nullptr;
        if (s_side) {
            cudaEventCreateWithFlags(&ev_fork, cudaEventDisableTiming);
            cudaEventCreateWithFlags(&ev_join, cudaEventDisableTiming);
        }
    }

    const int SCB = (NN + 1023) / 1024;  // 49

    if (s_side) {
        // fork: CSR build chain on side stream, weights/QKV on main stream
        cudaEventRecord(ev_fork, 0);
        cudaStreamWaitEvent(s_side, ev_fork, 0);

        zero_fill<<<SCB, 1024, 0, s_side>>>();
        prep_edges<<<(EE + 255) / 256, 256, 0, s_side>>>(ei);
        scan_bt<<<SCB, 1024, 0, s_side>>>();
        scan_fix<<<SCB, 1024, 0, s_side>>>();
        scatter_kernel<<<(EE + 255) / 256, 256, 0, s_side>>>();
        cudaEventRecord(ev_join, s_side);

        prep_wx<<<(NN * HID + 255) / 256, 256>>>(x, Wq, bq, Wk, bk, Wv, bv, Wo, bo, W1, b1, W2, b2);
        gemm_kernel<<<dim3(391, 3), 256, GEMM_SMEM>>>(0, NN, 384, 128, nullptr, nullptr, nullptr, nullptr); // QKV

        cudaStreamWaitEvent(0, ev_join, 0);
    } else {
        zero_fill<<<SCB, 1024>>>();
        prep_edges<<<(EE + 255) / 256, 256>>>(ei);
        scan_bt<<<SCB, 1024>>>();
        scan_fix<<<SCB, 1024>>>();
        scatter_kernel<<<(EE + 255) / 256, 256>>>();
        prep_wx<<<(NN * HID + 255) / 256, 256>>>(x, Wq, bq, Wk, bk, Wv, bv, Wo, bo, W1, b1, W2, b2);
        gemm_kernel<<<dim3(391, 3), 256, GEMM_SMEM>>>(0, NN, 384, 128, nullptr, nullptr, nullptr, nullptr);
    }

    attn_kernel<<<(NN * 32 + 255) / 256, 256>>>();                                                       // agg
    gemm_kernel<<<dim3(391, 1), 256, GEMM_SMEM>>>(1, NN, 128, 128, x, g1, be1, nullptr);                 // Wo + LN1
    gemm_kernel<<<dim3(391, 4), 256, GEMM_SMEM>>>(2, NN, 512, 128, nullptr, nullptr, nullptr, nullptr);  // W1 + gelu
    gemm_kernel<<<dim3(391, 1), 256, GEMM_SMEM>>>(3, NN, 128, 512, nullptr, g2, be2, out);               // W2 + LN2
}

// round 14
// speedup vs baseline: 1.5451x; 1.0030x over previous
#include <cuda_runtime.h>
#include <cuda_bf16.h>
#include <math.h>

#define NN 50000
#define EE 800000
#define HID 128
#define FFH 512

// ---------------- scratch (device globals: allocation-free) ----------------
__device__ __nv_bfloat16 g_xbf[(size_t)NN * HID];
__device__ __nv_bfloat16 g_wcat[384 * 128];
__device__ __nv_bfloat16 g_wo[128 * 128];
__device__ __nv_bfloat16 g_w1[512 * 128];
__device__ __nv_bfloat16 g_w2[128 * 512];
__device__ float g_bcat[384], g_bo[128], g_b1[512], g_b2[128];
__device__ __nv_bfloat16 g_qkv[(size_t)NN * 384];
__device__ int g_src[EE], g_dst[EE], g_esrc[EE];
__device__ int g_rowptr[NN + 1], g_fill[NN];
__device__ int g_bsum[64];
__device__ int g_arrive;   // static-init 0; reset to 0 by last block every call
__device__ __nv_bfloat16 g_aggbf[(size_t)NN * HID];
__device__ float g_h[(size_t)NN * HID];
__device__ __nv_bfloat16 g_hbf[(size_t)NN * HID];
__device__ __nv_bfloat16 g_ff1bf[(size_t)NN * FFH];

// ---------------- prep kernels ----------------
__global__ void zero_fill() {
    int i = blockIdx.x * blockDim.x + threadIdx.x;
    if (i < NN) g_fill[i] = 0;
}

__global__ void prep_edges(const void* __restrict__ ei) {
    int i = blockIdx.x * blockDim.x + threadIdx.x;
    if (i >= EE) return;
    // dtype sniff per-thread (L1-broadcast): int64 view of int32 data combines
    // two random node ids -> ~1e14, outside [0, NN). Deterministic.
    const long long* p64 = (const long long*)ei;
    int is64 = 1;
#pragma unroll
    for (int j = 0; j < 4; j++) {
        long long v = p64[j];
        if (v < 0 || v >= NN) is64 = 0;
    }
    long long s, d;
    if (is64) {
        s = p64[i];
        d = p64[(size_t)EE + i];
    } else {
        const int* p = (const int*)ei;
        s = p[i];
        d = p[(size_t)EE + i];
    }
    if (s < 0) s = 0; if (s >= NN) s = NN - 1;
    if (d < 0) d = 0; if (d >= NN) d = NN - 1;
    g_src[i] = (int)s;
    g_dst[i] = (int)d;
    atomicAdd(&g_fill[(int)d], 1);   // fused histogram
}

// fused block-scan + (last block) top-scan via arrival counter
__global__ void scan_bt() {
    __shared__ int sh[1024];
    __shared__ int s_old;
    int b = blockIdx.x, t = threadIdx.x;
    int i = b * 1024 + t;
    int d = (i < NN) ? g_fill[i] : 0;
    sh[t] = d;
    __syncthreads();
#pragma unroll
    for (int off = 1; off < 1024; off <<= 1) {
        int v = (t >= off) ? sh[t - off] : 0;
        __syncthreads();
        sh[t] += v;
        __syncthreads();
    }
    if (i < NN) g_rowptr[i] = sh[t] - d;  // exclusive, block-local
    if (t == 1023) {
        g_bsum[b] = sh[1023];
        __threadfence();
    }
    __syncthreads();
    if (t == 0) s_old = atomicAdd(&g_arrive, 1);
    __syncthreads();
    if (s_old == gridDim.x - 1) {
        int nb = gridDim.x;
        if (t < nb) sh[t] = *(volatile int*)&g_bsum[t];
        __syncthreads();
        if (t == 0) {
            int run = 0;
            for (int j = 0; j < nb; j++) { int v = sh[j]; sh[j] = run; run += v; }
            g_rowptr[NN] = run;
            g_arrive = 0;   // deterministic reset for next call
        }
        __syncthreads();
        if (t < nb) g_bsum[t] = sh[t];
    }
}

__global__ void scan_fix() {
    int b = blockIdx.x;
    int i = b * 1024 + threadIdx.x;
    if (i < NN) {
        int r = g_rowptr[i] + g_bsum[b];
        g_rowptr[i] = r;
        g_fill[i] = r;
    }
}

__global__ void scatter_kernel() {
    int i = blockIdx.x * blockDim.x + threadIdx.x;
    if (i < EE) {
        int d = g_dst[i];
        int p = atomicAdd(&g_fill[d], 1);
        g_esrc[p] = g_src[i];
    }
}

// fused: x -> bf16 conversion + weight conversion + bias staging
__global__ void prep_wx(const float* __restrict__ x,
                        const float* __restrict__ Wq, const float* __restrict__ bq,
                        const float* __restrict__ Wk, const float* __restrict__ bk,
                        const float* __restrict__ Wv, const float* __restrict__ bv,
                        const float* __restrict__ Wo, const float* __restrict__ bo,
                        const float* __restrict__ W1, const float* __restrict__ b1,
                        const float* __restrict__ W2, const float* __restrict__ b2) {
    int i = blockIdx.x * blockDim.x + threadIdx.x;
    if (i < NN * HID) g_xbf[i] = __float2bfloat16(x[i]);
    if (i < 128 * 128) {
        g_wcat[i]         = __float2bfloat16(Wq[i]);
        g_wcat[16384 + i] = __float2bfloat16(Wk[i]);
        g_wcat[32768 + i] = __float2bfloat16(Wv[i]);
        g_wo[i]           = __float2bfloat16(Wo[i]);
    }
    if (i < 512 * 128) {
        g_w1[i] = __float2bfloat16(W1[i]);
        g_w2[i] = __float2bfloat16(W2[i]);
    }
    if (i < 128) {
        g_bcat[i] = bq[i];
        g_bcat[128 + i] = bk[i];
        g_bcat[256 + i] = bv[i];
        g_bo[i] = bo[i];
        g_b2[i] = b2[i];
    }
    if (i < 512) g_b1[i] = b1[i];
}

// ---------------- bf16 tensor-core GEMM ----------------
__device__ __forceinline__ void mma16816(float c[4], unsigned a0, unsigned a1, unsigned a2,
                                         unsigned a3, unsigned b0, unsigned b1) {
    asm volatile(
        "mma.sync.aligned.m16n8k16.row.col.f32.bf16.bf16.f32 "
        "{%0,%1,%2,%3}, {%4,%5,%6,%7}, {%8,%9}, {%0,%1,%2,%3};\n"
        : "+f"(c[0]), "+f"(c[1]), "+f"(c[2]), "+f"(c[3])
        : "r"(a0), "r"(a1), "r"(a2), "r"(a3), "r"(b0), "r"(b1));
}

__device__ __forceinline__ void ldx4(unsigned& r0, unsigned& r1, unsigned& r2, unsigned& r3,
                                     unsigned addr) {
    asm volatile("ldmatrix.sync.aligned.m8n8.x4.shared.b16 {%0,%1,%2,%3}, [%4];"
                 : "=r"(r0), "=r"(r1), "=r"(r2), "=r"(r3)
                 : "r"(addr));
}

__device__ __forceinline__ void cp16(unsigned saddr, const void* gaddr, int szbytes) {
    asm volatile("cp.async.cg.shared.global [%0], [%1], 16, %2;"
                 :: "r"(saddr), "l"(gaddr), "r"(szbytes));
}

__device__ __forceinline__ float warp_sum(float s) {
#pragma unroll
    for (int o = 16; o > 0; o >>= 1) s += __shfl_xor_sync(0xffffffffu, s, o);
    return s;
}

__device__ __forceinline__ float gelu_f(float v) {
    return 0.5f * v * (1.0f + erff(v * 0.70710678118654752f));
}

// 64-deep K stages, double buffered (measured champion config: 2 CTAs/SM).
#define SSTG 36
#define STAGE_U (128 * SSTG)
#define GEMM_SMEM (4 * STAGE_U * 4)  // 73728 B

// block tile 128(M) x 128(N), 8 warps as 2(m) x 4(n), warp tile 64x32
// modes: 1 = bf16 store, 2 = gelu+bf16 store, 3 = +bias +resid -> LayerNorm
__global__ __launch_bounds__(256) void gemm_kernel(int sel, int M, int N, int K,
                                                   const float* __restrict__ resid_in,
                                                   const float* __restrict__ gam,
                                                   const float* __restrict__ bet,
                                                   float* __restrict__ outp) {
    const __nv_bfloat16 *A, *W;
    const float* bias;
    __nv_bfloat16* C16 = nullptr;
    int mode;
    if (sel == 0)      { A = g_xbf;   W = g_wcat; bias = g_bcat; mode = 1; C16 = g_qkv; }
    else if (sel == 1) { A = g_aggbf; W = g_wo;   bias = g_bo;   mode = 3; }
    else if (sel == 2) { A = g_hbf;   W = g_w1;   bias = g_b1;   mode = 2; C16 = g_ff1bf; }
    else               { A = g_ff1bf; W = g_w2;   bias = g_b2;   mode = 3; }
    const float* resid = (sel == 1) ? resid_in : g_h;
    float* O32 = (sel == 1) ? g_h : outp;
    __nv_bfloat16* O16 = (sel == 1) ? g_hbf : nullptr;

    extern __shared__ unsigned sh[];

    int t = threadIdx.x;
    int warp = t >> 5, lane = t & 31;
    int wm = warp >> 2, wn = warp & 3;
    int bm = blockIdx.x * 128, bn = blockIdx.y * 128;
    int r = lane >> 2, cp = lane & 3;

    float c[4][4][4];
#pragma unroll
    for (int a = 0; a < 4; a++)
#pragma unroll
        for (int b = 0; b < 4; b++)
#pragma unroll
            for (int d = 0; d < 4; d++) c[a][b][d] = 0.f;

    unsigned sbase = (unsigned)__cvta_generic_to_shared(sh);

    int q = lane >> 3, lr = lane & 7;
    int rb = lr + (q & 1) * 8;
    int cb4 = (q >> 1) * 4;
    unsigned aAddr[2];
#pragma unroll
    for (int mi2 = 0; mi2 < 2; mi2++)
        aAddr[mi2] = sbase + 4u * ((wm * 64 + mi2 * 32 + rb) * SSTG + cb4);
    unsigned bAddr[2];
#pragma unroll
    for (int n2 = 0; n2 < 2; n2++)
        bAddr[n2] = sbase + 4u * (2 * STAGE_U + (wn * 32 + n2 * 16 + rb) * SSTG + cb4);

    const int S = K >> 6;

    auto fill = [&](int s) {
        int b = s & 1;
        int kc = s << 6;
#pragma unroll
        for (int j = 0; j < 4; j++) {
            int flat = j * 256 + t;
            int row = flat >> 3, c16 = flat & 7;
            int gr = bm + row;
            const void* gp = A + (size_t)gr * K + kc + c16 * 8;
            unsigned sp = sbase + 4u * (b * STAGE_U + row * SSTG + c16 * 4);
            cp16(sp, gp, (gr < M) ? 16 : 0);
        }
#pragma unroll
        for (int j = 0; j < 4; j++) {
            int flat = j * 256 + t;
            int row = flat >> 3, c16 = flat & 7;
            const void* gp = W + (size_t)(bn + row) * K + kc + c16 * 8;
            unsigned sp = sbase + 4u * (2 * STAGE_U + b * STAGE_U + row * SSTG + c16 * 4);
            cp16(sp, gp, 16);
        }
        asm volatile("cp.async.commit_group;");
    };

    fill(0);
    for (int s = 0; s < S; s++) {
        if (s + 1 < S) {
            fill(s + 1);
            asm volatile("cp.async.wait_group 1;");
        } else {
            asm volatile("cp.async.wait_group 0;");
        }
        __syncthreads();
        unsigned boff = (unsigned)((s & 1) * STAGE_U * 4);
#pragma unroll
        for (int ks = 0; ks < 4; ks++) {
            unsigned bfr[4][2];
#pragma unroll
            for (int n2 = 0; n2 < 2; n2++) {
                unsigned r0, r1, r2, r3;
                ldx4(r0, r1, r2, r3, bAddr[n2] + boff + ks * 32);
                bfr[2 * n2][0] = r0; bfr[2 * n2 + 1][0] = r1;
                bfr[2 * n2][1] = r2; bfr[2 * n2 + 1][1] = r3;
            }
#pragma unroll
            for (int mi = 0; mi < 4; mi++) {
                unsigned a0, a1, a2, a3;
                ldx4(a0, a1, a2, a3, aAddr[mi >> 1] + boff + (mi & 1) * (16u * SSTG * 4) + ks * 32);
#pragma unroll
                for (int ni = 0; ni < 4; ni++)
                    mma16816(c[mi][ni], a0, a1, a2, a3, bfr[ni][0], bfr[ni][1]);
            }
        }
        __syncthreads();
    }

    if (mode != 3) {
#pragma unroll
        for (int mi = 0; mi < 4; mi++) {
            int grow0 = bm + wm * 64 + mi * 16 + r;
            int grow1 = grow0 + 8;
#pragma unroll
            for (int ni = 0; ni < 4; ni++) {
                int col = bn + wn * 32 + ni * 8 + cp * 2;
                float bb0 = bias[col], bb1 = bias[col + 1];
                float v0 = c[mi][ni][0] + bb0, v1 = c[mi][ni][1] + bb1;
                float v2 = c[mi][ni][2] + bb0, v3 = c[mi][ni][3] + bb1;
                if (mode == 2) { v0 = gelu_f(v0); v1 = gelu_f(v1); v2 = gelu_f(v2); v3 = gelu_f(v3); }
                if (grow0 < M) {
                    __nv_bfloat162 h;
                    h.x = __float2bfloat16(v0); h.y = __float2bfloat16(v1);
                    *reinterpret_cast<__nv_bfloat162*>(&C16[(size_t)grow0 * N + col]) = h;
                }
                if (grow1 < M) {
                    __nv_bfloat162 h;
                    h.x = __float2bfloat16(v2); h.y = __float2bfloat16(v3);
                    *reinterpret_cast<__nv_bfloat162*>(&C16[(size_t)grow1 * N + col]) = h;
                }
            }
        }
    } else {
        // fused residual + LayerNorm epilogue (N == 128, single bn block)
        float* Cs = (float*)sh;  // [128][132] = 67584 B <= GEMM_SMEM
#pragma unroll
        for (int mi = 0; mi < 4; mi++) {
            int rl0 = wm * 64 + mi * 16 + r;
#pragma unroll
            for (int ni = 0; ni < 4; ni++) {
                int col = wn * 32 + ni * 8 + cp * 2;
                Cs[rl0 * 132 + col]       = c[mi][ni][0];
                Cs[rl0 * 132 + col + 1]   = c[mi][ni][1];
                Cs[(rl0 + 8) * 132 + col]     = c[mi][ni][2];
                Cs[(rl0 + 8) * 132 + col + 1] = c[mi][ni][3];
            }
        }
        __syncthreads();
        int cbx = lane * 4;
        float b0 = bias[cbx], b1 = bias[cbx + 1], b2v = bias[cbx + 2], b3 = bias[cbx + 3];
        float gg0 = gam[cbx], gg1 = gam[cbx + 1], gg2 = gam[cbx + 2], gg3 = gam[cbx + 3];
        float bb0 = bet[cbx], bb1 = bet[cbx + 1], bb2 = bet[cbx + 2], bb3 = bet[cbx + 3];
#pragma unroll
        for (int i = 0; i < 16; i++) {
            int rl = warp * 16 + i;
            int grow = bm + rl;
            if (grow >= M) break;
            const float* rr = resid + (size_t)grow * 128 + cbx;
            float t0 = Cs[rl * 132 + cbx]     + b0 + rr[0];
            float t1 = Cs[rl * 132 + cbx + 1] + b1 + rr[1];
            float t2 = Cs[rl * 132 + cbx + 2] + b2v + rr[2];
            float t3 = Cs[rl * 132 + cbx + 3] + b3 + rr[3];
            float mu = warp_sum(t0 + t1 + t2 + t3) * (1.f / 128.f);
            float d0 = t0 - mu, d1 = t1 - mu, d2 = t2 - mu, d3 = t3 - mu;
            float var = warp_sum(d0 * d0 + d1 * d1 + d2 * d2 + d3 * d3) * (1.f / 128.f);
            float rs = rsqrtf(var + 1e-5f);
            float o0 = d0 * rs * gg0 + bb0;
            float o1 = d1 * rs * gg1 + bb1;
            float o2 = d2 * rs * gg2 + bb2;
            float o3 = d3 * rs * gg3 + bb3;
            *reinterpret_cast<float4*>(O32 + (size_t)grow * 128 + cbx) =
                make_float4(o0, o1, o2, o3);
            if (O16) {
                __nv_bfloat162 p0, p1;
                p0.x = __float2bfloat16(o0); p0.y = __float2bfloat16(o1);
                p1.x = __float2bfloat16(o2); p1.y = __float2bfloat16(o3);
                uint2 u;
                u.x = *reinterpret_cast<unsigned*>(&p0);
                u.y = *reinterpret_cast<unsigned*>(&p1);
                *reinterpret_cast<uint2*>(O16 + (size_t)grow * 128 + cbx) = u;
            }
        }
    }
}

// ---------------- attention: lane = (edge-group, head); 8 edges in flight ----------------
__device__ __forceinline__ void ld16bf(float* f, const __nv_bfloat16* p) {
    uint4 u0 = *reinterpret_cast<const uint4*>(p);
    uint4 u1 = *reinterpret_cast<const uint4*>(p + 8);
    const unsigned* w = &u0.x;
#pragma unroll
    for (int j = 0; j < 4; j++) {
        float2 f2 = __bfloat1622float2(*reinterpret_cast<const __nv_bfloat162*>(&w[j]));
        f[2 * j] = f2.x; f[2 * j + 1] = f2.y;
    }
    const unsigned* w1 = &u1.x;
#pragma unroll
    for (int j = 0; j < 4; j++) {
        float2 f2 = __bfloat1622float2(*reinterpret_cast<const __nv_bfloat162*>(&w1[j]));
        f[8 + 2 * j] = f2.x; f[8 + 2 * j + 1] = f2.y;
    }
}

__global__ __launch_bounds__(256) void attn_kernel() {
    int w = (blockIdx.x * blockDim.x + threadIdx.x) >> 5;  // node
    if (w >= NN) return;
    int lane = threadIdx.x & 31;
    int g = lane >> 3;   // edge-group 0..3
    int h = lane & 7;    // head 0..7

    float qv[16];
    ld16bf(qv, g_qkv + (size_t)w * 384 + h * 16);

    int s = g_rowptr[w], e = g_rowptr[w + 1];
    int iters = (e - s + 3) >> 2;

    float denom = 0.f;
    float acc[16];
#pragma unroll
    for (int i = 0; i < 16; i++) acc[i] = 0.f;

    // 2-way unrolled edge loop: 8 edges in flight per warp (2 per lane-group)
    int it = 0;
    for (; it + 2 <= iters; it += 2) {
        int p0 = s + it * 4 + g;
        int p1 = p0 + 4;
        bool v0 = p0 < e, v1 = p1 < e;
        int s0 = v0 ? g_esrc[p0] : 0;
        int s1 = v1 ? g_esrc[p1] : 0;
        const __nv_bfloat16* b0 = g_qkv + (size_t)s0 * 384 + h * 16;
        const __nv_bfloat16* b1 = g_qkv + (size_t)s1 * 384 + h * 16;
        float kv0[16], vv0[16], kv1[16], vv1[16];
        ld16bf(kv0, b0 + 128);
        ld16bf(vv0, b0 + 256);
        ld16bf(kv1, b1 + 128);
        ld16bf(vv1, b1 + 256);
        float d0 = 0.f, d1 = 0.f;
#pragma unroll
        for (int i = 0; i < 16; i++) { d0 += qv[i] * kv0[i]; d1 += qv[i] * kv1[i]; }
        float ea0 = v0 ? __expf(d0 * 0.25f) : 0.f;
        denom += ea0;
#pragma unroll
        for (int i = 0; i < 16; i++) acc[i] += ea0 * vv0[i];
        float ea1 = v1 ? __expf(d1 * 0.25f) : 0.f;
        denom += ea1;
#pragma unroll
        for (int i = 0; i < 16; i++) acc[i] += ea1 * vv1[i];
    }
    for (; it < iters; it++) {
        int p = s + it * 4 + g;
        bool valid = p < e;
        int src = valid ? g_esrc[p] : 0;
        const __nv_bfloat16* base = g_qkv + (size_t)src * 384 + h * 16;
        float kv[16], vv[16];
        ld16bf(kv, base + 128);
        ld16bf(vv, base + 256);
        float d = 0.f;
#pragma unroll
        for (int i = 0; i < 16; i++) d += qv[i] * kv[i];
        float ea = valid ? __expf(d * 0.25f) : 0.f;
        denom += ea;
#pragma unroll
        for (int i = 0; i < 16; i++) acc[i] += ea * vv[i];
    }

    denom += __shfl_xor_sync(0xffffffffu, denom, 8);
    denom += __shfl_xor_sync(0xffffffffu, denom, 16);
#pragma unroll
    for (int i = 0; i < 16; i++) {
        acc[i] += __shfl_xor_sync(0xffffffffu, acc[i], 8);
        acc[i] += __shfl_xor_sync(0xffffffffu, acc[i], 16);
    }
    float inv = 1.f / (denom + 1e-16f);
    if (g == 0) {
        unsigned pk[8];
#pragma unroll
        for (int j = 0; j < 8; j++) {
            __nv_bfloat162 b;
            b.x = __float2bfloat16(acc[2 * j] * inv);
            b.y = __float2bfloat16(acc[2 * j + 1] * inv);
            pk[j] = *reinterpret_cast<unsigned*>(&b);
        }
        __nv_bfloat16* out = g_aggbf + (size_t)w * 128 + h * 16;
        *reinterpret_cast<uint4*>(out)     = make_uint4(pk[0], pk[1], pk[2], pk[3]);
        *reinterpret_cast<uint4*>(out + 8) = make_uint4(pk[4], pk[5], pk[6], pk[7]);
    }
}

// ---------------- launch ----------------
extern "C" void kernel_launch(void* const* d_in, const int* in_sizes, int n_in,
                              void* d_out, int out_size) {
    const float* x = (const float*)d_in[0];
    const void* ei = d_in[1];
    const float* Wq = (const float*)d_in[2];
    const float* bq = (const float*)d_in[3];
    const float* Wk = (const float*)d_in[4];
    const float* bk = (const float*)d_in[5];
    const float* Wv = (const float*)d_in[6];
    const float* bv = (const float*)d_in[7];
    const float* Wo = (const float*)d_in[8];
    const float* bo = (const float*)d_in[9];
    const float* W1 = (const float*)d_in[10];
    const float* b1 = (const float*)d_in[11];
    const float* W2 = (const float*)d_in[12];
    const float* b2 = (const float*)d_in[13];
    const float* g1 = (const float*)d_in[14];
    const float* be1 = (const float*)d_in[15];
    const float* g2 = (const float*)d_in[16];
    const float* be2 = (const float*)d_in[17];
    float* out = (float*)d_out;

    cudaFuncSetAttribute(gemm_kernel, cudaFuncAttributeMaxDynamicSharedMemorySize, GEMM_SMEM);

    // Lazily-created side stream + fork/join events (created on the first
    // uncaptured correctness call; reused during capture -> parallel branches).
    static cudaStream_t s_side = nullptr;
    static cudaEvent_t ev_fork = nullptr, ev_join = nullptr;
    if (s_side == nullptr) {
        if (cudaStreamCreateWithFlags(&s_side, cudaStreamNonBlocking) != cudaSuccess)
            s_side = nullptr;
        if (s_side) {
            cudaEventCreateWithFlags(&ev_fork, cudaEventDisableTiming);
            cudaEventCreateWithFlags(&ev_join, cudaEventDisableTiming);
        }
    }

    const int SCB = (NN + 1023) / 1024;  // 49

    if (s_side) {
        // fork: CSR build chain on side stream, weights/QKV on main stream
        cudaEventRecord(ev_fork, 0);
        cudaStreamWaitEvent(s_side, ev_fork, 0);

        zero_fill<<<SCB, 1024, 0, s_side>>>();
        prep_edges<<<(EE + 255) / 256, 256, 0, s_side>>>(ei);
        scan_bt<<<SCB, 1024, 0, s_side>>>();
        scan_fix<<<SCB, 1024, 0, s_side>>>();
        scatter_kernel<<<(EE + 255) / 256, 256, 0, s_side>>>();
        cudaEventRecord(ev_join, s_side);

        prep_wx<<<(NN * HID + 255) / 256, 256>>>(x, Wq, bq, Wk, bk, Wv, bv, Wo, bo, W1, b1, W2, b2);
        gemm_kernel<<<dim3(391, 3), 256, GEMM_SMEM>>>(0, NN, 384, 128, nullptr, nullptr, nullptr, nullptr); // QKV

        cudaStreamWaitEvent(0, ev_join, 0);
    } else {
        zero_fill<<<SCB, 1024>>>();
        prep_edges<<<(EE + 255) / 256, 256>>>(ei);
        scan_bt<<<SCB, 1024>>>();
        scan_fix<<<SCB, 1024>>>();
        scatter_kernel<<<(EE + 255) / 256, 256>>>();
        prep_wx<<<(NN * HID + 255) / 256, 256>>>(x, Wq, bq, Wk, bk, Wv, bv, Wo, bo, W1, b1, W2, b2);
        gemm_kernel<<<dim3(391, 3), 256, GEMM_SMEM>>>(0, NN, 384, 128, nullptr, nullptr, nullptr, nullptr);
    }

    attn_kernel<<<(NN * 32 + 255) / 256, 256>>>();                                                       // agg
    gemm_kernel<<<dim3(391, 1), 256, GEMM_SMEM>>>(1, NN, 128, 128, x, g1, be1, nullptr);                 // Wo + LN1
    gemm_kernel<<<dim3(391, 4), 256, GEMM_SMEM>>>(2, NN, 512, 128, nullptr, nullptr, nullptr, nullptr);  // W1 + gelu
    gemm_kernel<<<dim3(391, 1), 256, GEMM_SMEM>>>(3, NN, 128, 512, nullptr, g2, be2, out);               // W2 + LN2
}

// round 15
// speedup vs baseline: 1.6246x; 1.0514x over previous
#include <cuda_runtime.h>
#include <cuda_bf16.h>
#include <math.h>

#define NN 50000
#define EE 800000
#define HID 128
#define FFH 512

// ---------------- scratch (device globals: allocation-free) ----------------
__device__ __nv_bfloat16 g_xbf[(size_t)NN * HID];
__device__ __nv_bfloat16 g_wcat[384 * 128];
__device__ __nv_bfloat16 g_wo[128 * 128];
__device__ __nv_bfloat16 g_w1[512 * 128];
__device__ __nv_bfloat16 g_w2[128 * 512];
__device__ float g_bcat[384], g_bo[128], g_b1[512], g_b2[128];
__device__ __nv_bfloat16 g_qkv[(size_t)NN * 384];
__device__ int g_src[EE], g_dst[EE], g_esrc[EE];
__device__ int g_rowptr[NN + 1], g_fill[NN];
__device__ int g_bsum[64];
__device__ int g_arrive;   // static-init 0; reset to 0 by last block every call
__device__ __nv_bfloat16 g_aggbf[(size_t)NN * HID];
__device__ float g_h[(size_t)NN * HID];
__device__ __nv_bfloat16 g_hbf[(size_t)NN * HID];
__device__ __nv_bfloat16 g_ff1bf[(size_t)NN * FFH];

// ---------------- prep kernels ----------------
__global__ void zero_fill() {
    int i = blockIdx.x * blockDim.x + threadIdx.x;
    if (i < NN) g_fill[i] = 0;
}

__global__ void prep_edges(const void* __restrict__ ei) {
    int i = blockIdx.x * blockDim.x + threadIdx.x;
    if (i >= EE) return;
    // dtype sniff per-thread (L1-broadcast): int64 view of int32 data combines
    // two random node ids -> ~1e14, outside [0, NN). Deterministic.
    const long long* p64 = (const long long*)ei;
    int is64 = 1;
#pragma unroll
    for (int j = 0; j < 4; j++) {
        long long v = p64[j];
        if (v < 0 || v >= NN) is64 = 0;
    }
    long long s, d;
    if (is64) {
        s = p64[i];
        d = p64[(size_t)EE + i];
    } else {
        const int* p = (const int*)ei;
        s = p[i];
        d = p[(size_t)EE + i];
    }
    if (s < 0) s = 0; if (s >= NN) s = NN - 1;
    if (d < 0) d = 0; if (d >= NN) d = NN - 1;
    g_src[i] = (int)s;
    g_dst[i] = (int)d;
    atomicAdd(&g_fill[(int)d], 1);   // fused histogram
}

// fused block-scan + (last block) top-scan via arrival counter
__global__ void scan_bt() {
    __shared__ int sh[1024];
    __shared__ int s_old;
    int b = blockIdx.x, t = threadIdx.x;
    int i = b * 1024 + t;
    int d = (i < NN) ? g_fill[i] : 0;
    sh[t] = d;
    __syncthreads();
#pragma unroll
    for (int off = 1; off < 1024; off <<= 1) {
        int v = (t >= off) ? sh[t - off] : 0;
        __syncthreads();
        sh[t] += v;
        __syncthreads();
    }
    if (i < NN) g_rowptr[i] = sh[t] - d;  // exclusive, block-local
    if (t == 1023) {
        g_bsum[b] = sh[1023];
        __threadfence();
    }
    __syncthreads();
    if (t == 0) s_old = atomicAdd(&g_arrive, 1);
    __syncthreads();
    if (s_old == gridDim.x - 1) {
        int nb = gridDim.x;
        if (t < nb) sh[t] = *(volatile int*)&g_bsum[t];
        __syncthreads();
        if (t == 0) {
            int run = 0;
            for (int j = 0; j < nb; j++) { int v = sh[j]; sh[j] = run; run += v; }
            g_rowptr[NN] = run;
            g_arrive = 0;   // deterministic reset for next call
        }
        __syncthreads();
        if (t < nb) g_bsum[t] = sh[t];
    }
}

__global__ void scan_fix() {
    int b = blockIdx.x;
    int i = b * 1024 + threadIdx.x;
    if (i < NN) {
        int r = g_rowptr[i] + g_bsum[b];
        g_rowptr[i] = r;
        g_fill[i] = r;
    }
}

__global__ void scatter_kernel() {
    int i = blockIdx.x * blockDim.x + threadIdx.x;
    if (i < EE) {
        int d = g_dst[i];
        int p = atomicAdd(&g_fill[d], 1);
        g_esrc[p] = g_src[i];
    }
}

// fused: x -> bf16 conversion + weight conversion + bias staging
__global__ void prep_wx(const float* __restrict__ x,
                        const float* __restrict__ Wq, const float* __restrict__ bq,
                        const float* __restrict__ Wk, const float* __restrict__ bk,
                        const float* __restrict__ Wv, const float* __restrict__ bv,
                        const float* __restrict__ Wo, const float* __restrict__ bo,
                        const float* __restrict__ W1, const float* __restrict__ b1,
                        const float* __restrict__ W2, const float* __restrict__ b2) {
    int i = blockIdx.x * blockDim.x + threadIdx.x;
    if (i < NN * HID) g_xbf[i] = __float2bfloat16(x[i]);
    if (i < 128 * 128) {
        g_wcat[i]         = __float2bfloat16(Wq[i]);
        g_wcat[16384 + i] = __float2bfloat16(Wk[i]);
        g_wcat[32768 + i] = __float2bfloat16(Wv[i]);
        g_wo[i]           = __float2bfloat16(Wo[i]);
    }
    if (i < 512 * 128) {
        g_w1[i] = __float2bfloat16(W1[i]);
        g_w2[i] = __float2bfloat16(W2[i]);
    }
    if (i < 128) {
        g_bcat[i] = bq[i];
        g_bcat[128 + i] = bk[i];
        g_bcat[256 + i] = bv[i];
        g_bo[i] = bo[i];
        g_b2[i] = b2[i];
    }
    if (i < 512) g_b1[i] = b1[i];
}

// ---------------- bf16 tensor-core GEMM ----------------
__device__ __forceinline__ void mma16816(float c[4], unsigned a0, unsigned a1, unsigned a2,
                                         unsigned a3, unsigned b0, unsigned b1) {
    asm volatile(
        "mma.sync.aligned.m16n8k16.row.col.f32.bf16.bf16.f32 "
        "{%0,%1,%2,%3}, {%4,%5,%6,%7}, {%8,%9}, {%0,%1,%2,%3};\n"
        : "+f"(c[0]), "+f"(c[1]), "+f"(c[2]), "+f"(c[3])
        : "r"(a0), "r"(a1), "r"(a2), "r"(a3), "r"(b0), "r"(b1));
}

__device__ __forceinline__ void ldx4(unsigned& r0, unsigned& r1, unsigned& r2, unsigned& r3,
                                     unsigned addr) {
    asm volatile("ldmatrix.sync.aligned.m8n8.x4.shared.b16 {%0,%1,%2,%3}, [%4];"
                 : "=r"(r0), "=r"(r1), "=r"(r2), "=r"(r3)
                 : "r"(addr));
}

__device__ __forceinline__ void cp16(unsigned saddr, const void* gaddr, int szbytes) {
    asm volatile("cp.async.cg.shared.global [%0], [%1], 16, %2;"
                 :: "r"(saddr), "l"(gaddr), "r"(szbytes));
}

__device__ __forceinline__ float warp_sum(float s) {
#pragma unroll
    for (int o = 16; o > 0; o >>= 1) s += __shfl_xor_sync(0xffffffffu, s, o);
    return s;
}

__device__ __forceinline__ float gelu_f(float v) {
    return 0.5f * v * (1.0f + erff(v * 0.70710678118654752f));
}

// 64-deep K stages, double buffered (champion config: 2 CTAs/SM).
#define SSTG 36
#define STAGE_U (128 * SSTG)
#define GEMM_SMEM (4 * STAGE_U * 4)  // 73728 B

// block tile 128(M) x 128(N), 8 warps as 2(m) x 4(n), warp tile 64x32
// modes: 1 = bf16 store, 2 = gelu+bf16 store
__global__ __launch_bounds__(256) void gemm_kernel(int sel, int M, int N, int K) {
    const __nv_bfloat16 *A, *W;
    const float* bias;
    __nv_bfloat16* C16;
    int mode;
    if (sel == 0) { A = g_xbf; W = g_wcat; bias = g_bcat; mode = 1; C16 = g_qkv; }
    else          { A = g_hbf; W = g_w1;   bias = g_b1;   mode = 2; C16 = g_ff1bf; }

    extern __shared__ unsigned sh[];

    int t = threadIdx.x;
    int warp = t >> 5, lane = t & 31;
    int wm = warp >> 2, wn = warp & 3;
    int bm = blockIdx.x * 128, bn = blockIdx.y * 128;
    int r = lane >> 2, cp = lane & 3;

    float c[4][4][4];
#pragma unroll
    for (int a = 0; a < 4; a++)
#pragma unroll
        for (int b = 0; b < 4; b++)
#pragma unroll
            for (int d = 0; d < 4; d++) c[a][b][d] = 0.f;

    unsigned sbase = (unsigned)__cvta_generic_to_shared(sh);

    int q = lane >> 3, lr = lane & 7;
    int rb = lr + (q & 1) * 8;
    int cb4 = (q >> 1) * 4;
    unsigned aAddr[2];
#pragma unroll
    for (int mi2 = 0; mi2 < 2; mi2++)
        aAddr[mi2] = sbase + 4u * ((wm * 64 + mi2 * 32 + rb) * SSTG + cb4);
    unsigned bAddr[2];
#pragma unroll
    for (int n2 = 0; n2 < 2; n2++)
        bAddr[n2] = sbase + 4u * (2 * STAGE_U + (wn * 32 + n2 * 16 + rb) * SSTG + cb4);

    const int S = K >> 6;

    auto fill = [&](int s) {
        int b = s & 1;
        int kc = s << 6;
#pragma unroll
        for (int j = 0; j < 4; j++) {
            int flat = j * 256 + t;
            int row = flat >> 3, c16 = flat & 7;
            int gr = bm + row;
            const void* gp = A + (size_t)gr * K + kc + c16 * 8;
            unsigned sp = sbase + 4u * (b * STAGE_U + row * SSTG + c16 * 4);
            cp16(sp, gp, (gr < M) ? 16 : 0);
        }
#pragma unroll
        for (int j = 0; j < 4; j++) {
            int flat = j * 256 + t;
            int row = flat >> 3, c16 = flat & 7;
            const void* gp = W + (size_t)(bn + row) * K + kc + c16 * 8;
            unsigned sp = sbase + 4u * (2 * STAGE_U + b * STAGE_U + row * SSTG + c16 * 4);
            cp16(sp, gp, 16);
        }
        asm volatile("cp.async.commit_group;");
    };

    fill(0);
    for (int s = 0; s < S; s++) {
        if (s + 1 < S) {
            fill(s + 1);
            asm volatile("cp.async.wait_group 1;");
        } else {
            asm volatile("cp.async.wait_group 0;");
        }
        __syncthreads();
        unsigned boff = (unsigned)((s & 1) * STAGE_U * 4);
#pragma unroll
        for (int ks = 0; ks < 4; ks++) {
            unsigned bfr[4][2];
#pragma unroll
            for (int n2 = 0; n2 < 2; n2++) {
                unsigned r0, r1, r2, r3;
                ldx4(r0, r1, r2, r3, bAddr[n2] + boff + ks * 32);
                bfr[2 * n2][0] = r0; bfr[2 * n2 + 1][0] = r1;
                bfr[2 * n2][1] = r2; bfr[2 * n2 + 1][1] = r3;
            }
#pragma unroll
            for (int mi = 0; mi < 4; mi++) {
                unsigned a0, a1, a2, a3;
                ldx4(a0, a1, a2, a3, aAddr[mi >> 1] + boff + (mi & 1) * (16u * SSTG * 4) + ks * 32);
#pragma unroll
                for (int ni = 0; ni < 4; ni++)
                    mma16816(c[mi][ni], a0, a1, a2, a3, bfr[ni][0], bfr[ni][1]);
            }
        }
        __syncthreads();
    }

#pragma unroll
    for (int mi = 0; mi < 4; mi++) {
        int grow0 = bm + wm * 64 + mi * 16 + r;
        int grow1 = grow0 + 8;
#pragma unroll
        for (int ni = 0; ni < 4; ni++) {
            int col = bn + wn * 32 + ni * 8 + cp * 2;
            float bb0 = bias[col], bb1 = bias[col + 1];
            float v0 = c[mi][ni][0] + bb0, v1 = c[mi][ni][1] + bb1;
            float v2 = c[mi][ni][2] + bb0, v3 = c[mi][ni][3] + bb1;
            if (mode == 2) { v0 = gelu_f(v0); v1 = gelu_f(v1); v2 = gelu_f(v2); v3 = gelu_f(v3); }
            if (grow0 < M) {
                __nv_bfloat162 h;
                h.x = __float2bfloat16(v0); h.y = __float2bfloat16(v1);
                *reinterpret_cast<__nv_bfloat162*>(&C16[(size_t)grow0 * N + col]) = h;
            }
            if (grow1 < M) {
                __nv_bfloat162 h;
                h.x = __float2bfloat16(v2); h.y = __float2bfloat16(v3);
                *reinterpret_cast<__nv_bfloat162*>(&C16[(size_t)grow1 * N + col]) = h;
            }
        }
    }
}

// ============ 64x128-tile GEMM with fused residual+LN epilogue ============
// sel 1: agg @ Wo^T (K=128) -> LN1 -> g_h/g_hbf ; sel 3: ff1 @ W2^T (K=512) -> LN2 -> out
#define A64_U (64 * SSTG)
#define B64_U (128 * SSTG)
#define GEMM64_SMEM ((2 * A64_U + 2 * B64_U) * 4)  // 55296 B

__global__ __launch_bounds__(256) void gemm_ln64(int sel, int M, int K,
                                                 const float* __restrict__ resid_in,
                                                 const float* __restrict__ gam,
                                                 const float* __restrict__ bet,
                                                 float* __restrict__ outp) {
    const __nv_bfloat16 *A, *W;
    const float* bias;
    if (sel == 1) { A = g_aggbf; W = g_wo; bias = g_bo; }
    else          { A = g_ff1bf; W = g_w2; bias = g_b2; }
    const float* resid = (sel == 1) ? resid_in : g_h;
    float* O32 = (sel == 1) ? g_h : outp;
    __nv_bfloat16* O16 = (sel == 1) ? g_hbf : nullptr;

    extern __shared__ unsigned sh[];

    int t = threadIdx.x;
    int warp = t >> 5, lane = t & 31;
    int wm = warp >> 2, wn = warp & 3;
    int bm = blockIdx.x * 64;
    int r = lane >> 2, cp = lane & 3;

    float c[2][4][4];
#pragma unroll
    for (int a = 0; a < 2; a++)
#pragma unroll
        for (int b = 0; b < 4; b++)
#pragma unroll
            for (int d = 0; d < 4; d++) c[a][b][d] = 0.f;

    unsigned sbase = (unsigned)__cvta_generic_to_shared(sh);

    int q = lane >> 3, lr = lane & 7;
    int rb = lr + (q & 1) * 8;
    int cb4 = (q >> 1) * 4;
    unsigned aAddr[2];
#pragma unroll
    for (int mi = 0; mi < 2; mi++)
        aAddr[mi] = sbase + 4u * ((wm * 32 + mi * 16 + rb) * SSTG + cb4);
    unsigned bAddr[2];
#pragma unroll
    for (int n2 = 0; n2 < 2; n2++)
        bAddr[n2] = sbase + 4u * (2 * A64_U + (wn * 32 + n2 * 16 + rb) * SSTG + cb4);

    const int S = K >> 6;

    auto fill = [&](int s) {
        int b = s & 1;
        int kc = s << 6;
#pragma unroll
        for (int j = 0; j < 2; j++) {   // A: 64 rows x 8 c16
            int flat = j * 256 + t;
            int row = flat >> 3, c16 = flat & 7;
            int gr = bm + row;
            const void* gp = A + (size_t)gr * K + kc + c16 * 8;
            unsigned sp = sbase + 4u * (b * A64_U + row * SSTG + c16 * 4);
            cp16(sp, gp, (gr < M) ? 16 : 0);
        }
#pragma unroll
        for (int j = 0; j < 4; j++) {   // B: 128 rows x 8 c16
            int flat = j * 256 + t;
            int row = flat >> 3, c16 = flat & 7;
            const void* gp = W + (size_t)row * K + kc + c16 * 8;
            unsigned sp = sbase + 4u * (2 * A64_U + b * B64_U + row * SSTG + c16 * 4);
            cp16(sp, gp, 16);
        }
        asm volatile("cp.async.commit_group;");
    };

    fill(0);
    for (int s = 0; s < S; s++) {
        if (s + 1 < S) {
            fill(s + 1);
            asm volatile("cp.async.wait_group 1;");
        } else {
            asm volatile("cp.async.wait_group 0;");
        }
        __syncthreads();
        unsigned aoff = (unsigned)((s & 1) * A64_U * 4);
        unsigned boff = (unsigned)((s & 1) * B64_U * 4);
#pragma unroll
        for (int ks = 0; ks < 4; ks++) {
            unsigned bfr[4][2];
#pragma unroll
            for (int n2 = 0; n2 < 2; n2++) {
                unsigned r0, r1, r2, r3;
                ldx4(r0, r1, r2, r3, bAddr[n2] + boff + ks * 32);
                bfr[2 * n2][0] = r0; bfr[2 * n2 + 1][0] = r1;
                bfr[2 * n2][1] = r2; bfr[2 * n2 + 1][1] = r3;
            }
#pragma unroll
            for (int mi = 0; mi < 2; mi++) {
                unsigned a0, a1, a2, a3;
                ldx4(a0, a1, a2, a3, aAddr[mi] + aoff + ks * 32);
#pragma unroll
                for (int ni = 0; ni < 4; ni++)
                    mma16816(c[mi][ni], a0, a1, a2, a3, bfr[ni][0], bfr[ni][1]);
            }
        }
        __syncthreads();
    }

    // fused residual + LayerNorm epilogue over 64-row tile
    float* Cs = (float*)sh;  // [64][132] = 33792 B
#pragma unroll
    for (int mi = 0; mi < 2; mi++) {
        int rl0 = wm * 32 + mi * 16 + r;
#pragma unroll
        for (int ni = 0; ni < 4; ni++) {
            int col = wn * 32 + ni * 8 + cp * 2;
            Cs[rl0 * 132 + col]           = c[mi][ni][0];
            Cs[rl0 * 132 + col + 1]       = c[mi][ni][1];
            Cs[(rl0 + 8) * 132 + col]     = c[mi][ni][2];
            Cs[(rl0 + 8) * 132 + col + 1] = c[mi][ni][3];
        }
    }
    __syncthreads();
    int cbx = lane * 4;
    float b0 = bias[cbx], b1 = bias[cbx + 1], b2v = bias[cbx + 2], b3 = bias[cbx + 3];
    float gg0 = gam[cbx], gg1 = gam[cbx + 1], gg2 = gam[cbx + 2], gg3 = gam[cbx + 3];
    float bb0 = bet[cbx], bb1 = bet[cbx + 1], bb2 = bet[cbx + 2], bb3 = bet[cbx + 3];
#pragma unroll
    for (int i = 0; i < 8; i++) {
        int rl = warp * 8 + i;
        int grow = bm + rl;
        if (grow >= M) break;
        const float* rr = resid + (size_t)grow * 128 + cbx;
        float t0 = Cs[rl * 132 + cbx]     + b0 + rr[0];
        float t1 = Cs[rl * 132 + cbx + 1] + b1 + rr[1];
        float t2 = Cs[rl * 132 + cbx + 2] + b2v + rr[2];
        float t3 = Cs[rl * 132 + cbx + 3] + b3 + rr[3];
        float mu = warp_sum(t0 + t1 + t2 + t3) * (1.f / 128.f);
        float d0 = t0 - mu, d1 = t1 - mu, d2 = t2 - mu, d3 = t3 - mu;
        float var = warp_sum(d0 * d0 + d1 * d1 + d2 * d2 + d3 * d3) * (1.f / 128.f);
        float rs = rsqrtf(var + 1e-5f);
        float o0 = d0 * rs * gg0 + bb0;
        float o1 = d1 * rs * gg1 + bb1;
        float o2 = d2 * rs * gg2 + bb2;
        float o3 = d3 * rs * gg3 + bb3;
        *reinterpret_cast<float4*>(O32 + (size_t)grow * 128 + cbx) =
            make_float4(o0, o1, o2, o3);
        if (O16) {
            __nv_bfloat162 p0, p1;
            p0.x = __float2bfloat16(o0); p0.y = __float2bfloat16(o1);
            p1.x = __float2bfloat16(o2); p1.y = __float2bfloat16(o3);
            uint2 u;
            u.x = *reinterpret_cast<unsigned*>(&p0);
            u.y = *reinterpret_cast<unsigned*>(&p1);
            *reinterpret_cast<uint2*>(O16 + (size_t)grow * 128 + cbx) = u;
        }
    }
}

// ---------------- attention: lane = (edge-group, head); 8 edges in flight ----------------
__device__ __forceinline__ void ld16bf(float* f, const __nv_bfloat16* p) {
    uint4 u0 = *reinterpret_cast<const uint4*>(p);
    uint4 u1 = *reinterpret_cast<const uint4*>(p + 8);
    const unsigned* w = &u0.x;
#pragma unroll
    for (int j = 0; j < 4; j++) {
        float2 f2 = __bfloat1622float2(*reinterpret_cast<const __nv_bfloat162*>(&w[j]));
        f[2 * j] = f2.x; f[2 * j + 1] = f2.y;
    }
    const unsigned* w1 = &u1.x;
#pragma unroll
    for (int j = 0; j < 4; j++) {
        float2 f2 = __bfloat1622float2(*reinterpret_cast<const __nv_bfloat162*>(&w1[j]));
        f[8 + 2 * j] = f2.x; f[8 + 2 * j + 1] = f2.y;
    }
}

__global__ __launch_bounds__(256) void attn_kernel() {
    int w = (blockIdx.x * blockDim.x + threadIdx.x) >> 5;  // node
    if (w >= NN) return;
    int lane = threadIdx.x & 31;
    int g = lane >> 3;   // edge-group 0..3
    int h = lane & 7;    // head 0..7

    float qv[16];
    ld16bf(qv, g_qkv + (size_t)w * 384 + h * 16);

    int s = g_rowptr[w], e = g_rowptr[w + 1];
    int iters = (e - s + 3) >> 2;

    float denom = 0.f;
    float acc[16];
#pragma unroll
    for (int i = 0; i < 16; i++) acc[i] = 0.f;

    int it = 0;
    for (; it + 2 <= iters; it += 2) {
        int p0 = s + it * 4 + g;
        int p1 = p0 + 4;
        bool v0 = p0 < e, v1 = p1 < e;
        int s0 = v0 ? g_esrc[p0] : 0;
        int s1 = v1 ? g_esrc[p1] : 0;
        const __nv_bfloat16* b0 = g_qkv + (size_t)s0 * 384 + h * 16;
        const __nv_bfloat16* b1 = g_qkv + (size_t)s1 * 384 + h * 16;
        float kv0[16], vv0[16], kv1[16], vv1[16];
        ld16bf(kv0, b0 + 128);
        ld16bf(vv0, b0 + 256);
        ld16bf(kv1, b1 + 128);
        ld16bf(vv1, b1 + 256);
        float d0 = 0.f, d1 = 0.f;
#pragma unroll
        for (int i = 0; i < 16; i++) { d0 += qv[i] * kv0[i]; d1 += qv[i] * kv1[i]; }
        float ea0 = v0 ? __expf(d0 * 0.25f) : 0.f;
        denom += ea0;
#pragma unroll
        for (int i = 0; i < 16; i++) acc[i] += ea0 * vv0[i];
        float ea1 = v1 ? __expf(d1 * 0.25f) : 0.f;
        denom += ea1;
#pragma unroll
        for (int i = 0; i < 16; i++) acc[i] += ea1 * vv1[i];
    }
    for (; it < iters; it++) {
        int p = s + it * 4 + g;
        bool valid = p < e;
        int src = valid ? g_esrc[p] : 0;
        const __nv_bfloat16* base = g_qkv + (size_t)src * 384 + h * 16;
        float kv[16], vv[16];
        ld16bf(kv, base + 128);
        ld16bf(vv, base + 256);
        float d = 0.f;
#pragma unroll
        for (int i = 0; i < 16; i++) d += qv[i] * kv[i];
        float ea = valid ? __expf(d * 0.25f) : 0.f;
        denom += ea;
#pragma unroll
        for (int i = 0; i < 16; i++) acc[i] += ea * vv[i];
    }

    denom += __shfl_xor_sync(0xffffffffu, denom, 8);
    denom += __shfl_xor_sync(0xffffffffu, denom, 16);
#pragma unroll
    for (int i = 0; i < 16; i++) {
        acc[i] += __shfl_xor_sync(0xffffffffu, acc[i], 8);
        acc[i] += __shfl_xor_sync(0xffffffffu, acc[i], 16);
    }
    float inv = 1.f / (denom + 1e-16f);
    if (g == 0) {
        unsigned pk[8];
#pragma unroll
        for (int j = 0; j < 8; j++) {
            __nv_bfloat162 b;
            b.x = __float2bfloat16(acc[2 * j] * inv);
            b.y = __float2bfloat16(acc[2 * j + 1] * inv);
            pk[j] = *reinterpret_cast<unsigned*>(&b);
        }
        __nv_bfloat16* out = g_aggbf + (size_t)w * 128 + h * 16;
        *reinterpret_cast<uint4*>(out)     = make_uint4(pk[0], pk[1], pk[2], pk[3]);
        *reinterpret_cast<uint4*>(out + 8) = make_uint4(pk[4], pk[5], pk[6], pk[7]);
    }
}

// ---------------- launch ----------------
extern "C" void kernel_launch(void* const* d_in, const int* in_sizes, int n_in,
                              void* d_out, int out_size) {
    const float* x = (const float*)d_in[0];
    const void* ei = d_in[1];
    const float* Wq = (const float*)d_in[2];
    const float* bq = (const float*)d_in[3];
    const float* Wk = (const float*)d_in[4];
    const float* bk = (const float*)d_in[5];
    const float* Wv = (const float*)d_in[6];
    const float* bv = (const float*)d_in[7];
    const float* Wo = (const float*)d_in[8];
    const float* bo = (const float*)d_in[9];
    const float* W1 = (const float*)d_in[10];
    const float* b1 = (const float*)d_in[11];
    const float* W2 = (const float*)d_in[12];
    const float* b2 = (const float*)d_in[13];
    const float* g1 = (const float*)d_in[14];
    const float* be1 = (const float*)d_in[15];
    const float* g2 = (const float*)d_in[16];
    const float* be2 = (const float*)d_in[17];
    float* out = (float*)d_out;

    cudaFuncSetAttribute(gemm_kernel, cudaFuncAttributeMaxDynamicSharedMemorySize, GEMM_SMEM);
    cudaFuncSetAttribute(gemm_ln64, cudaFuncAttributeMaxDynamicSharedMemorySize, GEMM64_SMEM);

    // Lazily-created side stream + fork/join events (created on the first
    // uncaptured correctness call; reused during capture -> parallel branches).
    static cudaStream_t s_side = nullptr;
    static cudaEvent_t ev_fork = nullptr, ev_join = nullptr;
    if (s_side == nullptr) {
        if (cudaStreamCreateWithFlags(&s_side, cudaStreamNonBlocking) != cudaSuccess)
            s_side = nullptr;
        if (s_side) {
            cudaEventCreateWithFlags(&ev_fork, cudaEventDisableTiming);
            cudaEventCreateWithFlags(&ev_join, cudaEventDisableTiming);
        }
    }

    const int SCB = (NN + 1023) / 1024;  // 49
    const int M64 = (NN + 63) / 64;      // 782

    if (s_side) {
        // fork: CSR build chain on side stream, weights/QKV on main stream
        cudaEventRecord(ev_fork, 0);
        cudaStreamWaitEvent(s_side, ev_fork, 0);

        zero_fill<<<SCB, 1024, 0, s_side>>>();
        prep_edges<<<(EE + 255) / 256, 256, 0, s_side>>>(ei);
        scan_bt<<<SCB, 1024, 0, s_side>>>();
        scan_fix<<<SCB, 1024, 0, s_side>>>();
        scatter_kernel<<<(EE + 255) / 256, 256, 0, s_side>>>();
        cudaEventRecord(ev_join, s_side);

        prep_wx<<<(NN * HID + 255) / 256, 256>>>(x, Wq, bq, Wk, bk, Wv, bv, Wo, bo, W1, b1, W2, b2);
        gemm_kernel<<<dim3(391, 3), 256, GEMM_SMEM>>>(0, NN, 384, 128);   // QKV

        cudaStreamWaitEvent(0, ev_join, 0);
    } else {
        zero_fill<<<SCB, 1024>>>();
        prep_edges<<<(EE + 255) / 256, 256>>>(ei);
        scan_bt<<<SCB, 1024>>>();
        scan_fix<<<SCB, 1024>>>();
        scatter_kernel<<<(EE + 255) / 256, 256>>>();
        prep_wx<<<(NN * HID + 255) / 256, 256>>>(x, Wq, bq, Wk, bk, Wv, bv, Wo, bo, W1, b1, W2, b2);
        gemm_kernel<<<dim3(391, 3), 256, GEMM_SMEM>>>(0, NN, 384, 128);
    }

    attn_kernel<<<(NN * 32 + 255) / 256, 256>>>();                              // agg
    gemm_ln64<<<M64, 256, GEMM64_SMEM>>>(1, NN, 128, x, g1, be1, nullptr);      // Wo + LN1
    gemm_kernel<<<dim3(391, 4), 256, GEMM_SMEM>>>(2, NN, 512, 128);             // W1 + gelu
    gemm_ln64<<<M64, 256, GEMM64_SMEM>>>(3, NN, 512, nullptr, g2, be2, out);    // W2 + LN2
}

// round 16
// speedup vs baseline: 1.6600x; 1.0218x over previous
#include <cuda_runtime.h>
#include <cuda_bf16.h>
#include <math.h>

#define NN 50000
#define EE 800000
#define HID 128
#define FFH 512

// ---------------- scratch (device globals: allocation-free) ----------------
__device__ __nv_bfloat16 g_xbf[(size_t)NN * HID];
__device__ __nv_bfloat16 g_wcat[384 * 128];
__device__ __nv_bfloat16 g_wo[128 * 128];
__device__ __nv_bfloat16 g_w1[512 * 128];
__device__ __nv_bfloat16 g_w2[128 * 512];
__device__ float g_bcat[384], g_bo[128], g_b1[512], g_b2[128];
__device__ __nv_bfloat16 g_qkv[(size_t)NN * 384];
__device__ int g_src[EE], g_dst[EE], g_esrc[EE];
__device__ int g_rowptr[NN + 1], g_fill[NN];
__device__ int g_bsum[64];
__device__ int g_arrive;   // static-init 0; reset to 0 by last block every call
__device__ __nv_bfloat16 g_aggbf[(size_t)NN * HID];
__device__ float g_h[(size_t)NN * HID];
__device__ __nv_bfloat16 g_hbf[(size_t)NN * HID];
__device__ __nv_bfloat16 g_ff1bf[(size_t)NN * FFH];

// ---------------- prep kernels ----------------
__global__ void zero_fill() {
    int i = blockIdx.x * blockDim.x + threadIdx.x;
    if (i < NN) g_fill[i] = 0;
}

__global__ void prep_edges(const void* __restrict__ ei) {
    int i = blockIdx.x * blockDim.x + threadIdx.x;
    if (i >= EE) return;
    // dtype sniff per-thread (L1-broadcast): int64 view of int32 data combines
    // two random node ids -> ~1e14, outside [0, NN). Deterministic.
    const long long* p64 = (const long long*)ei;
    int is64 = 1;
#pragma unroll
    for (int j = 0; j < 4; j++) {
        long long v = p64[j];
        if (v < 0 || v >= NN) is64 = 0;
    }
    long long s, d;
    if (is64) {
        s = p64[i];
        d = p64[(size_t)EE + i];
    } else {
        const int* p = (const int*)ei;
        s = p[i];
        d = p[(size_t)EE + i];
    }
    if (s < 0) s = 0; if (s >= NN) s = NN - 1;
    if (d < 0) d = 0; if (d >= NN) d = NN - 1;
    g_src[i] = (int)s;
    g_dst[i] = (int)d;
    atomicAdd(&g_fill[(int)d], 1);   // fused histogram
}

// fused block-scan + (last block) top-scan via arrival counter
__global__ void scan_bt() {
    __shared__ int sh[1024];
    __shared__ int s_old;
    int b = blockIdx.x, t = threadIdx.x;
    int i = b * 1024 + t;
    int d = (i < NN) ? g_fill[i] : 0;
    sh[t] = d;
    __syncthreads();
#pragma unroll
    for (int off = 1; off < 1024; off <<= 1) {
        int v = (t >= off) ? sh[t - off] : 0;
        __syncthreads();
        sh[t] += v;
        __syncthreads();
    }
    if (i < NN) g_rowptr[i] = sh[t] - d;  // exclusive, block-local
    if (t == 1023) {
        g_bsum[b] = sh[1023];
        __threadfence();
    }
    __syncthreads();
    if (t == 0) s_old = atomicAdd(&g_arrive, 1);
    __syncthreads();
    if (s_old == gridDim.x - 1) {
        int nb = gridDim.x;
        if (t < nb) sh[t] = *(volatile int*)&g_bsum[t];
        __syncthreads();
        if (t == 0) {
            int run = 0;
            for (int j = 0; j < nb; j++) { int v = sh[j]; sh[j] = run; run += v; }
            g_rowptr[NN] = run;
            g_arrive = 0;   // deterministic reset for next call
        }
        __syncthreads();
        if (t < nb) g_bsum[t] = sh[t];
    }
}

__global__ void scan_fix() {
    int b = blockIdx.x;
    int i = b * 1024 + threadIdx.x;
    if (i < NN) {
        int r = g_rowptr[i] + g_bsum[b];
        g_rowptr[i] = r;
        g_fill[i] = r;
    }
}

__global__ void scatter_kernel() {
    int i = blockIdx.x * blockDim.x + threadIdx.x;
    if (i < EE) {
        int d = g_dst[i];
        int p = atomicAdd(&g_fill[d], 1);
        g_esrc[p] = g_src[i];
    }
}

// fused: x -> bf16 conversion + weight conversion + bias staging
__global__ void prep_wx(const float* __restrict__ x,
                        const float* __restrict__ Wq, const float* __restrict__ bq,
                        const float* __restrict__ Wk, const float* __restrict__ bk,
                        const float* __restrict__ Wv, const float* __restrict__ bv,
                        const float* __restrict__ Wo, const float* __restrict__ bo,
                        const float* __restrict__ W1, const float* __restrict__ b1,
                        const float* __restrict__ W2, const float* __restrict__ b2) {
    int i = blockIdx.x * blockDim.x + threadIdx.x;
    if (i < NN * HID) g_xbf[i] = __float2bfloat16(x[i]);
    if (i < 128 * 128) {
        g_wcat[i]         = __float2bfloat16(Wq[i]);
        g_wcat[16384 + i] = __float2bfloat16(Wk[i]);
        g_wcat[32768 + i] = __float2bfloat16(Wv[i]);
        g_wo[i]           = __float2bfloat16(Wo[i]);
    }
    if (i < 512 * 128) {
        g_w1[i] = __float2bfloat16(W1[i]);
        g_w2[i] = __float2bfloat16(W2[i]);
    }
    if (i < 128) {
        g_bcat[i] = bq[i];
        g_bcat[128 + i] = bk[i];
        g_bcat[256 + i] = bv[i];
        g_bo[i] = bo[i];
        g_b2[i] = b2[i];
    }
    if (i < 512) g_b1[i] = b1[i];
}

// ---------------- bf16 tensor-core GEMM ----------------
__device__ __forceinline__ void mma16816(float c[4], unsigned a0, unsigned a1, unsigned a2,
                                         unsigned a3, unsigned b0, unsigned b1) {
    asm volatile(
        "mma.sync.aligned.m16n8k16.row.col.f32.bf16.bf16.f32 "
        "{%0,%1,%2,%3}, {%4,%5,%6,%7}, {%8,%9}, {%0,%1,%2,%3};\n"
        : "+f"(c[0]), "+f"(c[1]), "+f"(c[2]), "+f"(c[3])
        : "r"(a0), "r"(a1), "r"(a2), "r"(a3), "r"(b0), "r"(b1));
}

__device__ __forceinline__ void ldx4(unsigned& r0, unsigned& r1, unsigned& r2, unsigned& r3,
                                     unsigned addr) {
    asm volatile("ldmatrix.sync.aligned.m8n8.x4.shared.b16 {%0,%1,%2,%3}, [%4];"
                 : "=r"(r0), "=r"(r1), "=r"(r2), "=r"(r3)
                 : "r"(addr));
}

__device__ __forceinline__ void cp16(unsigned saddr, const void* gaddr, int szbytes) {
    asm volatile("cp.async.cg.shared.global [%0], [%1], 16, %2;"
                 :: "r"(saddr), "l"(gaddr), "r"(szbytes));
}

__device__ __forceinline__ float warp_sum(float s) {
#pragma unroll
    for (int o = 16; o > 0; o >>= 1) s += __shfl_xor_sync(0xffffffffu, s, o);
    return s;
}

__device__ __forceinline__ float gelu_f(float v) {
    return 0.5f * v * (1.0f + erff(v * 0.70710678118654752f));
}

// 64-deep K stages, double buffered (champion config: 2 CTAs/SM).
#define SSTG 36
#define STAGE_U (128 * SSTG)
#define GEMM_SMEM (4 * STAGE_U * 4)  // 73728 B

// ============ 128x128 GEMM: QKV only ============
__global__ __launch_bounds__(256) void gemm_kernel(int M, int N, int K) {
    const __nv_bfloat16 *A = g_xbf, *W = g_wcat;
    const float* bias = g_bcat;
    __nv_bfloat16* C16 = g_qkv;

    extern __shared__ unsigned sh[];

    int t = threadIdx.x;
    int warp = t >> 5, lane = t & 31;
    int wm = warp >> 2, wn = warp & 3;
    int bm = blockIdx.x * 128, bn = blockIdx.y * 128;
    int r = lane >> 2, cp = lane & 3;

    float c[4][4][4];
#pragma unroll
    for (int a = 0; a < 4; a++)
#pragma unroll
        for (int b = 0; b < 4; b++)
#pragma unroll
            for (int d = 0; d < 4; d++) c[a][b][d] = 0.f;

    unsigned sbase = (unsigned)__cvta_generic_to_shared(sh);

    int q = lane >> 3, lr = lane & 7;
    int rb = lr + (q & 1) * 8;
    int cb4 = (q >> 1) * 4;
    unsigned aAddr[2];
#pragma unroll
    for (int mi2 = 0; mi2 < 2; mi2++)
        aAddr[mi2] = sbase + 4u * ((wm * 64 + mi2 * 32 + rb) * SSTG + cb4);
    unsigned bAddr[2];
#pragma unroll
    for (int n2 = 0; n2 < 2; n2++)
        bAddr[n2] = sbase + 4u * (2 * STAGE_U + (wn * 32 + n2 * 16 + rb) * SSTG + cb4);

    const int S = K >> 6;

    auto fill = [&](int s) {
        int b = s & 1;
        int kc = s << 6;
#pragma unroll
        for (int j = 0; j < 4; j++) {
            int flat = j * 256 + t;
            int row = flat >> 3, c16 = flat & 7;
            int gr = bm + row;
            const void* gp = A + (size_t)gr * K + kc + c16 * 8;
            unsigned sp = sbase + 4u * (b * STAGE_U + row * SSTG + c16 * 4);
            cp16(sp, gp, (gr < M) ? 16 : 0);
        }
#pragma unroll
        for (int j = 0; j < 4; j++) {
            int flat = j * 256 + t;
            int row = flat >> 3, c16 = flat & 7;
            const void* gp = W + (size_t)(bn + row) * K + kc + c16 * 8;
            unsigned sp = sbase + 4u * (2 * STAGE_U + b * STAGE_U + row * SSTG + c16 * 4);
            cp16(sp, gp, 16);
        }
        asm volatile("cp.async.commit_group;");
    };

    fill(0);
    for (int s = 0; s < S; s++) {
        if (s + 1 < S) {
            fill(s + 1);
            asm volatile("cp.async.wait_group 1;");
        } else {
            asm volatile("cp.async.wait_group 0;");
        }
        __syncthreads();
        unsigned boff = (unsigned)((s & 1) * STAGE_U * 4);
#pragma unroll
        for (int ks = 0; ks < 4; ks++) {
            unsigned bfr[4][2];
#pragma unroll
            for (int n2 = 0; n2 < 2; n2++) {
                unsigned r0, r1, r2, r3;
                ldx4(r0, r1, r2, r3, bAddr[n2] + boff + ks * 32);
                bfr[2 * n2][0] = r0; bfr[2 * n2 + 1][0] = r1;
                bfr[2 * n2][1] = r2; bfr[2 * n2 + 1][1] = r3;
            }
#pragma unroll
            for (int mi = 0; mi < 4; mi++) {
                unsigned a0, a1, a2, a3;
                ldx4(a0, a1, a2, a3, aAddr[mi >> 1] + boff + (mi & 1) * (16u * SSTG * 4) + ks * 32);
#pragma unroll
                for (int ni = 0; ni < 4; ni++)
                    mma16816(c[mi][ni], a0, a1, a2, a3, bfr[ni][0], bfr[ni][1]);
            }
        }
        __syncthreads();
    }

#pragma unroll
    for (int mi = 0; mi < 4; mi++) {
        int grow0 = bm + wm * 64 + mi * 16 + r;
        int grow1 = grow0 + 8;
#pragma unroll
        for (int ni = 0; ni < 4; ni++) {
            int col = bn + wn * 32 + ni * 8 + cp * 2;
            float bb0 = bias[col], bb1 = bias[col + 1];
            float v0 = c[mi][ni][0] + bb0, v1 = c[mi][ni][1] + bb1;
            float v2 = c[mi][ni][2] + bb0, v3 = c[mi][ni][3] + bb1;
            if (grow0 < M) {
                __nv_bfloat162 h;
                h.x = __float2bfloat16(v0); h.y = __float2bfloat16(v1);
                *reinterpret_cast<__nv_bfloat162*>(&C16[(size_t)grow0 * N + col]) = h;
            }
            if (grow1 < M) {
                __nv_bfloat162 h;
                h.x = __float2bfloat16(v2); h.y = __float2bfloat16(v3);
                *reinterpret_cast<__nv_bfloat162*>(&C16[(size_t)grow1 * N + col]) = h;
            }
        }
    }
}

// ============ 64x128-tile GEMM: LN epilogues + FF1(gelu) ============
// sel 1: agg @ Wo^T (K=128) -> LN1 ; sel 2: h @ W1^T (K=128, N=512) -> gelu -> ff1
// sel 3: ff1 @ W2^T (K=512) -> LN2 -> out
#define A64_U (64 * SSTG)
#define B64_U (128 * SSTG)
#define GEMM64_SMEM ((2 * A64_U + 2 * B64_U) * 4)  // 55296 B

__global__ __launch_bounds__(256) void gemm64(int sel, int M, int K,
                                              const float* __restrict__ resid_in,
                                              const float* __restrict__ gam,
                                              const float* __restrict__ bet,
                                              float* __restrict__ outp) {
    const __nv_bfloat16 *A, *W;
    const float* bias;
    if (sel == 1)      { A = g_aggbf; W = g_wo; bias = g_bo; }
    else if (sel == 2) { A = g_hbf;   W = g_w1; bias = g_b1; }
    else               { A = g_ff1bf; W = g_w2; bias = g_b2; }
    const float* resid = (sel == 1) ? resid_in : g_h;
    float* O32 = (sel == 1) ? g_h : outp;
    __nv_bfloat16* O16 = (sel == 1) ? g_hbf : nullptr;

    extern __shared__ unsigned sh[];

    int t = threadIdx.x;
    int warp = t >> 5, lane = t & 31;
    int wm = warp >> 2, wn = warp & 3;
    int bm = blockIdx.x * 64;
    int bn = blockIdx.y * 128;   // 0 except sel 2 (N=512)
    int r = lane >> 2, cp = lane & 3;

    float c[2][4][4];
#pragma unroll
    for (int a = 0; a < 2; a++)
#pragma unroll
        for (int b = 0; b < 4; b++)
#pragma unroll
            for (int d = 0; d < 4; d++) c[a][b][d] = 0.f;

    unsigned sbase = (unsigned)__cvta_generic_to_shared(sh);

    int q = lane >> 3, lr = lane & 7;
    int rb = lr + (q & 1) * 8;
    int cb4 = (q >> 1) * 4;
    unsigned aAddr[2];
#pragma unroll
    for (int mi = 0; mi < 2; mi++)
        aAddr[mi] = sbase + 4u * ((wm * 32 + mi * 16 + rb) * SSTG + cb4);
    unsigned bAddr[2];
#pragma unroll
    for (int n2 = 0; n2 < 2; n2++)
        bAddr[n2] = sbase + 4u * (2 * A64_U + (wn * 32 + n2 * 16 + rb) * SSTG + cb4);

    const int S = K >> 6;

    auto fill = [&](int s) {
        int b = s & 1;
        int kc = s << 6;
#pragma unroll
        for (int j = 0; j < 2; j++) {   // A: 64 rows x 8 c16
            int flat = j * 256 + t;
            int row = flat >> 3, c16 = flat & 7;
            int gr = bm + row;
            const void* gp = A + (size_t)gr * K + kc + c16 * 8;
            unsigned sp = sbase + 4u * (b * A64_U + row * SSTG + c16 * 4);
            cp16(sp, gp, (gr < M) ? 16 : 0);
        }
#pragma unroll
        for (int j = 0; j < 4; j++) {   // B: 128 rows x 8 c16
            int flat = j * 256 + t;
            int row = flat >> 3, c16 = flat & 7;
            const void* gp = W + (size_t)(bn + row) * K + kc + c16 * 8;
            unsigned sp = sbase + 4u * (2 * A64_U + b * B64_U + row * SSTG + c16 * 4);
            cp16(sp, gp, 16);
        }
        asm volatile("cp.async.commit_group;");
    };

    fill(0);
    for (int s = 0; s < S; s++) {
        if (s + 1 < S) {
            fill(s + 1);
            asm volatile("cp.async.wait_group 1;");
        } else {
            asm volatile("cp.async.wait_group 0;");
        }
        __syncthreads();
        unsigned aoff = (unsigned)((s & 1) * A64_U * 4);
        unsigned boff = (unsigned)((s & 1) * B64_U * 4);
#pragma unroll
        for (int ks = 0; ks < 4; ks++) {
            unsigned bfr[4][2];
#pragma unroll
            for (int n2 = 0; n2 < 2; n2++) {
                unsigned r0, r1, r2, r3;
                ldx4(r0, r1, r2, r3, bAddr[n2] + boff + ks * 32);
                bfr[2 * n2][0] = r0; bfr[2 * n2 + 1][0] = r1;
                bfr[2 * n2][1] = r2; bfr[2 * n2 + 1][1] = r3;
            }
#pragma unroll
            for (int mi = 0; mi < 2; mi++) {
                unsigned a0, a1, a2, a3;
                ldx4(a0, a1, a2, a3, aAddr[mi] + aoff + ks * 32);
#pragma unroll
                for (int ni = 0; ni < 4; ni++)
                    mma16816(c[mi][ni], a0, a1, a2, a3, bfr[ni][0], bfr[ni][1]);
            }
        }
        __syncthreads();
    }

    if (sel == 2) {
        // gelu + bf16 store, N = 512
#pragma unroll
        for (int mi = 0; mi < 2; mi++) {
            int grow0 = bm + wm * 32 + mi * 16 + r;
            int grow1 = grow0 + 8;
#pragma unroll
            for (int ni = 0; ni < 4; ni++) {
                int col = bn + wn * 32 + ni * 8 + cp * 2;
                float bb0 = bias[col], bb1 = bias[col + 1];
                float v0 = gelu_f(c[mi][ni][0] + bb0), v1 = gelu_f(c[mi][ni][1] + bb1);
                float v2 = gelu_f(c[mi][ni][2] + bb0), v3 = gelu_f(c[mi][ni][3] + bb1);
                if (grow0 < M) {
                    __nv_bfloat162 h;
                    h.x = __float2bfloat16(v0); h.y = __float2bfloat16(v1);
                    *reinterpret_cast<__nv_bfloat162*>(&g_ff1bf[(size_t)grow0 * FFH + col]) = h;
                }
                if (grow1 < M) {
                    __nv_bfloat162 h;
                    h.x = __float2bfloat16(v2); h.y = __float2bfloat16(v3);
                    *reinterpret_cast<__nv_bfloat162*>(&g_ff1bf[(size_t)grow1 * FFH + col]) = h;
                }
            }
        }
        return;
    }

    // fused residual + LayerNorm epilogue over 64-row tile (N == 128)
    float* Cs = (float*)sh;  // [64][132] = 33792 B
#pragma unroll
    for (int mi = 0; mi < 2; mi++) {
        int rl0 = wm * 32 + mi * 16 + r;
#pragma unroll
        for (int ni = 0; ni < 4; ni++) {
            int col = wn * 32 + ni * 8 + cp * 2;
            Cs[rl0 * 132 + col]           = c[mi][ni][0];
            Cs[rl0 * 132 + col + 1]       = c[mi][ni][1];
            Cs[(rl0 + 8) * 132 + col]     = c[mi][ni][2];
            Cs[(rl0 + 8) * 132 + col + 1] = c[mi][ni][3];
        }
    }
    __syncthreads();
    int cbx = lane * 4;
    float b0 = bias[cbx], b1 = bias[cbx + 1], b2v = bias[cbx + 2], b3 = bias[cbx + 3];
    float gg0 = gam[cbx], gg1 = gam[cbx + 1], gg2 = gam[cbx + 2], gg3 = gam[cbx + 3];
    float bb0 = bet[cbx], bb1 = bet[cbx + 1], bb2 = bet[cbx + 2], bb3 = bet[cbx + 3];
#pragma unroll
    for (int i = 0; i < 8; i++) {
        int rl = warp * 8 + i;
        int grow = bm + rl;
        if (grow >= M) break;
        const float* rr = resid + (size_t)grow * 128 + cbx;
        float t0 = Cs[rl * 132 + cbx]     + b0 + rr[0];
        float t1 = Cs[rl * 132 + cbx + 1] + b1 + rr[1];
        float t2 = Cs[rl * 132 + cbx + 2] + b2v + rr[2];
        float t3 = Cs[rl * 132 + cbx + 3] + b3 + rr[3];
        float mu = warp_sum(t0 + t1 + t2 + t3) * (1.f / 128.f);
        float d0 = t0 - mu, d1 = t1 - mu, d2 = t2 - mu, d3 = t3 - mu;
        float var = warp_sum(d0 * d0 + d1 * d1 + d2 * d2 + d3 * d3) * (1.f / 128.f);
        float rs = rsqrtf(var + 1e-5f);
        float o0 = d0 * rs * gg0 + bb0;
        float o1 = d1 * rs * gg1 + bb1;
        float o2 = d2 * rs * gg2 + bb2;
        float o3 = d3 * rs * gg3 + bb3;
        *reinterpret_cast<float4*>(O32 + (size_t)grow * 128 + cbx) =
            make_float4(o0, o1, o2, o3);
        if (O16) {
            __nv_bfloat162 p0, p1;
            p0.x = __float2bfloat16(o0); p0.y = __float2bfloat16(o1);
            p1.x = __float2bfloat16(o2); p1.y = __float2bfloat16(o3);
            uint2 u;
            u.x = *reinterpret_cast<unsigned*>(&p0);
            u.y = *reinterpret_cast<unsigned*>(&p1);
            *reinterpret_cast<uint2*>(O16 + (size_t)grow * 128 + cbx) = u;
        }
    }
}

// ---------------- attention: lane = (edge-group, head); 8 edges in flight ----------------
__device__ __forceinline__ void ld16bf(float* f, const __nv_bfloat16* p) {
    uint4 u0 = *reinterpret_cast<const uint4*>(p);
    uint4 u1 = *reinterpret_cast<const uint4*>(p + 8);
    const unsigned* w = &u0.x;
#pragma unroll
    for (int j = 0; j < 4; j++) {
        float2 f2 = __bfloat1622float2(*reinterpret_cast<const __nv_bfloat162*>(&w[j]));
        f[2 * j] = f2.x; f[2 * j + 1] = f2.y;
    }
    const unsigned* w1 = &u1.x;
#pragma unroll
    for (int j = 0; j < 4; j++) {
        float2 f2 = __bfloat1622float2(*reinterpret_cast<const __nv_bfloat162*>(&w1[j]));
        f[8 + 2 * j] = f2.x; f[8 + 2 * j + 1] = f2.y;
    }
}

__global__ __launch_bounds__(256) void attn_kernel() {
    int w = (blockIdx.x * blockDim.x + threadIdx.x) >> 5;  // node
    if (w >= NN) return;
    int lane = threadIdx.x & 31;
    int g = lane >> 3;   // edge-group 0..3
    int h = lane & 7;    // head 0..7

    float qv[16];
    ld16bf(qv, g_qkv + (size_t)w * 384 + h * 16);

    int s = g_rowptr[w], e = g_rowptr[w + 1];
    int iters = (e - s + 3) >> 2;

    float denom = 0.f;
    float acc[16];
#pragma unroll
    for (int i = 0; i < 16; i++) acc[i] = 0.f;

    int it = 0;
    for (; it + 2 <= iters; it += 2) {
        int p0 = s + it * 4 + g;
        int p1 = p0 + 4;
        bool v0 = p0 < e, v1 = p1 < e;
        int s0 = v0 ? g_esrc[p0] : 0;
        int s1 = v1 ? g_esrc[p1] : 0;
        const __nv_bfloat16* b0 = g_qkv + (size_t)s0 * 384 + h * 16;
        const __nv_bfloat16* b1 = g_qkv + (size_t)s1 * 384 + h * 16;
        float kv0[16], vv0[16], kv1[16], vv1[16];
        ld16bf(kv0, b0 + 128);
        ld16bf(vv0, b0 + 256);
        ld16bf(kv1, b1 + 128);
        ld16bf(vv1, b1 + 256);
        float d0 = 0.f, d1 = 0.f;
#pragma unroll
        for (int i = 0; i < 16; i++) { d0 += qv[i] * kv0[i]; d1 += qv[i] * kv1[i]; }
        float ea0 = v0 ? __expf(d0 * 0.25f) : 0.f;
        denom += ea0;
#pragma unroll
        for (int i = 0; i < 16; i++) acc[i] += ea0 * vv0[i];
        float ea1 = v1 ? __expf(d1 * 0.25f) : 0.f;
        denom += ea1;
#pragma unroll
        for (int i = 0; i < 16; i++) acc[i] += ea1 * vv1[i];
    }
    for (; it < iters; it++) {
        int p = s + it * 4 + g;
        bool valid = p < e;
        int src = valid ? g_esrc[p] : 0;
        const __nv_bfloat16* base = g_qkv + (size_t)src * 384 + h * 16;
        float kv[16], vv[16];
        ld16bf(kv, base + 128);
        ld16bf(vv, base + 256);
        float d = 0.f;
#pragma unroll
        for (int i = 0; i < 16; i++) d += qv[i] * kv[i];
        float ea = valid ? __expf(d * 0.25f) : 0.f;
        denom += ea;
#pragma unroll
        for (int i = 0; i < 16; i++) acc[i] += ea * vv[i];
    }

    denom += __shfl_xor_sync(0xffffffffu, denom, 8);
    denom += __shfl_xor_sync(0xffffffffu, denom, 16);
#pragma unroll
    for (int i = 0; i < 16; i++) {
        acc[i] += __shfl_xor_sync(0xffffffffu, acc[i], 8);
        acc[i] += __shfl_xor_sync(0xffffffffu, acc[i], 16);
    }
    float inv = 1.f / (denom + 1e-16f);
    if (g == 0) {
        unsigned pk[8];
#pragma unroll
        for (int j = 0; j < 8; j++) {
            __nv_bfloat162 b;
            b.x = __float2bfloat16(acc[2 * j] * inv);
            b.y = __float2bfloat16(acc[2 * j + 1] * inv);
            pk[j] = *reinterpret_cast<unsigned*>(&b);
        }
        __nv_bfloat16* out = g_aggbf + (size_t)w * 128 + h * 16;
        *reinterpret_cast<uint4*>(out)     = make_uint4(pk[0], pk[1], pk[2], pk[3]);
        *reinterpret_cast<uint4*>(out + 8) = make_uint4(pk[4], pk[5], pk[6], pk[7]);
    }
}

// ---------------- launch ----------------
extern "C" void kernel_launch(void* const* d_in, const int* in_sizes, int n_in,
                              void* d_out, int out_size) {
    const float* x = (const float*)d_in[0];
    const void* ei = d_in[1];
    const float* Wq = (const float*)d_in[2];
    const float* bq = (const float*)d_in[3];
    const float* Wk = (const float*)d_in[4];
    const float* bk = (const float*)d_in[5];
    const float* Wv = (const float*)d_in[6];
    const float* bv = (const float*)d_in[7];
    const float* Wo = (const float*)d_in[8];
    const float* bo = (const float*)d_in[9];
    const float* W1 = (const float*)d_in[10];
    const float* b1 = (const float*)d_in[11];
    const float* W2 = (const float*)d_in[12];
    const float* b2 = (const float*)d_in[13];
    const float* g1 = (const float*)d_in[14];
    const float* be1 = (const float*)d_in[15];
    const float* g2 = (const float*)d_in[16];
    const float* be2 = (const float*)d_in[17];
    float* out = (float*)d_out;

    cudaFuncSetAttribute(gemm_kernel, cudaFuncAttributeMaxDynamicSharedMemorySize, GEMM_SMEM);
    cudaFuncSetAttribute(gemm64, cudaFuncAttributeMaxDynamicSharedMemorySize, GEMM64_SMEM);

    // Lazily-created side stream + fork/join events (created on the first
    // uncaptured correctness call; reused during capture -> parallel branches).
    static cudaStream_t s_side = nullptr;
    static cudaEvent_t ev_fork = nullptr, ev_join = nullptr;
    if (s_side == nullptr) {
        if (cudaStreamCreateWithFlags(&s_side, cudaStreamNonBlocking) != cudaSuccess)
            s_side = nullptr;
        if (s_side) {
            cudaEventCreateWithFlags(&ev_fork, cudaEventDisableTiming);
            cudaEventCreateWithFlags(&ev_join, cudaEventDisableTiming);
        }
    }

    const int SCB = (NN + 1023) / 1024;  // 49
    const int M64 = (NN + 63) / 64;      // 782

    if (s_side) {
        // fork: CSR build chain on side stream, weights/QKV on main stream
        cudaEventRecord(ev_fork, 0);
        cudaStreamWaitEvent(s_side, ev_fork, 0);

        zero_fill<<<SCB, 1024, 0, s_side>>>();
        prep_edges<<<(EE + 255) / 256, 256, 0, s_side>>>(ei);
        scan_bt<<<SCB, 1024, 0, s_side>>>();
        scan_fix<<<SCB, 1024, 0, s_side>>>();
        scatter_kernel<<<(EE + 255) / 256, 256, 0, s_side>>>();
        cudaEventRecord(ev_join, s_side);

        prep_wx<<<(NN * HID + 255) / 256, 256>>>(x, Wq, bq, Wk, bk, Wv, bv, Wo, bo, W1, b1, W2, b2);
        gemm_kernel<<<dim3(391, 3), 256, GEMM_SMEM>>>(NN, 384, 128);   // QKV

        cudaStreamWaitEvent(0, ev_join, 0);
    } else {
        zero_fill<<<SCB, 1024>>>();
        prep_edges<<<(EE + 255) / 256, 256>>>(ei);
        scan_bt<<<SCB, 1024>>>();
        scan_fix<<<SCB, 1024>>>();
        scatter_kernel<<<(EE + 255) / 256, 256>>>();
        prep_wx<<<(NN * HID + 255) / 256, 256>>>(x, Wq, bq, Wk, bk, Wv, bv, Wo, bo, W1, b1, W2, b2);
        gemm_kernel<<<dim3(391, 3), 256, GEMM_SMEM>>>(NN, 384, 128);
    }

    attn_kernel<<<(NN * 32 + 255) / 256, 256>>>();                                  // agg
    gemm64<<<dim3(M64, 1), 256, GEMM64_SMEM>>>(1, NN, 128, x, g1, be1, nullptr);    // Wo + LN1
    gemm64<<<dim3(M64, 4), 256, GEMM64_SMEM>>>(2, NN, 128, nullptr, nullptr, nullptr, nullptr); // W1 + gelu
    gemm64<<<dim3(M64, 1), 256, GEMM64_SMEM>>>(3, NN, 512, nullptr, g2, be2, out);  // W2 + LN2
}

// round 17
// speedup vs baseline: 1.6720x; 1.0072x over previous
#include <cuda_runtime.h>
#include <cuda_bf16.h>
#include <math.h>

#define NN 50000
#define EE 800000
#define HID 128
#define FFH 512

// ---------------- scratch (device globals: allocation-free) ----------------
__device__ __nv_bfloat16 g_xbf[(size_t)NN * HID];
__device__ __nv_bfloat16 g_wcat[384 * 128];
__device__ __nv_bfloat16 g_wo[128 * 128];
__device__ __nv_bfloat16 g_w1[512 * 128];
__device__ __nv_bfloat16 g_w2[128 * 512];
__device__ float g_bcat[384], g_bo[128], g_b1[512], g_b2[128];
__device__ __nv_bfloat16 g_qkv[(size_t)NN * 384];
__device__ int g_src[EE], g_dst[EE], g_esrc[EE];
__device__ int g_rowptr[NN + 1], g_fill[NN];
__device__ int g_bsum[64];
__device__ int g_arrive;   // static-init 0; reset to 0 by last block every call
__device__ __nv_bfloat16 g_aggbf[(size_t)NN * HID];
__device__ float g_h[(size_t)NN * HID];
__device__ __nv_bfloat16 g_ff1bf[(size_t)NN * FFH];

// ---------------- prep kernels ----------------
__global__ void zero_fill() {
    int i = blockIdx.x * blockDim.x + threadIdx.x;
    if (i < NN) g_fill[i] = 0;
}

__global__ void prep_edges(const void* __restrict__ ei) {
    int i = blockIdx.x * blockDim.x + threadIdx.x;
    if (i >= EE) return;
    // dtype sniff per-thread (L1-broadcast): int64 view of int32 data combines
    // two random node ids -> ~1e14, outside [0, NN). Deterministic.
    const long long* p64 = (const long long*)ei;
    int is64 = 1;
#pragma unroll
    for (int j = 0; j < 4; j++) {
        long long v = p64[j];
        if (v < 0 || v >= NN) is64 = 0;
    }
    long long s, d;
    if (is64) {
        s = p64[i];
        d = p64[(size_t)EE + i];
    } else {
        const int* p = (const int*)ei;
        s = p[i];
        d = p[(size_t)EE + i];
    }
    if (s < 0) s = 0; if (s >= NN) s = NN - 1;
    if (d < 0) d = 0; if (d >= NN) d = NN - 1;
    g_src[i] = (int)s;
    g_dst[i] = (int)d;
    atomicAdd(&g_fill[(int)d], 1);   // fused histogram
}

// fused block-scan + (last block) top-scan via arrival counter
__global__ void scan_bt() {
    __shared__ int sh[1024];
    __shared__ int s_old;
    int b = blockIdx.x, t = threadIdx.x;
    int i = b * 1024 + t;
    int d = (i < NN) ? g_fill[i] : 0;
    sh[t] = d;
    __syncthreads();
#pragma unroll
    for (int off = 1; off < 1024; off <<= 1) {
        int v = (t >= off) ? sh[t - off] : 0;
        __syncthreads();
        sh[t] += v;
        __syncthreads();
    }
    if (i < NN) g_rowptr[i] = sh[t] - d;  // exclusive, block-local
    if (t == 1023) {
        g_bsum[b] = sh[1023];
        __threadfence();
    }
    __syncthreads();
    if (t == 0) s_old = atomicAdd(&g_arrive, 1);
    __syncthreads();
    if (s_old == gridDim.x - 1) {
        int nb = gridDim.x;
        if (t < nb) sh[t] = *(volatile int*)&g_bsum[t];
        __syncthreads();
        if (t == 0) {
            int run = 0;
            for (int j = 0; j < nb; j++) { int v = sh[j]; sh[j] = run; run += v; }
            g_rowptr[NN] = run;
            g_arrive = 0;   // deterministic reset for next call
        }
        __syncthreads();
        if (t < nb) g_bsum[t] = sh[t];
    }
}

__global__ void scan_fix() {
    int b = blockIdx.x;
    int i = b * 1024 + threadIdx.x;
    if (i < NN) {
        int r = g_rowptr[i] + g_bsum[b];
        g_rowptr[i] = r;
        g_fill[i] = r;
    }
}

__global__ void scatter_kernel() {
    int i = blockIdx.x * blockDim.x + threadIdx.x;
    if (i < EE) {
        int d = g_dst[i];
        int p = atomicAdd(&g_fill[d], 1);
        g_esrc[p] = g_src[i];
    }
}

// fused: x -> bf16 conversion + weight conversion + bias staging
__global__ void prep_wx(const float* __restrict__ x,
                        const float* __restrict__ Wq, const float* __restrict__ bq,
                        const float* __restrict__ Wk, const float* __restrict__ bk,
                        const float* __restrict__ Wv, const float* __restrict__ bv,
                        const float* __restrict__ Wo, const float* __restrict__ bo,
                        const float* __restrict__ W1, const float* __restrict__ b1,
                        const float* __restrict__ W2, const float* __restrict__ b2) {
    int i = blockIdx.x * blockDim.x + threadIdx.x;
    if (i < NN * HID) g_xbf[i] = __float2bfloat16(x[i]);
    if (i < 128 * 128) {
        g_wcat[i]         = __float2bfloat16(Wq[i]);
        g_wcat[16384 + i] = __float2bfloat16(Wk[i]);
        g_wcat[32768 + i] = __float2bfloat16(Wv[i]);
        g_wo[i]           = __float2bfloat16(Wo[i]);
    }
    if (i < 512 * 128) {
        g_w1[i] = __float2bfloat16(W1[i]);
        g_w2[i] = __float2bfloat16(W2[i]);
    }
    if (i < 128) {
        g_bcat[i] = bq[i];
        g_bcat[128 + i] = bk[i];
        g_bcat[256 + i] = bv[i];
        g_bo[i] = bo[i];
        g_b2[i] = b2[i];
    }
    if (i < 512) g_b1[i] = b1[i];
}

// ---------------- bf16 tensor-core GEMM ----------------
__device__ __forceinline__ void mma16816(float c[4], unsigned a0, unsigned a1, unsigned a2,
                                         unsigned a3, unsigned b0, unsigned b1) {
    asm volatile(
        "mma.sync.aligned.m16n8k16.row.col.f32.bf16.bf16.f32 "
        "{%0,%1,%2,%3}, {%4,%5,%6,%7}, {%8,%9}, {%0,%1,%2,%3};\n"
        : "+f"(c[0]), "+f"(c[1]), "+f"(c[2]), "+f"(c[3])
        : "r"(a0), "r"(a1), "r"(a2), "r"(a3), "r"(b0), "r"(b1));
}

__device__ __forceinline__ void ldx4(unsigned& r0, unsigned& r1, unsigned& r2, unsigned& r3,
                                     unsigned addr) {
    asm volatile("ldmatrix.sync.aligned.m8n8.x4.shared.b16 {%0,%1,%2,%3}, [%4];"
                 : "=r"(r0), "=r"(r1), "=r"(r2), "=r"(r3)
                 : "r"(addr));
}

__device__ __forceinline__ void cp16(unsigned saddr, const void* gaddr, int szbytes) {
    asm volatile("cp.async.cg.shared.global [%0], [%1], 16, %2;"
                 :: "r"(saddr), "l"(gaddr), "r"(szbytes));
}

__device__ __forceinline__ float warp_sum(float s) {
#pragma unroll
    for (int o = 16; o > 0; o >>= 1) s += __shfl_xor_sync(0xffffffffu, s, o);
    return s;
}

__device__ __forceinline__ float gelu_f(float v) {
    return 0.5f * v * (1.0f + erff(v * 0.70710678118654752f));
}

// 64-deep K stages, double buffered (champion config: 2 CTAs/SM).
#define SSTG 36
#define STAGE_U (128 * SSTG)
#define GEMM_SMEM (4 * STAGE_U * 4)  // 73728 B

// ============ 128x128 GEMM: QKV only ============
__global__ __launch_bounds__(256) void gemm_kernel(int M, int N, int K) {
    const __nv_bfloat16 *A = g_xbf, *W = g_wcat;
    const float* bias = g_bcat;
    __nv_bfloat16* C16 = g_qkv;

    extern __shared__ unsigned sh[];

    int t = threadIdx.x;
    int warp = t >> 5, lane = t & 31;
    int wm = warp >> 2, wn = warp & 3;
    int bm = blockIdx.x * 128, bn = blockIdx.y * 128;
    int r = lane >> 2, cp = lane & 3;

    float c[4][4][4];
#pragma unroll
    for (int a = 0; a < 4; a++)
#pragma unroll
        for (int b = 0; b < 4; b++)
#pragma unroll
            for (int d = 0; d < 4; d++) c[a][b][d] = 0.f;

    unsigned sbase = (unsigned)__cvta_generic_to_shared(sh);

    int q = lane >> 3, lr = lane & 7;
    int rb = lr + (q & 1) * 8;
    int cb4 = (q >> 1) * 4;
    unsigned aAddr[2];
#pragma unroll
    for (int mi2 = 0; mi2 < 2; mi2++)
        aAddr[mi2] = sbase + 4u * ((wm * 64 + mi2 * 32 + rb) * SSTG + cb4);
    unsigned bAddr[2];
#pragma unroll
    for (int n2 = 0; n2 < 2; n2++)
        bAddr[n2] = sbase + 4u * (2 * STAGE_U + (wn * 32 + n2 * 16 + rb) * SSTG + cb4);

    const int S = K >> 6;

    auto fill = [&](int s) {
        int b = s & 1;
        int kc = s << 6;
#pragma unroll
        for (int j = 0; j < 4; j++) {
            int flat = j * 256 + t;
            int row = flat >> 3, c16 = flat & 7;
            int gr = bm + row;
            const void* gp = A + (size_t)gr * K + kc + c16 * 8;
            unsigned sp = sbase + 4u * (b * STAGE_U + row * SSTG + c16 * 4);
            cp16(sp, gp, (gr < M) ? 16 : 0);
        }
#pragma unroll
        for (int j = 0; j < 4; j++) {
            int flat = j * 256 + t;
            int row = flat >> 3, c16 = flat & 7;
            const void* gp = W + (size_t)(bn + row) * K + kc + c16 * 8;
            unsigned sp = sbase + 4u * (2 * STAGE_U + b * STAGE_U + row * SSTG + c16 * 4);
            cp16(sp, gp, 16);
        }
        asm volatile("cp.async.commit_group;");
    };

    fill(0);
    for (int s = 0; s < S; s++) {
        if (s + 1 < S) {
            fill(s + 1);
            asm volatile("cp.async.wait_group 1;");
        } else {
            asm volatile("cp.async.wait_group 0;");
        }
        __syncthreads();
        unsigned boff = (unsigned)((s & 1) * STAGE_U * 4);
#pragma unroll
        for (int ks = 0; ks < 4; ks++) {
            unsigned bfr[4][2];
#pragma unroll
            for (int n2 = 0; n2 < 2; n2++) {
                unsigned r0, r1, r2, r3;
                ldx4(r0, r1, r2, r3, bAddr[n2] + boff + ks * 32);
                bfr[2 * n2][0] = r0; bfr[2 * n2 + 1][0] = r1;
                bfr[2 * n2][1] = r2; bfr[2 * n2 + 1][1] = r3;
            }
#pragma unroll
            for (int mi = 0; mi < 4; mi++) {
                unsigned a0, a1, a2, a3;
                ldx4(a0, a1, a2, a3, aAddr[mi >> 1] + boff + (mi & 1) * (16u * SSTG * 4) + ks * 32);
#pragma unroll
                for (int ni = 0; ni < 4; ni++)
                    mma16816(c[mi][ni], a0, a1, a2, a3, bfr[ni][0], bfr[ni][1]);
            }
        }
        __syncthreads();
    }

#pragma unroll
    for (int mi = 0; mi < 4; mi++) {
        int grow0 = bm + wm * 64 + mi * 16 + r;
        int grow1 = grow0 + 8;
#pragma unroll
        for (int ni = 0; ni < 4; ni++) {
            int col = bn + wn * 32 + ni * 8 + cp * 2;
            float bb0 = bias[col], bb1 = bias[col + 1];
            float v0 = c[mi][ni][0] + bb0, v1 = c[mi][ni][1] + bb1;
            float v2 = c[mi][ni][2] + bb0, v3 = c[mi][ni][3] + bb1;
            if (grow0 < M) {
                __nv_bfloat162 h;
                h.x = __float2bfloat16(v0); h.y = __float2bfloat16(v1);
                *reinterpret_cast<__nv_bfloat162*>(&C16[(size_t)grow0 * N + col]) = h;
            }
            if (grow1 < M) {
                __nv_bfloat162 h;
                h.x = __float2bfloat16(v2); h.y = __float2bfloat16(v3);
                *reinterpret_cast<__nv_bfloat162*>(&C16[(size_t)grow1 * N + col]) = h;
            }
        }
    }
}

// ============ fused mid kernel: Wo GEMM -> LN1 -> FF1(gelu), 64-row tile ============
#define A64_U (64 * SSTG)
#define B64_U (128 * SSTG)
#define GEMM64_SMEM ((2 * A64_U + 2 * B64_U) * 4)  // 55296 B

__global__ __launch_bounds__(256) void fused_mid(int M,
                                                 const float* __restrict__ resid,
                                                 const float* __restrict__ gam,
                                                 const float* __restrict__ bet) {
    extern __shared__ unsigned sh[];

    int t = threadIdx.x;
    int warp = t >> 5, lane = t & 31;
    int wm = warp >> 2, wn = warp & 3;
    int bm = blockIdx.x * 64;
    int r = lane >> 2, cp = lane & 3;

    float c[2][4][4];
#pragma unroll
    for (int a = 0; a < 2; a++)
#pragma unroll
        for (int b = 0; b < 4; b++)
#pragma unroll
            for (int d = 0; d < 4; d++) c[a][b][d] = 0.f;

    unsigned sbase = (unsigned)__cvta_generic_to_shared(sh);

    int q = lane >> 3, lr = lane & 7;
    int rb = lr + (q & 1) * 8;
    int cb4 = (q >> 1) * 4;
    unsigned aAddr[2];
#pragma unroll
    for (int mi = 0; mi < 2; mi++)
        aAddr[mi] = sbase + 4u * ((wm * 32 + mi * 16 + rb) * SSTG + cb4);
    unsigned bAddr[2];
#pragma unroll
    for (int n2 = 0; n2 < 2; n2++)
        bAddr[n2] = sbase + 4u * (2 * A64_U + (wn * 32 + n2 * 16 + rb) * SSTG + cb4);

    // ---- phase 1: Wo GEMM (K=128, 2 stages) ----
    auto fill1 = [&](int s) {
        int b = s & 1;
        int kc = s << 6;
#pragma unroll
        for (int j = 0; j < 2; j++) {
            int flat = j * 256 + t;
            int row = flat >> 3, c16 = flat & 7;
            int gr = bm + row;
            const void* gp = g_aggbf + (size_t)gr * 128 + kc + c16 * 8;
            unsigned sp = sbase + 4u * (b * A64_U + row * SSTG + c16 * 4);
            cp16(sp, gp, (gr < M) ? 16 : 0);
        }
#pragma unroll
        for (int j = 0; j < 4; j++) {
            int flat = j * 256 + t;
            int row = flat >> 3, c16 = flat & 7;
            const void* gp = g_wo + (size_t)row * 128 + kc + c16 * 8;
            unsigned sp = sbase + 4u * (2 * A64_U + b * B64_U + row * SSTG + c16 * 4);
            cp16(sp, gp, 16);
        }
        asm volatile("cp.async.commit_group;");
    };

    fill1(0);
    for (int s = 0; s < 2; s++) {
        if (s == 0) {
            fill1(1);
            asm volatile("cp.async.wait_group 1;");
        } else {
            asm volatile("cp.async.wait_group 0;");
        }
        __syncthreads();
        unsigned aoff = (unsigned)((s & 1) * A64_U * 4);
        unsigned boff = (unsigned)((s & 1) * B64_U * 4);
#pragma unroll
        for (int ks = 0; ks < 4; ks++) {
            unsigned bfr[4][2];
#pragma unroll
            for (int n2 = 0; n2 < 2; n2++) {
                unsigned r0, r1, r2, r3;
                ldx4(r0, r1, r2, r3, bAddr[n2] + boff + ks * 32);
                bfr[2 * n2][0] = r0; bfr[2 * n2 + 1][0] = r1;
                bfr[2 * n2][1] = r2; bfr[2 * n2 + 1][1] = r3;
            }
#pragma unroll
            for (int mi = 0; mi < 2; mi++) {
                unsigned a0, a1, a2, a3;
                ldx4(a0, a1, a2, a3, aAddr[mi] + aoff + ks * 32);
#pragma unroll
                for (int ni = 0; ni < 4; ni++)
                    mma16816(c[mi][ni], a0, a1, a2, a3, bfr[ni][0], bfr[ni][1]);
            }
        }
        __syncthreads();
    }

    // ---- LN1 epilogue: Cs staged in B-buffer region; h (bf16) -> A-buffers ----
    float* Cs = (float*)(sh + 2 * A64_U);  // [64][132] f32 = 33792 B (fits 36864 B)
#pragma unroll
    for (int mi = 0; mi < 2; mi++) {
        int rl0 = wm * 32 + mi * 16 + r;
#pragma unroll
        for (int ni = 0; ni < 4; ni++) {
            int col = wn * 32 + ni * 8 + cp * 2;
            Cs[rl0 * 132 + col]           = c[mi][ni][0];
            Cs[rl0 * 132 + col + 1]       = c[mi][ni][1];
            Cs[(rl0 + 8) * 132 + col]     = c[mi][ni][2];
            Cs[(rl0 + 8) * 132 + col + 1] = c[mi][ni][3];
        }
    }
    __syncthreads();
    {
        int cbx = lane * 4;
        float b0 = g_bo[cbx], b1 = g_bo[cbx + 1], b2v = g_bo[cbx + 2], b3 = g_bo[cbx + 3];
        float gg0 = gam[cbx], gg1 = gam[cbx + 1], gg2 = gam[cbx + 2], gg3 = gam[cbx + 3];
        float bb0 = bet[cbx], bb1 = bet[cbx + 1], bb2 = bet[cbx + 2], bb3 = bet[cbx + 3];
        unsigned hbase = ((cbx >> 6) ? (unsigned)A64_U : 0u) + (unsigned)((cbx & 63) >> 1);
#pragma unroll
        for (int i = 0; i < 8; i++) {
            int rl = warp * 8 + i;
            int grow = bm + rl;
            if (grow >= M) break;
            const float* rr = resid + (size_t)grow * 128 + cbx;
            float t0 = Cs[rl * 132 + cbx]     + b0 + rr[0];
            float t1 = Cs[rl * 132 + cbx + 1] + b1 + rr[1];
            float t2 = Cs[rl * 132 + cbx + 2] + b2v + rr[2];
            float t3 = Cs[rl * 132 + cbx + 3] + b3 + rr[3];
            float mu = warp_sum(t0 + t1 + t2 + t3) * (1.f / 128.f);
            float d0 = t0 - mu, d1 = t1 - mu, d2 = t2 - mu, d3 = t3 - mu;
            float var = warp_sum(d0 * d0 + d1 * d1 + d2 * d2 + d3 * d3) * (1.f / 128.f);
            float rs = rsqrtf(var + 1e-5f);
            float o0 = d0 * rs * gg0 + bb0;
            float o1 = d1 * rs * gg1 + bb1;
            float o2 = d2 * rs * gg2 + bb2;
            float o3 = d3 * rs * gg3 + bb3;
            *reinterpret_cast<float4*>(g_h + (size_t)grow * 128 + cbx) =
                make_float4(o0, o1, o2, o3);
            // h bf16 into A-buffer region, fill-compatible layout
            __nv_bfloat162 p0, p1;
            p0.x = __float2bfloat16(o0); p0.y = __float2bfloat16(o1);
            p1.x = __float2bfloat16(o2); p1.y = __float2bfloat16(o3);
            uint2 u;
            u.x = *reinterpret_cast<unsigned*>(&p0);
            u.y = *reinterpret_cast<unsigned*>(&p1);
            *reinterpret_cast<uint2*>(sh + hbase + (unsigned)rl * SSTG) = u;
        }
    }
    __syncthreads();   // Cs consumed, h writes visible before phase-2 fills clobber B region

    // ---- phase 2: FF1 = h @ W1^T, 4 N-blocks x 2 K-halves = 8 chunks ----
#pragma unroll
    for (int a = 0; a < 2; a++)
#pragma unroll
        for (int b = 0; b < 4; b++)
#pragma unroll
            for (int d = 0; d < 4; d++) c[a][b][d] = 0.f;

    auto fill2 = [&](int u) {   // u = bn*2 + half
        int buf = u & 1;
        int kc = (u & 1) << 6;
        int brow0 = (u >> 1) * 128;
#pragma unroll
        for (int j = 0; j < 4; j++) {
            int flat = j * 256 + t;
            int row = flat >> 3, c16 = flat & 7;
            const void* gp = g_w1 + (size_t)(brow0 + row) * 128 + kc + c16 * 8;
            unsigned sp = sbase + 4u * (2 * A64_U + buf * B64_U + row * SSTG + c16 * 4);
            cp16(sp, gp, 16);
        }
        asm volatile("cp.async.commit_group;");
    };

    fill2(0);
    for (int u = 0; u < 8; u++) {
        if (u + 1 < 8) {
            fill2(u + 1);
            asm volatile("cp.async.wait_group 1;");
        } else {
            asm volatile("cp.async.wait_group 0;");
        }
        __syncthreads();
        unsigned aoff = (unsigned)((u & 1) * A64_U * 4);
        unsigned boff = (unsigned)((u & 1) * B64_U * 4);
#pragma unroll
        for (int ks = 0; ks < 4; ks++) {
            unsigned bfr[4][2];
#pragma unroll
            for (int n2 = 0; n2 < 2; n2++) {
                unsigned r0, r1, r2, r3;
                ldx4(r0, r1, r2, r3, bAddr[n2] + boff + ks * 32);
                bfr[2 * n2][0] = r0; bfr[2 * n2 + 1][0] = r1;
                bfr[2 * n2][1] = r2; bfr[2 * n2 + 1][1] = r3;
            }
#pragma unroll
            for (int mi = 0; mi < 2; mi++) {
                unsigned a0, a1, a2, a3;
                ldx4(a0, a1, a2, a3, aAddr[mi] + aoff + ks * 32);
#pragma unroll
                for (int ni = 0; ni < 4; ni++)
                    mma16816(c[mi][ni], a0, a1, a2, a3, bfr[ni][0], bfr[ni][1]);
            }
        }
        if (u & 1) {
            // both K-halves of this bn accumulated -> gelu epilogue
            int bn = (u >> 1) * 128;
#pragma unroll
            for (int mi = 0; mi < 2; mi++) {
                int grow0 = bm + wm * 32 + mi * 16 + r;
                int grow1 = grow0 + 8;
#pragma unroll
                for (int ni = 0; ni < 4; ni++) {
                    int col = bn + wn * 32 + ni * 8 + cp * 2;
                    float bb0 = g_b1[col], bb1 = g_b1[col + 1];
                    float v0 = gelu_f(c[mi][ni][0] + bb0), v1 = gelu_f(c[mi][ni][1] + bb1);
                    float v2 = gelu_f(c[mi][ni][2] + bb0), v3 = gelu_f(c[mi][ni][3] + bb1);
                    c[mi][ni][0] = 0.f; c[mi][ni][1] = 0.f; c[mi][ni][2] = 0.f; c[mi][ni][3] = 0.f;
                    if (grow0 < M) {
                        __nv_bfloat162 h;
                        h.x = __float2bfloat16(v0); h.y = __float2bfloat16(v1);
                        *reinterpret_cast<__nv_bfloat162*>(&g_ff1bf[(size_t)grow0 * FFH + col]) = h;
                    }
                    if (grow1 < M) {
                        __nv_bfloat162 h;
                        h.x = __float2bfloat16(v2); h.y = __float2bfloat16(v3);
                        *reinterpret_cast<__nv_bfloat162*>(&g_ff1bf[(size_t)grow1 * FFH + col]) = h;
                    }
                }
            }
        }
        __syncthreads();
    }
}

// ============ FF2 + LN2 (64-row tile, K=512) ============
__global__ __launch_bounds__(256) void gemm_ff2(int M,
                                                const float* __restrict__ gam,
                                                const float* __restrict__ bet,
                                                float* __restrict__ outp) {
    extern __shared__ unsigned sh[];

    int t = threadIdx.x;
    int warp = t >> 5, lane = t & 31;
    int wm = warp >> 2, wn = warp & 3;
    int bm = blockIdx.x * 64;
    int r = lane >> 2, cp = lane & 3;

    float c[2][4][4];
#pragma unroll
    for (int a = 0; a < 2; a++)
#pragma unroll
        for (int b = 0; b < 4; b++)
#pragma unroll
            for (int d = 0; d < 4; d++) c[a][b][d] = 0.f;

    unsigned sbase = (unsigned)__cvta_generic_to_shared(sh);

    int q = lane >> 3, lr = lane & 7;
    int rb = lr + (q & 1) * 8;
    int cb4 = (q >> 1) * 4;
    unsigned aAddr[2];
#pragma unroll
    for (int mi = 0; mi < 2; mi++)
        aAddr[mi] = sbase + 4u * ((wm * 32 + mi * 16 + rb) * SSTG + cb4);
    unsigned bAddr[2];
#pragma unroll
    for (int n2 = 0; n2 < 2; n2++)
        bAddr[n2] = sbase + 4u * (2 * A64_U + (wn * 32 + n2 * 16 + rb) * SSTG + cb4);

    const int K = 512, S = K >> 6;

    auto fill = [&](int s) {
        int b = s & 1;
        int kc = s << 6;
#pragma unroll
        for (int j = 0; j < 2; j++) {
            int flat = j * 256 + t;
            int row = flat >> 3, c16 = flat & 7;
            int gr = bm + row;
            const void* gp = g_ff1bf + (size_t)gr * K + kc + c16 * 8;
            unsigned sp = sbase + 4u * (b * A64_U + row * SSTG + c16 * 4);
            cp16(sp, gp, (gr < M) ? 16 : 0);
        }
#pragma unroll
        for (int j = 0; j < 4; j++) {
            int flat = j * 256 + t;
            int row = flat >> 3, c16 = flat & 7;
            const void* gp = g_w2 + (size_t)row * K + kc + c16 * 8;
            unsigned sp = sbase + 4u * (2 * A64_U + b * B64_U + row * SSTG + c16 * 4);
            cp16(sp, gp, 16);
        }
        asm volatile("cp.async.commit_group;");
    };

    fill(0);
    for (int s = 0; s < S; s++) {
        if (s + 1 < S) {
            fill(s + 1);
            asm volatile("cp.async.wait_group 1;");
        } else {
            asm volatile("cp.async.wait_group 0;");
        }
        __syncthreads();
        unsigned aoff = (unsigned)((s & 1) * A64_U * 4);
        unsigned boff = (unsigned)((s & 1) * B64_U * 4);
#pragma unroll
        for (int ks = 0; ks < 4; ks++) {
            unsigned bfr[4][2];
#pragma unroll
            for (int n2 = 0; n2 < 2; n2++) {
                unsigned r0, r1, r2, r3;
                ldx4(r0, r1, r2, r3, bAddr[n2] + boff + ks * 32);
                bfr[2 * n2][0] = r0; bfr[2 * n2 + 1][0] = r1;
                bfr[2 * n2][1] = r2; bfr[2 * n2 + 1][1] = r3;
            }
#pragma unroll
            for (int mi = 0; mi < 2; mi++) {
                unsigned a0, a1, a2, a3;
                ldx4(a0, a1, a2, a3, aAddr[mi] + aoff + ks * 32);
#pragma unroll
                for (int ni = 0; ni < 4; ni++)
                    mma16816(c[mi][ni], a0, a1, a2, a3, bfr[ni][0], bfr[ni][1]);
            }
        }
        __syncthreads();
    }

    // fused residual + LayerNorm epilogue
    float* Cs = (float*)sh;  // [64][132] = 33792 B
#pragma unroll
    for (int mi = 0; mi < 2; mi++) {
        int rl0 = wm * 32 + mi * 16 + r;
#pragma unroll
        for (int ni = 0; ni < 4; ni++) {
            int col = wn * 32 + ni * 8 + cp * 2;
            Cs[rl0 * 132 + col]           = c[mi][ni][0];
            Cs[rl0 * 132 + col + 1]       = c[mi][ni][1];
            Cs[(rl0 + 8) * 132 + col]     = c[mi][ni][2];
            Cs[(rl0 + 8) * 132 + col + 1] = c[mi][ni][3];
        }
    }
    __syncthreads();
    int cbx = lane * 4;
    float b0 = g_b2[cbx], b1 = g_b2[cbx + 1], b2v = g_b2[cbx + 2], b3 = g_b2[cbx + 3];
    float gg0 = gam[cbx], gg1 = gam[cbx + 1], gg2 = gam[cbx + 2], gg3 = gam[cbx + 3];
    float bb0 = bet[cbx], bb1 = bet[cbx + 1], bb2 = bet[cbx + 2], bb3 = bet[cbx + 3];
#pragma unroll
    for (int i = 0; i < 8; i++) {
        int rl = warp * 8 + i;
        int grow = bm + rl;
        if (grow >= M) break;
        const float* rr = g_h + (size_t)grow * 128 + cbx;
        float t0 = Cs[rl * 132 + cbx]     + b0 + rr[0];
        float t1 = Cs[rl * 132 + cbx + 1] + b1 + rr[1];
        float t2 = Cs[rl * 132 + cbx + 2] + b2v + rr[2];
        float t3 = Cs[rl * 132 + cbx + 3] + b3 + rr[3];
        float mu = warp_sum(t0 + t1 + t2 + t3) * (1.f / 128.f);
        float d0 = t0 - mu, d1 = t1 - mu, d2 = t2 - mu, d3 = t3 - mu;
        float var = warp_sum(d0 * d0 + d1 * d1 + d2 * d2 + d3 * d3) * (1.f / 128.f);
        float rs = rsqrtf(var + 1e-5f);
        *reinterpret_cast<float4*>(outp + (size_t)grow * 128 + cbx) =
            make_float4(d0 * rs * gg0 + bb0, d1 * rs * gg1 + bb1,
                        d2 * rs * gg2 + bb2, d3 * rs * gg3 + bb3);
    }
}

// ---------------- attention: lane = (edge-group, head); 8 edges in flight ----------------
__device__ __forceinline__ void ld16bf(float* f, const __nv_bfloat16* p) {
    uint4 u0 = *reinterpret_cast<const uint4*>(p);
    uint4 u1 = *reinterpret_cast<const uint4*>(p + 8);
    const unsigned* w = &u0.x;
#pragma unroll
    for (int j = 0; j < 4; j++) {
        float2 f2 = __bfloat1622float2(*reinterpret_cast<const __nv_bfloat162*>(&w[j]));
        f[2 * j] = f2.x; f[2 * j + 1] = f2.y;
    }
    const unsigned* w1 = &u1.x;
#pragma unroll
    for (int j = 0; j < 4; j++) {
        float2 f2 = __bfloat1622float2(*reinterpret_cast<const __nv_bfloat162*>(&w1[j]));
        f[8 + 2 * j] = f2.x; f[8 + 2 * j + 1] = f2.y;
    }
}

__global__ __launch_bounds__(256) void attn_kernel() {
    int w = (blockIdx.x * blockDim.x + threadIdx.x) >> 5;  // node
    if (w >= NN) return;
    int lane = threadIdx.x & 31;
    int g = lane >> 3;   // edge-group 0..3
    int h = lane & 7;    // head 0..7

    float qv[16];
    ld16bf(qv, g_qkv + (size_t)w * 384 + h * 16);

    int s = g_rowptr[w], e = g_rowptr[w + 1];
    int iters = (e - s + 3) >> 2;

    float denom = 0.f;
    float acc[16];
#pragma unroll
    for (int i = 0; i < 16; i++) acc[i] = 0.f;

    int it = 0;
    for (; it + 2 <= iters; it += 2) {
        int p0 = s + it * 4 + g;
        int p1 = p0 + 4;
        bool v0 = p0 < e, v1 = p1 < e;
        int s0 = v0 ? g_esrc[p0] : 0;
        int s1 = v1 ? g_esrc[p1] : 0;
        const __nv_bfloat16* b0 = g_qkv + (size_t)s0 * 384 + h * 16;
        const __nv_bfloat16* b1 = g_qkv + (size_t)s1 * 384 + h * 16;
        float kv0[16], vv0[16], kv1[16], vv1[16];
        ld16bf(kv0, b0 + 128);
        ld16bf(vv0, b0 + 256);
        ld16bf(kv1, b1 + 128);
        ld16bf(vv1, b1 + 256);
        float d0 = 0.f, d1 = 0.f;
#pragma unroll
        for (int i = 0; i < 16; i++) { d0 += qv[i] * kv0[i]; d1 += qv[i] * kv1[i]; }
        float ea0 = v0 ? __expf(d0 * 0.25f) : 0.f;
        denom += ea0;
#pragma unroll
        for (int i = 0; i < 16; i++) acc[i] += ea0 * vv0[i];
        float ea1 = v1 ? __expf(d1 * 0.25f) : 0.f;
        denom += ea1;
#pragma unroll
        for (int i = 0; i < 16; i++) acc[i] += ea1 * vv1[i];
    }
    for (; it < iters; it++) {
        int p = s + it * 4 + g;
        bool valid = p < e;
        int src = valid ? g_esrc[p] : 0;
        const __nv_bfloat16* base = g_qkv + (size_t)src * 384 + h * 16;
        float kv[16], vv[16];
        ld16bf(kv, base + 128);
        ld16bf(vv, base + 256);
        float d = 0.f;
#pragma unroll
        for (int i = 0; i < 16; i++) d += qv[i] * kv[i];
        float ea = valid ? __expf(d * 0.25f) : 0.f;
        denom += ea;
#pragma unroll
        for (int i = 0; i < 16; i++) acc[i] += ea * vv[i];
    }

    denom += __shfl_xor_sync(0xffffffffu, denom, 8);
    denom += __shfl_xor_sync(0xffffffffu, denom, 16);
#pragma unroll
    for (int i = 0; i < 16; i++) {
        acc[i] += __shfl_xor_sync(0xffffffffu, acc[i], 8);
        acc[i] += __shfl_xor_sync(0xffffffffu, acc[i], 16);
    }
    float inv = 1.f / (denom + 1e-16f);
    if (g == 0) {
        unsigned pk[8];
#pragma unroll
        for (int j = 0; j < 8; j++) {
            __nv_bfloat162 b;
            b.x = __float2bfloat16(acc[2 * j] * inv);
            b.y = __float2bfloat16(acc[2 * j + 1] * inv);
            pk[j] = *reinterpret_cast<unsigned*>(&b);
        }
        __nv_bfloat16* out = g_aggbf + (size_t)w * 128 + h * 16;
        *reinterpret_cast<uint4*>(out)     = make_uint4(pk[0], pk[1], pk[2], pk[3]);
        *reinterpret_cast<uint4*>(out + 8) = make_uint4(pk[4], pk[5], pk[6], pk[7]);
    }
}

// ---------------- launch ----------------
extern "C" void kernel_launch(void* const* d_in, const int* in_sizes, int n_in,
                              void* d_out, int out_size) {
    const float* x = (const float*)d_in[0];
    const void* ei = d_in[1];
    const float* Wq = (const float*)d_in[2];
    const float* bq = (const float*)d_in[3];
    const float* Wk = (const float*)d_in[4];
    const float* bk = (const float*)d_in[5];
    const float* Wv = (const float*)d_in[6];
    const float* bv = (const float*)d_in[7];
    const float* Wo = (const float*)d_in[8];
    const float* bo = (const float*)d_in[9];
    const float* W1 = (const float*)d_in[10];
    const float* b1 = (const float*)d_in[11];
    const float* W2 = (const float*)d_in[12];
    const float* b2 = (const float*)d_in[13];
    const float* g1 = (const float*)d_in[14];
    const float* be1 = (const float*)d_in[15];
    const float* g2 = (const float*)d_in[16];
    const float* be2 = (const float*)d_in[17];
    float* out = (float*)d_out;

    cudaFuncSetAttribute(gemm_kernel, cudaFuncAttributeMaxDynamicSharedMemorySize, GEMM_SMEM);
    cudaFuncSetAttribute(fused_mid, cudaFuncAttributeMaxDynamicSharedMemorySize, GEMM64_SMEM);
    cudaFuncSetAttribute(gemm_ff2, cudaFuncAttributeMaxDynamicSharedMemorySize, GEMM64_SMEM);

    // Lazily-created side stream + fork/join events (created on the first
    // uncaptured correctness call; reused during capture -> parallel branches).
    static cudaStream_t s_side = nullptr;
    static cudaEvent_t ev_fork = nullptr, ev_join = nullptr;
    if (s_side == nullptr) {
        if (cudaStreamCreateWithFlags(&s_side, cudaStreamNonBlocking) != cudaSuccess)
            s_side = nullptr;
        if (s_side) {
            cudaEventCreateWithFlags(&ev_fork, cudaEventDisableTiming);
            cudaEventCreateWithFlags(&ev_join, cudaEventDisableTiming);
        }
    }

    const int SCB = (NN + 1023) / 1024;  // 49
    const int M64 = (NN + 63) / 64;      // 782

    if (s_side) {
        // fork: CSR build chain on side stream, weights/QKV on main stream
        cudaEventRecord(ev_fork, 0);
        cudaStreamWaitEvent(s_side, ev_fork, 0);

        zero_fill<<<SCB, 1024, 0, s_side>>>();
        prep_edges<<<(EE + 255) / 256, 256, 0, s_side>>>(ei);
        scan_bt<<<SCB, 1024, 0, s_side>>>();
        scan_fix<<<SCB, 1024, 0, s_side>>>();
        scatter_kernel<<<(EE + 255) / 256, 256, 0, s_side>>>();
        cudaEventRecord(ev_join, s_side);

        prep_wx<<<(NN * HID + 255) / 256, 256>>>(x, Wq, bq, Wk, bk, Wv, bv, Wo, bo, W1, b1, W2, b2);
        gemm_kernel<<<dim3(391, 3), 256, GEMM_SMEM>>>(NN, 384, 128);   // QKV

        cudaStreamWaitEvent(0, ev_join, 0);
    } else {
        zero_fill<<<SCB, 1024>>>();
        prep_edges<<<(EE + 255) / 256, 256>>>(ei);
        scan_bt<<<SCB, 1024>>>();
        scan_fix<<<SCB, 1024>>>();
        scatter_kernel<<<(EE + 255) / 256, 256>>>();
        prep_wx<<<(NN * HID + 255) / 256, 256>>>(x, Wq, bq, Wk, bk, Wv, bv, Wo, bo, W1, b1, W2, b2);
        gemm_kernel<<<dim3(391, 3), 256, GEMM_SMEM>>>(NN, 384, 128);
    }

    attn_kernel<<<(NN * 32 + 255) / 256, 256>>>();                      // agg
    fused_mid<<<M64, 256, GEMM64_SMEM>>>(NN, x, g1, be1);               // Wo + LN1 + FF1
    gemm_ff2<<<M64, 256, GEMM64_SMEM>>>(NN, g2, be2, out);              // FF2 + LN2
}